// round 2
// baseline (speedup 1.0000x reference)
#include <cuda_runtime.h>
#include <math.h>

#define Bv 4
#define Tv 2048
#define Cv 1024
#define Hv 16
#define HSv 64
#define Mv (Bv*Tv)   /* 8192 */

// Scratch (static device memory — no runtime allocation)
__device__ float g_q[Bv*Hv*Tv*HSv];
__device__ float g_k[Bv*Hv*Tv*HSv];
__device__ float g_v[Bv*Hv*Tv*HSv];
__device__ float g_combo[(size_t)Bv*Tv*Cv];

// ---------------------------------------------------------------------------
// Kernel 1: QKV projections.  out[b,h,t,d] = sum_c x[b,t,c] * W[h,c,d]
// One GEMM M=8192, N=1024 (n = h*64+d), K=1024. grid.z in {0,1,2} -> q,k,v.
// Tiles: BM=BN=64, BK=16, 256 threads, 4x4 per thread.
// ---------------------------------------------------------------------------
__global__ __launch_bounds__(256) void qkv_kernel(
    const float* __restrict__ x,
    const float* __restrict__ Wq,
    const float* __restrict__ Wk,
    const float* __restrict__ Wv)
{
    __shared__ float As[16][68];   // As[k][m]
    __shared__ float Bs[16][68];   // Bs[k][d]
    const float* W   = (blockIdx.z == 0) ? Wq : (blockIdx.z == 1 ? Wk : Wv);
    float*       out = (blockIdx.z == 0) ? g_q : (blockIdx.z == 1 ? g_k : g_v);

    const int m0 = blockIdx.y * 64;
    const int h  = blockIdx.x;                 // BN=64 == HS -> one head per tile
    const float* Wh = W + (size_t)h * (Cv * HSv);

    const int tid = threadIdx.x;
    const int ty = tid >> 4, tx = tid & 15;
    const int am = tid >> 2, ak4 = (tid & 3) * 4;

    float acc[4][4] = {};

    for (int k0 = 0; k0 < Cv; k0 += 16) {
        // A tile: As[k][m] = x[(m0+m)*C + k0+k]
        float4 a4 = *(const float4*)&x[(size_t)(m0 + am) * Cv + k0 + ak4];
        As[ak4 + 0][am] = a4.x; As[ak4 + 1][am] = a4.y;
        As[ak4 + 2][am] = a4.z; As[ak4 + 3][am] = a4.w;
        // B tile: Bs[k][d] = Wh[(k0+k)*64 + d]  (contiguous 1024 floats)
        float4 b4 = *(const float4*)&Wh[(size_t)k0 * 64 + tid * 4];
        *(float4*)&Bs[tid >> 4][(tid & 15) * 4] = b4;
        __syncthreads();

        #pragma unroll
        for (int kk = 0; kk < 16; kk++) {
            float4 a = *(const float4*)&As[kk][ty * 4];
            float4 b = *(const float4*)&Bs[kk][tx * 4];
            acc[0][0] += a.x*b.x; acc[0][1] += a.x*b.y; acc[0][2] += a.x*b.z; acc[0][3] += a.x*b.w;
            acc[1][0] += a.y*b.x; acc[1][1] += a.y*b.y; acc[1][2] += a.y*b.z; acc[1][3] += a.y*b.w;
            acc[2][0] += a.z*b.x; acc[2][1] += a.z*b.y; acc[2][2] += a.z*b.z; acc[2][3] += a.z*b.w;
            acc[3][0] += a.w*b.x; acc[3][1] += a.w*b.y; acc[3][2] += a.w*b.z; acc[3][3] += a.w*b.w;
        }
        __syncthreads();
    }

    #pragma unroll
    for (int i = 0; i < 4; i++) {
        int m = m0 + ty * 4 + i;
        int b = m >> 11;              // m / T
        int t = m & (Tv - 1);
        float4 v = make_float4(acc[i][0], acc[i][1], acc[i][2], acc[i][3]);
        *(float4*)&out[(((size_t)b * Hv + h) * Tv + t) * HSv + tx * 4] = v;
    }
}

// ---------------------------------------------------------------------------
// Kernel 2: causal flash attention per (b,h).
// Block = 64 query rows; loops kv tiles jt = 0..qt (causal skip).
// 256 threads (16x16), thread (ty,tx) owns rows 4ty.., cols/dims 4tx..
// ---------------------------------------------------------------------------
__global__ __launch_bounds__(256) void flash_kernel()
{
    extern __shared__ float sm[];
    float* Qs  = sm;                 // [64][64]
    float* KsT = Qs  + 64 * 64;      // [64][68]  d-major (transposed)
    float* Vs  = KsT + 64 * 68;      // [64][64]
    float* Ps  = Vs  + 64 * 64;      // [64][64]

    const int qt  = blockIdx.x;
    const int bh  = blockIdx.y;      // b*H + h
    const int tid = threadIdx.x;
    const int ty = tid >> 4, tx = tid & 15;
    const int lr  = tid >> 2;          // loader row 0..63
    const int ld4 = (tid & 3) * 4;     // loader col offset
    const float scale = 0.125f;        // HS^-0.5

    const size_t qbase = ((size_t)bh * Tv + (size_t)qt * 64) * HSv;
    #pragma unroll
    for (int c = ld4; c < 64; c += 16) {
        float4 q4 = *(const float4*)&g_q[qbase + lr * 64 + c];
        q4.x *= scale; q4.y *= scale; q4.z *= scale; q4.w *= scale;
        *(float4*)&Qs[lr * 64 + c] = q4;
    }

    float m_i[4], l_i[4], acc[4][4];
    #pragma unroll
    for (int i = 0; i < 4; i++) {
        m_i[i] = -1e30f; l_i[i] = 0.0f;
        #pragma unroll
        for (int j = 0; j < 4; j++) acc[i][j] = 0.0f;
    }

    for (int jt = 0; jt <= qt; jt++) {
        __syncthreads();
        const size_t kvbase = ((size_t)bh * Tv + (size_t)jt * 64) * HSv;
        #pragma unroll
        for (int c = ld4; c < 64; c += 16) {
            float4 k4 = *(const float4*)&g_k[kvbase + lr * 64 + c];
            KsT[(c + 0) * 68 + lr] = k4.x;
            KsT[(c + 1) * 68 + lr] = k4.y;
            KsT[(c + 2) * 68 + lr] = k4.z;
            KsT[(c + 3) * 68 + lr] = k4.w;
            float4 v4 = *(const float4*)&g_v[kvbase + lr * 64 + c];
            *(float4*)&Vs[lr * 64 + c] = v4;
        }
        __syncthreads();

        // S = Q K^T  (64x64x64), register tiled
        float s[4][4] = {};
        #pragma unroll
        for (int d4 = 0; d4 < 64; d4 += 4) {
            float4 qv[4], kv[4];
            #pragma unroll
            for (int i = 0; i < 4; i++)  qv[i]  = *(const float4*)&Qs[(4 * ty + i) * 64 + d4];
            #pragma unroll
            for (int dd = 0; dd < 4; dd++) kv[dd] = *(const float4*)&KsT[(d4 + dd) * 68 + 4 * tx];
            #pragma unroll
            for (int i = 0; i < 4; i++) {
                s[i][0] += qv[i].x*kv[0].x + qv[i].y*kv[1].x + qv[i].z*kv[2].x + qv[i].w*kv[3].x;
                s[i][1] += qv[i].x*kv[0].y + qv[i].y*kv[1].y + qv[i].z*kv[2].y + qv[i].w*kv[3].y;
                s[i][2] += qv[i].x*kv[0].z + qv[i].y*kv[1].z + qv[i].z*kv[2].z + qv[i].w*kv[3].z;
                s[i][3] += qv[i].x*kv[0].w + qv[i].y*kv[1].w + qv[i].z*kv[2].w + qv[i].w*kv[3].w;
            }
        }

        if (jt == qt) {  // causal mask on diagonal tile only
            #pragma unroll
            for (int i = 0; i < 4; i++) {
                int r = 4 * ty + i;
                #pragma unroll
                for (int j = 0; j < 4; j++)
                    if (4 * tx + j > r) s[i][j] = -1e30f;
            }
        }

        // online softmax; row groups are the 16 lanes sharing ty
        #pragma unroll
        for (int i = 0; i < 4; i++) {
            float mx = fmaxf(fmaxf(s[i][0], s[i][1]), fmaxf(s[i][2], s[i][3]));
            mx = fmaxf(mx, __shfl_xor_sync(0xffffffffu, mx, 1));
            mx = fmaxf(mx, __shfl_xor_sync(0xffffffffu, mx, 2));
            mx = fmaxf(mx, __shfl_xor_sync(0xffffffffu, mx, 4));
            mx = fmaxf(mx, __shfl_xor_sync(0xffffffffu, mx, 8));
            float m_new = fmaxf(m_i[i], mx);
            float fct = __expf(m_i[i] - m_new);
            float p0 = __expf(s[i][0] - m_new);
            float p1 = __expf(s[i][1] - m_new);
            float p2 = __expf(s[i][2] - m_new);
            float p3 = __expf(s[i][3] - m_new);
            float rs = p0 + p1 + p2 + p3;
            rs += __shfl_xor_sync(0xffffffffu, rs, 1);
            rs += __shfl_xor_sync(0xffffffffu, rs, 2);
            rs += __shfl_xor_sync(0xffffffffu, rs, 4);
            rs += __shfl_xor_sync(0xffffffffu, rs, 8);
            l_i[i] = l_i[i] * fct + rs;
            m_i[i] = m_new;
            acc[i][0] *= fct; acc[i][1] *= fct; acc[i][2] *= fct; acc[i][3] *= fct;
            *(float4*)&Ps[(4 * ty + i) * 64 + 4 * tx] = make_float4(p0, p1, p2, p3);
        }
        __syncthreads();

        // acc += P @ V  (64x64x64)
        #pragma unroll
        for (int c4 = 0; c4 < 64; c4 += 4) {
            float4 pv[4], vv[4];
            #pragma unroll
            for (int i = 0; i < 4; i++)   pv[i]  = *(const float4*)&Ps[(4 * ty + i) * 64 + c4];
            #pragma unroll
            for (int cc = 0; cc < 4; cc++) vv[cc] = *(const float4*)&Vs[(c4 + cc) * 64 + 4 * tx];
            #pragma unroll
            for (int i = 0; i < 4; i++) {
                acc[i][0] += pv[i].x*vv[0].x + pv[i].y*vv[1].x + pv[i].z*vv[2].x + pv[i].w*vv[3].x;
                acc[i][1] += pv[i].x*vv[0].y + pv[i].y*vv[1].y + pv[i].z*vv[2].y + pv[i].w*vv[3].y;
                acc[i][2] += pv[i].x*vv[0].z + pv[i].y*vv[1].z + pv[i].z*vv[2].z + pv[i].w*vv[3].z;
                acc[i][3] += pv[i].x*vv[0].w + pv[i].y*vv[1].w + pv[i].z*vv[2].w + pv[i].w*vv[3].w;
            }
        }
    }

    const int b = bh >> 4, h = bh & 15;
    #pragma unroll
    for (int i = 0; i < 4; i++) {
        float inv = 1.0f / l_i[i];
        int t = qt * 64 + 4 * ty + i;
        float4 o = make_float4(acc[i][0] * inv, acc[i][1] * inv, acc[i][2] * inv, acc[i][3] * inv);
        *(float4*)&g_combo[((size_t)b * Tv + t) * Cv + h * 64 + 4 * tx] = o;
    }
}

// ---------------------------------------------------------------------------
// Kernel 3: out = combo @ Wproj^T + bproj.  B[k][n] = Wproj[n*C + k].
// ---------------------------------------------------------------------------
__global__ __launch_bounds__(256) void proj_kernel(
    const float* __restrict__ Wp,
    const float* __restrict__ bias,
    float* __restrict__ out)
{
    __shared__ float As[16][68];
    __shared__ float Bs[16][68];
    const int m0 = blockIdx.y * 64;
    const int n0 = blockIdx.x * 64;
    const int tid = threadIdx.x;
    const int ty = tid >> 4, tx = tid & 15;
    const int am = tid >> 2, ak4 = (tid & 3) * 4;

    float acc[4][4] = {};

    for (int k0 = 0; k0 < Cv; k0 += 16) {
        float4 a4 = *(const float4*)&g_combo[(size_t)(m0 + am) * Cv + k0 + ak4];
        As[ak4 + 0][am] = a4.x; As[ak4 + 1][am] = a4.y;
        As[ak4 + 2][am] = a4.z; As[ak4 + 3][am] = a4.w;
        // Bs[k][n] = Wp[(n0+n)*C + k0+k], coalesced along k
        float4 b4 = *(const float4*)&Wp[(size_t)(n0 + am) * Cv + k0 + ak4];
        Bs[ak4 + 0][am] = b4.x; Bs[ak4 + 1][am] = b4.y;
        Bs[ak4 + 2][am] = b4.z; Bs[ak4 + 3][am] = b4.w;
        __syncthreads();

        #pragma unroll
        for (int kk = 0; kk < 16; kk++) {
            float4 a = *(const float4*)&As[kk][ty * 4];
            float4 b = *(const float4*)&Bs[kk][tx * 4];
            acc[0][0] += a.x*b.x; acc[0][1] += a.x*b.y; acc[0][2] += a.x*b.z; acc[0][3] += a.x*b.w;
            acc[1][0] += a.y*b.x; acc[1][1] += a.y*b.y; acc[1][2] += a.y*b.z; acc[1][3] += a.y*b.w;
            acc[2][0] += a.z*b.x; acc[2][1] += a.z*b.y; acc[2][2] += a.z*b.z; acc[2][3] += a.z*b.w;
            acc[3][0] += a.w*b.x; acc[3][1] += a.w*b.y; acc[3][2] += a.w*b.z; acc[3][3] += a.w*b.w;
        }
        __syncthreads();
    }

    float4 bv = *(const float4*)&bias[n0 + tx * 4];
    #pragma unroll
    for (int i = 0; i < 4; i++) {
        int m = m0 + ty * 4 + i;
        float4 o = make_float4(acc[i][0] + bv.x, acc[i][1] + bv.y,
                               acc[i][2] + bv.z, acc[i][3] + bv.w);
        *(float4*)&out[(size_t)m * Cv + n0 + tx * 4] = o;
    }
}

// ---------------------------------------------------------------------------
extern "C" void kernel_launch(void* const* d_in, const int* in_sizes, int n_in,
                              void* d_out, int out_size)
{
    const float* x  = (const float*)d_in[0];
    const float* Wq = (const float*)d_in[1];
    const float* Wk = (const float*)d_in[2];
    const float* Wv = (const float*)d_in[3];
    const float* Wp = (const float*)d_in[4];
    const float* bp = (const float*)d_in[5];
    float* out = (float*)d_out;

    qkv_kernel<<<dim3(Hv, Mv / 64, 3), 256>>>(x, Wq, Wk, Wv);

    const int shmem = (64 * 64 + 64 * 68 + 64 * 64 + 64 * 64) * (int)sizeof(float); // 66560 B
    cudaFuncSetAttribute(flash_kernel, cudaFuncAttributeMaxDynamicSharedMemorySize, shmem);
    flash_kernel<<<dim3(Tv / 64, Bv * Hv), 256, shmem>>>();

    proj_kernel<<<dim3(Cv / 64, Mv / 64), 256>>>(Wp, bp, out);
}

// round 4
// speedup vs baseline: 1.6562x; 1.6562x over previous
#include <cuda_runtime.h>
#include <cuda_bf16.h>
#include <stdint.h>

#define Bv 4
#define Tv 2048
#define Cv 1024
#define Hv 16
#define HSv 64
#define Mv (Bv*Tv)   /* 8192 */
#define NC 32        /* K=1024 / BK=32 */

// ---------------------------------------------------------------------------
// Static device scratch (no runtime allocation)
// ---------------------------------------------------------------------------
__device__ float g_q[Bv*Hv*Tv*HSv];
__device__ float g_k[Bv*Hv*Tv*HSv];
__device__ float g_v[Bv*Hv*Tv*HSv];
__device__ float g_combo[(size_t)Mv*Cv];

__device__ __nv_bfloat16 g_xhi[(size_t)Mv*Cv],  g_xlo[(size_t)Mv*Cv];
__device__ __nv_bfloat16 g_chi[(size_t)Mv*Cv],  g_clo[(size_t)Mv*Cv];
__device__ __nv_bfloat16 g_wthi[(size_t)3*Hv*HSv*Cv], g_wtlo[(size_t)3*Hv*HSv*Cv];
__device__ __nv_bfloat16 g_wphi[(size_t)Cv*Cv], g_wplo[(size_t)Cv*Cv];

// ---------------------------------------------------------------------------
// Helpers
// ---------------------------------------------------------------------------
__device__ __forceinline__ uint32_t smem_u32(const void* p) {
    uint32_t a;
    asm("{ .reg .u64 t; cvta.to.shared.u64 t, %1; cvt.u32.u64 %0, t; }" : "=r"(a) : "l"(p));
    return a;
}

__device__ __forceinline__ void ldm_x4(uint32_t* r, uint32_t a) {
    asm volatile("ldmatrix.sync.aligned.m8n8.x4.shared.b16 {%0,%1,%2,%3}, [%4];"
        : "=r"(r[0]), "=r"(r[1]), "=r"(r[2]), "=r"(r[3]) : "r"(a));
}
__device__ __forceinline__ void ldm_x2(uint32_t* r, uint32_t a) {
    asm volatile("ldmatrix.sync.aligned.m8n8.x2.shared.b16 {%0,%1}, [%2];"
        : "=r"(r[0]), "=r"(r[1]) : "r"(a));
}
__device__ __forceinline__ void mma16816(float* d, const uint32_t* a, const uint32_t* b) {
    asm volatile(
        "mma.sync.aligned.m16n8k16.row.col.f32.bf16.bf16.f32 "
        "{%0,%1,%2,%3}, {%4,%5,%6,%7}, {%8,%9}, {%0,%1,%2,%3};"
        : "+f"(d[0]), "+f"(d[1]), "+f"(d[2]), "+f"(d[3])
        : "r"(a[0]), "r"(a[1]), "r"(a[2]), "r"(a[3]), "r"(b[0]), "r"(b[1]));
}

#define CP_ASYNC(dst, src) \
    asm volatile("cp.async.cg.shared.global [%0], [%1], 16;" :: "r"(dst), "l"(src) : "memory")
#define CP_COMMIT() asm volatile("cp.async.commit_group;" ::: "memory")
#define CP_WAIT1()  asm volatile("cp.async.wait_group 1;" ::: "memory")
#define CP_WAIT0()  asm volatile("cp.async.wait_group 0;" ::: "memory")

// ---------------------------------------------------------------------------
// Decompose fp32 -> bf16 hi + bf16 lo
// ---------------------------------------------------------------------------
__global__ void decomp_kernel(const float* __restrict__ src,
                              __nv_bfloat16* __restrict__ hi,
                              __nv_bfloat16* __restrict__ lo, int n4)
{
    int i = blockIdx.x * blockDim.x + threadIdx.x;
    if (i >= n4) return;
    float4 v = ((const float4*)src)[i];
    __nv_bfloat16 h0 = __float2bfloat16(v.x);
    __nv_bfloat16 h1 = __float2bfloat16(v.y);
    __nv_bfloat16 h2 = __float2bfloat16(v.z);
    __nv_bfloat16 h3 = __float2bfloat16(v.w);
    __nv_bfloat16 l0 = __float2bfloat16(v.x - __bfloat162float(h0));
    __nv_bfloat16 l1 = __float2bfloat16(v.y - __bfloat162float(h1));
    __nv_bfloat16 l2 = __float2bfloat16(v.z - __bfloat162float(h2));
    __nv_bfloat16 l3 = __float2bfloat16(v.w - __bfloat162float(h3));
    __nv_bfloat162* hp = (__nv_bfloat162*)hi;
    __nv_bfloat162* lp = (__nv_bfloat162*)lo;
    hp[2*i]   = __nv_bfloat162(h0, h1);
    hp[2*i+1] = __nv_bfloat162(h2, h3);
    lp[2*i]   = __nv_bfloat162(l0, l1);
    lp[2*i+1] = __nv_bfloat162(l2, l3);
}

// ---------------------------------------------------------------------------
// Transpose + decompose Wq/Wk/Wv: W[h][c][d] -> Wt[mat][h][d][c]  (bf16 hi/lo)
// ---------------------------------------------------------------------------
__global__ __launch_bounds__(256) void wtrans_kernel(
    const float* __restrict__ Wq, const float* __restrict__ Wk, const float* __restrict__ Wv)
{
    __shared__ float ts[64][65];
    const int c0 = blockIdx.x * 64;
    const int h  = blockIdx.y;
    const int mat = blockIdx.z;
    const float* W = (mat == 0) ? Wq : (mat == 1 ? Wk : Wv);
    const int tid = threadIdx.x;

    #pragma unroll
    for (int i = 0; i < 16; i++) {
        int idx = tid + i * 256;
        int r = idx >> 6, d = idx & 63;
        ts[r][d] = W[(size_t)h * (Cv * HSv) + (size_t)(c0 + r) * HSv + d];
    }
    __syncthreads();
    #pragma unroll
    for (int i = 0; i < 16; i++) {
        int idx = tid + i * 256;
        int dd = idx >> 6, cc = idx & 63;
        float v = ts[cc][dd];
        __nv_bfloat16 hv = __float2bfloat16(v);
        __nv_bfloat16 lv = __float2bfloat16(v - __bfloat162float(hv));
        size_t o = ((size_t)(mat * Hv + h) * HSv + dd) * Cv + c0 + cc;
        g_wthi[o] = hv;
        g_wtlo[o] = lv;
    }
}

// ---------------------------------------------------------------------------
// bf16x3 GEMM on mma.sync (HMMA).  C[m][n] = sum_k A[m][k] * B[n][k]
// MODE 0: QKV  (A = x hi/lo,     B = Wt[mat],  out -> g_q/g_k/g_v (b,h,t,d))
// MODE 1: proj (A = combo hi/lo, B = Wp,       out -> outp + bias)
// CTA: 128x128, BK=32, 8 warps (2x4), warp tile 64x32.
// smem per stage (40960 B): Ahi | Alo | Bhi | Blo, each 128 rows x 40 bf16 (80B).
// ---------------------------------------------------------------------------
template<int MODE>
__global__ __launch_bounds__(256) void gemm_kernel(const float* __restrict__ bias,
                                                   float* __restrict__ outp)
{
    extern __shared__ char smem[];
    const uint32_t sb = smem_u32(smem);
    const int tid = threadIdx.x, lane = tid & 31, wid = tid >> 5;
    const int wm = wid & 1, wn = wid >> 1;
    const int nb = blockIdx.x, m0 = blockIdx.y * 128, mat = blockIdx.z;

    const __nv_bfloat16 *ahi, *alo, *bhi, *blo;
    if (MODE == 0) {
        ahi = g_xhi; alo = g_xlo;
        bhi = g_wthi + (size_t)mat * (Hv * HSv * Cv);
        blo = g_wtlo + (size_t)mat * (Hv * HSv * Cv);
    } else {
        ahi = g_chi; alo = g_clo;
        bhi = g_wphi; blo = g_wplo;
    }

    // cp.async loader: 2048 16B slots per stage, 8 per thread
    auto issue = [&](int c, int stg) {
        const int kc0 = c * 32;
        const uint32_t sbase = sb + (uint32_t)stg * 40960u;
        #pragma unroll
        for (int i = 0; i < 8; i++) {
            int s = tid + i * 256;
            int ms = s >> 9, r = (s >> 2) & 127, c4 = s & 3;
            const __nv_bfloat16* src = (ms == 0) ? ahi : (ms == 1) ? alo : (ms == 2) ? bhi : blo;
            int row = ((ms < 2) ? m0 : nb * 128) + r;
            const void* g = src + (size_t)row * Cv + kc0 + c4 * 8;
            uint32_t d = sbase + (uint32_t)ms * 10240u + (uint32_t)(r * 40 + c4 * 8) * 2u;
            CP_ASYNC(d, g);
        }
        CP_COMMIT();
    };

    issue(0, 0);
    issue(1, 1);

    float acc[4][4][4] = {};

    for (int c = 0; c < NC; c++) {
        if (c + 1 < NC) CP_WAIT1(); else CP_WAIT0();
        __syncthreads();
        const uint32_t stg = sb + (uint32_t)(c & 1) * 40960u;

        #pragma unroll
        for (int ks = 0; ks < 2; ks++) {
            uint32_t a_hi[4][4], a_lo[4][4], b_hi[4][2], b_lo[4][2];
            // A fragments: ldmatrix x4 (row-major m16 x k16 tile)
            const int arow = (lane & 7) + ((lane >> 3) & 1) * 8;
            const int acol = ks * 16 + (lane >> 4) * 8;
            #pragma unroll
            for (int mt = 0; mt < 4; mt++) {
                uint32_t off = (uint32_t)(((wm * 64 + mt * 16 + arow) * 40 + acol) * 2);
                ldm_x4(a_hi[mt], stg + off);
                ldm_x4(a_lo[mt], stg + 10240u + off);
            }
            // B fragments: ldmatrix x2 on B^T rows ([n][k])
            const int brow = lane & 7;
            const int bcol = ks * 16 + ((lane >> 3) & 1) * 8;
            #pragma unroll
            for (int nt = 0; nt < 4; nt++) {
                uint32_t off = (uint32_t)(((wn * 32 + nt * 8 + brow) * 40 + bcol) * 2);
                ldm_x2(b_hi[nt], stg + 20480u + off);
                ldm_x2(b_lo[nt], stg + 30720u + off);
            }
            #pragma unroll
            for (int mt = 0; mt < 4; mt++)
                #pragma unroll
                for (int nt = 0; nt < 4; nt++) {
                    mma16816(acc[mt][nt], a_hi[mt], b_hi[nt]);
                    mma16816(acc[mt][nt], a_hi[mt], b_lo[nt]);
                    mma16816(acc[mt][nt], a_lo[mt], b_hi[nt]);
                }
        }
        __syncthreads();
        if (c + 2 < NC) issue(c + 2, c & 1);
    }

    // Epilogue. Fragment: c0=(g,2tig) c1=(g,2tig+1) c2=(g+8,2tig) c3=(g+8,2tig+1)
    const int g = lane >> 2, tig = lane & 3;
    #pragma unroll
    for (int mt = 0; mt < 4; mt++) {
        const int r0 = m0 + wm * 64 + mt * 16 + g;
        const int r1 = r0 + 8;
        #pragma unroll
        for (int nt = 0; nt < 4; nt++) {
            const int n = nb * 128 + wn * 32 + nt * 8 + tig * 2;
            if (MODE == 0) {
                const int h = n >> 6, dd = n & 63;
                float* go = (mat == 0) ? g_q : (mat == 1 ? g_k : g_v);
                int b0 = r0 >> 11, t0 = r0 & (Tv - 1);
                int b1 = r1 >> 11, t1 = r1 & (Tv - 1);
                *(float2*)&go[(((size_t)(b0 * Hv + h)) * Tv + t0) * HSv + dd] =
                    make_float2(acc[mt][nt][0], acc[mt][nt][1]);
                *(float2*)&go[(((size_t)(b1 * Hv + h)) * Tv + t1) * HSv + dd] =
                    make_float2(acc[mt][nt][2], acc[mt][nt][3]);
            } else {
                float2 bv = *(const float2*)&bias[n];
                *(float2*)&outp[(size_t)r0 * Cv + n] =
                    make_float2(acc[mt][nt][0] + bv.x, acc[mt][nt][1] + bv.y);
                *(float2*)&outp[(size_t)r1 * Cv + n] =
                    make_float2(acc[mt][nt][2] + bv.x, acc[mt][nt][3] + bv.y);
            }
        }
    }
}

// ---------------------------------------------------------------------------
// Causal flash attention (fp32 SIMT — known correct from R2)
// ---------------------------------------------------------------------------
__global__ __launch_bounds__(256) void flash_kernel()
{
    extern __shared__ float sm[];
    float* Qs  = sm;
    float* KsT = Qs  + 64 * 64;
    float* Vs  = KsT + 64 * 68;
    float* Ps  = Vs  + 64 * 64;

    const int qt  = blockIdx.x;
    const int bh  = blockIdx.y;
    const int tid = threadIdx.x;
    const int ty = tid >> 4, tx = tid & 15;
    const int lr  = tid >> 2;
    const int ld4 = (tid & 3) * 4;
    const float scale = 0.125f;

    const size_t qbase = ((size_t)bh * Tv + (size_t)qt * 64) * HSv;
    #pragma unroll
    for (int c = ld4; c < 64; c += 16) {
        float4 q4 = *(const float4*)&g_q[qbase + lr * 64 + c];
        q4.x *= scale; q4.y *= scale; q4.z *= scale; q4.w *= scale;
        *(float4*)&Qs[lr * 64 + c] = q4;
    }

    float m_i[4], l_i[4], acc[4][4];
    #pragma unroll
    for (int i = 0; i < 4; i++) {
        m_i[i] = -1e30f; l_i[i] = 0.0f;
        #pragma unroll
        for (int j = 0; j < 4; j++) acc[i][j] = 0.0f;
    }

    for (int jt = 0; jt <= qt; jt++) {
        __syncthreads();
        const size_t kvbase = ((size_t)bh * Tv + (size_t)jt * 64) * HSv;
        #pragma unroll
        for (int c = ld4; c < 64; c += 16) {
            float4 k4 = *(const float4*)&g_k[kvbase + lr * 64 + c];
            KsT[(c + 0) * 68 + lr] = k4.x;
            KsT[(c + 1) * 68 + lr] = k4.y;
            KsT[(c + 2) * 68 + lr] = k4.z;
            KsT[(c + 3) * 68 + lr] = k4.w;
            float4 v4 = *(const float4*)&g_v[kvbase + lr * 64 + c];
            *(float4*)&Vs[lr * 64 + c] = v4;
        }
        __syncthreads();

        float s[4][4] = {};
        #pragma unroll
        for (int d4 = 0; d4 < 64; d4 += 4) {
            float4 qv[4], kv[4];
            #pragma unroll
            for (int i = 0; i < 4; i++)  qv[i]  = *(const float4*)&Qs[(4 * ty + i) * 64 + d4];
            #pragma unroll
            for (int dd = 0; dd < 4; dd++) kv[dd] = *(const float4*)&KsT[(d4 + dd) * 68 + 4 * tx];
            #pragma unroll
            for (int i = 0; i < 4; i++) {
                s[i][0] += qv[i].x*kv[0].x + qv[i].y*kv[1].x + qv[i].z*kv[2].x + qv[i].w*kv[3].x;
                s[i][1] += qv[i].x*kv[0].y + qv[i].y*kv[1].y + qv[i].z*kv[2].y + qv[i].w*kv[3].y;
                s[i][2] += qv[i].x*kv[0].z + qv[i].y*kv[1].z + qv[i].z*kv[2].z + qv[i].w*kv[3].z;
                s[i][3] += qv[i].x*kv[0].w + qv[i].y*kv[1].w + qv[i].z*kv[2].w + qv[i].w*kv[3].w;
            }
        }

        if (jt == qt) {
            #pragma unroll
            for (int i = 0; i < 4; i++) {
                int r = 4 * ty + i;
                #pragma unroll
                for (int j = 0; j < 4; j++)
                    if (4 * tx + j > r) s[i][j] = -1e30f;
            }
        }

        #pragma unroll
        for (int i = 0; i < 4; i++) {
            float mx = fmaxf(fmaxf(s[i][0], s[i][1]), fmaxf(s[i][2], s[i][3]));
            mx = fmaxf(mx, __shfl_xor_sync(0xffffffffu, mx, 1));
            mx = fmaxf(mx, __shfl_xor_sync(0xffffffffu, mx, 2));
            mx = fmaxf(mx, __shfl_xor_sync(0xffffffffu, mx, 4));
            mx = fmaxf(mx, __shfl_xor_sync(0xffffffffu, mx, 8));
            float m_new = fmaxf(m_i[i], mx);
            float fct = __expf(m_i[i] - m_new);
            float p0 = __expf(s[i][0] - m_new);
            float p1 = __expf(s[i][1] - m_new);
            float p2 = __expf(s[i][2] - m_new);
            float p3 = __expf(s[i][3] - m_new);
            float rs = p0 + p1 + p2 + p3;
            rs += __shfl_xor_sync(0xffffffffu, rs, 1);
            rs += __shfl_xor_sync(0xffffffffu, rs, 2);
            rs += __shfl_xor_sync(0xffffffffu, rs, 4);
            rs += __shfl_xor_sync(0xffffffffu, rs, 8);
            l_i[i] = l_i[i] * fct + rs;
            m_i[i] = m_new;
            acc[i][0] *= fct; acc[i][1] *= fct; acc[i][2] *= fct; acc[i][3] *= fct;
            *(float4*)&Ps[(4 * ty + i) * 64 + 4 * tx] = make_float4(p0, p1, p2, p3);
        }
        __syncthreads();

        #pragma unroll
        for (int c4 = 0; c4 < 64; c4 += 4) {
            float4 pv[4], vv[4];
            #pragma unroll
            for (int i = 0; i < 4; i++)   pv[i]  = *(const float4*)&Ps[(4 * ty + i) * 64 + c4];
            #pragma unroll
            for (int cc = 0; cc < 4; cc++) vv[cc] = *(const float4*)&Vs[(c4 + cc) * 64 + 4 * tx];
            #pragma unroll
            for (int i = 0; i < 4; i++) {
                acc[i][0] += pv[i].x*vv[0].x + pv[i].y*vv[1].x + pv[i].z*vv[2].x + pv[i].w*vv[3].x;
                acc[i][1] += pv[i].x*vv[0].y + pv[i].y*vv[1].y + pv[i].z*vv[2].y + pv[i].w*vv[3].y;
                acc[i][2] += pv[i].x*vv[0].z + pv[i].y*vv[1].z + pv[i].z*vv[2].z + pv[i].w*vv[3].z;
                acc[i][3] += pv[i].x*vv[0].w + pv[i].y*vv[1].w + pv[i].z*vv[2].w + pv[i].w*vv[3].w;
            }
        }
    }

    const int b = bh >> 4, h = bh & 15;
    #pragma unroll
    for (int i = 0; i < 4; i++) {
        float inv = 1.0f / l_i[i];
        int t = qt * 64 + 4 * ty + i;
        float4 o = make_float4(acc[i][0] * inv, acc[i][1] * inv, acc[i][2] * inv, acc[i][3] * inv);
        *(float4*)&g_combo[((size_t)b * Tv + t) * Cv + h * 64 + 4 * tx] = o;
    }
}

// ---------------------------------------------------------------------------
extern "C" void kernel_launch(void* const* d_in, const int* in_sizes, int n_in,
                              void* d_out, int out_size)
{
    const float* x  = (const float*)d_in[0];
    const float* Wq = (const float*)d_in[1];
    const float* Wk = (const float*)d_in[2];
    const float* Wv = (const float*)d_in[3];
    const float* Wp = (const float*)d_in[4];
    const float* bp = (const float*)d_in[5];
    float* out = (float*)d_out;

    __nv_bfloat16 *xhi, *xlo, *wphi, *wplo, *chi, *clo;
    float* combo;
    cudaGetSymbolAddress((void**)&xhi,  g_xhi);
    cudaGetSymbolAddress((void**)&xlo,  g_xlo);
    cudaGetSymbolAddress((void**)&wphi, g_wphi);
    cudaGetSymbolAddress((void**)&wplo, g_wplo);
    cudaGetSymbolAddress((void**)&chi,  g_chi);
    cudaGetSymbolAddress((void**)&clo,  g_clo);
    cudaGetSymbolAddress((void**)&combo, g_combo);

    const int gemm_smem = 2 * 40960; // 81920 B
    cudaFuncSetAttribute(gemm_kernel<0>, cudaFuncAttributeMaxDynamicSharedMemorySize, gemm_smem);
    cudaFuncSetAttribute(gemm_kernel<1>, cudaFuncAttributeMaxDynamicSharedMemorySize, gemm_smem);

    // 1. decompose x, Wproj; transpose+decompose Wq/k/v
    decomp_kernel<<<(Mv * Cv / 4 + 255) / 256, 256>>>(x, xhi, xlo, Mv * Cv / 4);
    decomp_kernel<<<(Cv * Cv / 4 + 255) / 256, 256>>>(Wp, wphi, wplo, Cv * Cv / 4);
    wtrans_kernel<<<dim3(Cv / 64, Hv, 3), 256>>>(Wq, Wk, Wv);

    // 2. QKV projections (HMMA bf16x3)
    gemm_kernel<0><<<dim3(Cv / 128, Mv / 128, 3), 256, gemm_smem>>>(nullptr, nullptr);

    // 3. causal flash attention (fp32)
    const int fl_smem = (64 * 64 + 64 * 68 + 64 * 64 + 64 * 64) * (int)sizeof(float);
    cudaFuncSetAttribute(flash_kernel, cudaFuncAttributeMaxDynamicSharedMemorySize, fl_smem);
    flash_kernel<<<dim3(Tv / 64, Bv * Hv), 256, fl_smem>>>();

    // 4. decompose combo, output projection (HMMA bf16x3) + bias
    decomp_kernel<<<(Mv * Cv / 4 + 255) / 256, 256>>>(combo, chi, clo, Mv * Cv / 4);
    gemm_kernel<1><<<dim3(Cv / 128, Mv / 128, 1), 256, gemm_smem>>>(bp, out);
}

// round 5
// speedup vs baseline: 2.5934x; 1.5659x over previous
#include <cuda_runtime.h>
#include <cuda_bf16.h>
#include <stdint.h>

#define Bv 4
#define Tv 2048
#define Cv 1024
#define Hv 16
#define HSv 64
#define Mv (Bv*Tv)   /* 8192 */
#define NC 32        /* K=1024 / BK=32 */

// ---------------------------------------------------------------------------
// Static device scratch (no runtime allocation)
// ---------------------------------------------------------------------------
__device__ __nv_bfloat16 g_xhi[(size_t)Mv*Cv],  g_xlo[(size_t)Mv*Cv];
__device__ __nv_bfloat16 g_chi[(size_t)Mv*Cv],  g_clo[(size_t)Mv*Cv];
__device__ __nv_bfloat16 g_wthi[(size_t)3*Hv*HSv*Cv], g_wtlo[(size_t)3*Hv*HSv*Cv];
__device__ __nv_bfloat16 g_wphi[(size_t)Cv*Cv], g_wplo[(size_t)Cv*Cv];
__device__ __nv_bfloat16 g_qhi[(size_t)Bv*Hv*Tv*HSv], g_qlo[(size_t)Bv*Hv*Tv*HSv];
__device__ __nv_bfloat16 g_khi[(size_t)Bv*Hv*Tv*HSv], g_klo[(size_t)Bv*Hv*Tv*HSv];
__device__ __nv_bfloat16 g_vhi[(size_t)Bv*Hv*Tv*HSv], g_vlo[(size_t)Bv*Hv*Tv*HSv];

// ---------------------------------------------------------------------------
// Helpers
// ---------------------------------------------------------------------------
__device__ __forceinline__ uint32_t smem_u32(const void* p) {
    uint32_t a;
    asm("{ .reg .u64 t; cvta.to.shared.u64 t, %1; cvt.u32.u64 %0, t; }" : "=r"(a) : "l"(p));
    return a;
}
__device__ __forceinline__ void ldm_x4(uint32_t* r, uint32_t a) {
    asm volatile("ldmatrix.sync.aligned.m8n8.x4.shared.b16 {%0,%1,%2,%3}, [%4];"
        : "=r"(r[0]), "=r"(r[1]), "=r"(r[2]), "=r"(r[3]) : "r"(a));
}
__device__ __forceinline__ void ldm_x4t(uint32_t* r, uint32_t a) {
    asm volatile("ldmatrix.sync.aligned.m8n8.x4.trans.shared.b16 {%0,%1,%2,%3}, [%4];"
        : "=r"(r[0]), "=r"(r[1]), "=r"(r[2]), "=r"(r[3]) : "r"(a));
}
__device__ __forceinline__ void ldm_x2(uint32_t* r, uint32_t a) {
    asm volatile("ldmatrix.sync.aligned.m8n8.x2.shared.b16 {%0,%1}, [%2];"
        : "=r"(r[0]), "=r"(r[1]) : "r"(a));
}
__device__ __forceinline__ void mma16816(float* d, const uint32_t* a, const uint32_t* b) {
    asm volatile(
        "mma.sync.aligned.m16n8k16.row.col.f32.bf16.bf16.f32 "
        "{%0,%1,%2,%3}, {%4,%5,%6,%7}, {%8,%9}, {%0,%1,%2,%3};"
        : "+f"(d[0]), "+f"(d[1]), "+f"(d[2]), "+f"(d[3])
        : "r"(a[0]), "r"(a[1]), "r"(a[2]), "r"(a[3]), "r"(b[0]), "r"(b[1]));
}
#define CP_ASYNC(dst, src) \
    asm volatile("cp.async.cg.shared.global [%0], [%1], 16;" :: "r"(dst), "l"(src) : "memory")
#define CP_COMMIT() asm volatile("cp.async.commit_group;" ::: "memory")
#define CP_WAIT1()  asm volatile("cp.async.wait_group 1;" ::: "memory")
#define CP_WAIT0()  asm volatile("cp.async.wait_group 0;" ::: "memory")

__device__ __forceinline__ uint32_t pack_bf16x2(float a, float b) {
    __nv_bfloat162 t = __floats2bfloat162_rn(a, b);
    return *(uint32_t*)&t;
}
// write fp32 pair (a,b) as bf16 hi/lo pairs at hi[idx],lo[idx]
__device__ __forceinline__ void wr_hilo(__nv_bfloat16* hi, __nv_bfloat16* lo,
                                        size_t idx, float a, float b) {
    __nv_bfloat16 ha = __float2bfloat16(a), hb = __float2bfloat16(b);
    __nv_bfloat162 h2; h2.x = ha; h2.y = hb;
    *(__nv_bfloat162*)&hi[idx] = h2;
    __nv_bfloat162 l2;
    l2.x = __float2bfloat16(a - __bfloat162float(ha));
    l2.y = __float2bfloat16(b - __bfloat162float(hb));
    *(__nv_bfloat162*)&lo[idx] = l2;
}

// ---------------------------------------------------------------------------
// Decompose fp32 -> bf16 hi + bf16 lo
// ---------------------------------------------------------------------------
__global__ void decomp_kernel(const float* __restrict__ src,
                              __nv_bfloat16* __restrict__ hi,
                              __nv_bfloat16* __restrict__ lo, int n4)
{
    int i = blockIdx.x * blockDim.x + threadIdx.x;
    if (i >= n4) return;
    float4 v = ((const float4*)src)[i];
    __nv_bfloat16 h0 = __float2bfloat16(v.x);
    __nv_bfloat16 h1 = __float2bfloat16(v.y);
    __nv_bfloat16 h2 = __float2bfloat16(v.z);
    __nv_bfloat16 h3 = __float2bfloat16(v.w);
    __nv_bfloat162* hp = (__nv_bfloat162*)hi;
    __nv_bfloat162* lp = (__nv_bfloat162*)lo;
    hp[2*i]   = __nv_bfloat162(h0, h1);
    hp[2*i+1] = __nv_bfloat162(h2, h3);
    lp[2*i]   = __nv_bfloat162(__float2bfloat16(v.x - __bfloat162float(h0)),
                               __float2bfloat16(v.y - __bfloat162float(h1)));
    lp[2*i+1] = __nv_bfloat162(__float2bfloat16(v.z - __bfloat162float(h2)),
                               __float2bfloat16(v.w - __bfloat162float(h3)));
}

// ---------------------------------------------------------------------------
// Transpose + decompose Wq/Wk/Wv: W[h][c][d] -> Wt[mat][h][d][c]  (bf16 hi/lo)
// ---------------------------------------------------------------------------
__global__ __launch_bounds__(256) void wtrans_kernel(
    const float* __restrict__ Wq, const float* __restrict__ Wk, const float* __restrict__ Wv)
{
    __shared__ float ts[64][65];
    const int c0 = blockIdx.x * 64;
    const int h  = blockIdx.y;
    const int mat = blockIdx.z;
    const float* W = (mat == 0) ? Wq : (mat == 1 ? Wk : Wv);
    const int tid = threadIdx.x;

    #pragma unroll
    for (int i = 0; i < 16; i++) {
        int idx = tid + i * 256;
        int r = idx >> 6, d = idx & 63;
        ts[r][d] = W[(size_t)h * (Cv * HSv) + (size_t)(c0 + r) * HSv + d];
    }
    __syncthreads();
    #pragma unroll
    for (int i = 0; i < 16; i++) {
        int idx = tid + i * 256;
        int dd = idx >> 6, cc = idx & 63;
        float v = ts[cc][dd];
        __nv_bfloat16 hv = __float2bfloat16(v);
        size_t o = ((size_t)(mat * Hv + h) * HSv + dd) * Cv + c0 + cc;
        g_wthi[o] = hv;
        g_wtlo[o] = __float2bfloat16(v - __bfloat162float(hv));
    }
}

// ---------------------------------------------------------------------------
// bf16x3 GEMM on mma.sync (HMMA).
// MODE 0: QKV  -> writes q/k/v as bf16 hi/lo in (b,h,t,d); q scaled by 0.125
// MODE 1: proj -> fp32 out + bias
// CTA 128x128, BK=32, 8 warps (2x4), warp tile 64x32.
// ---------------------------------------------------------------------------
template<int MODE>
__global__ __launch_bounds__(256) void gemm_kernel(const float* __restrict__ bias,
                                                   float* __restrict__ outp)
{
    extern __shared__ char smem[];
    const uint32_t sb = smem_u32(smem);
    const int tid = threadIdx.x, lane = tid & 31, wid = tid >> 5;
    const int wm = wid & 1, wn = wid >> 1;
    const int nb = blockIdx.x, m0 = blockIdx.y * 128, mat = blockIdx.z;

    const __nv_bfloat16 *ahi, *alo, *bhi, *blo;
    if (MODE == 0) {
        ahi = g_xhi; alo = g_xlo;
        bhi = g_wthi + (size_t)mat * (Hv * HSv * Cv);
        blo = g_wtlo + (size_t)mat * (Hv * HSv * Cv);
    } else {
        ahi = g_chi; alo = g_clo;
        bhi = g_wphi; blo = g_wplo;
    }

    auto issue = [&](int c, int stg) {
        const int kc0 = c * 32;
        const uint32_t sbase = sb + (uint32_t)stg * 40960u;
        #pragma unroll
        for (int i = 0; i < 8; i++) {
            int s = tid + i * 256;
            int ms = s >> 9, r = (s >> 2) & 127, c4 = s & 3;
            const __nv_bfloat16* src = (ms == 0) ? ahi : (ms == 1) ? alo : (ms == 2) ? bhi : blo;
            int row = ((ms < 2) ? m0 : nb * 128) + r;
            const void* g = src + (size_t)row * Cv + kc0 + c4 * 8;
            uint32_t d = sbase + (uint32_t)ms * 10240u + (uint32_t)(r * 40 + c4 * 8) * 2u;
            CP_ASYNC(d, g);
        }
        CP_COMMIT();
    };

    issue(0, 0);
    issue(1, 1);

    float acc[4][4][4] = {};

    for (int c = 0; c < NC; c++) {
        if (c + 1 < NC) CP_WAIT1(); else CP_WAIT0();
        __syncthreads();
        const uint32_t stg = sb + (uint32_t)(c & 1) * 40960u;

        #pragma unroll
        for (int ks = 0; ks < 2; ks++) {
            uint32_t a_hi[4][4], a_lo[4][4], b_hi[4][2], b_lo[4][2];
            const int arow = (lane & 7) + ((lane >> 3) & 1) * 8;
            const int acol = ks * 16 + (lane >> 4) * 8;
            #pragma unroll
            for (int mt = 0; mt < 4; mt++) {
                uint32_t off = (uint32_t)(((wm * 64 + mt * 16 + arow) * 40 + acol) * 2);
                ldm_x4(a_hi[mt], stg + off);
                ldm_x4(a_lo[mt], stg + 10240u + off);
            }
            const int brow = lane & 7;
            const int bcol = ks * 16 + ((lane >> 3) & 1) * 8;
            #pragma unroll
            for (int nt = 0; nt < 4; nt++) {
                uint32_t off = (uint32_t)(((wn * 32 + nt * 8 + brow) * 40 + bcol) * 2);
                ldm_x2(b_hi[nt], stg + 20480u + off);
                ldm_x2(b_lo[nt], stg + 30720u + off);
            }
            #pragma unroll
            for (int mt = 0; mt < 4; mt++)
                #pragma unroll
                for (int nt = 0; nt < 4; nt++) {
                    mma16816(acc[mt][nt], a_hi[mt], b_hi[nt]);
                    mma16816(acc[mt][nt], a_hi[mt], b_lo[nt]);
                    mma16816(acc[mt][nt], a_lo[mt], b_hi[nt]);
                }
        }
        __syncthreads();
        if (c + 2 < NC) issue(c + 2, c & 1);
    }

    const int g = lane >> 2, tig = lane & 3;
    const float qscale = (MODE == 0 && mat == 0) ? 0.125f : 1.0f;
    #pragma unroll
    for (int mt = 0; mt < 4; mt++) {
        const int r0 = m0 + wm * 64 + mt * 16 + g;
        const int r1 = r0 + 8;
        #pragma unroll
        for (int nt = 0; nt < 4; nt++) {
            const int n = nb * 128 + wn * 32 + nt * 8 + tig * 2;
            if (MODE == 0) {
                const int h = n >> 6, dd = n & 63;
                __nv_bfloat16 *ghi, *glo;
                if (mat == 0)      { ghi = g_qhi; glo = g_qlo; }
                else if (mat == 1) { ghi = g_khi; glo = g_klo; }
                else               { ghi = g_vhi; glo = g_vlo; }
                int b0 = r0 >> 11, t0 = r0 & (Tv - 1);
                int b1 = r1 >> 11, t1 = r1 & (Tv - 1);
                wr_hilo(ghi, glo, (((size_t)(b0 * Hv + h)) * Tv + t0) * HSv + dd,
                        acc[mt][nt][0] * qscale, acc[mt][nt][1] * qscale);
                wr_hilo(ghi, glo, (((size_t)(b1 * Hv + h)) * Tv + t1) * HSv + dd,
                        acc[mt][nt][2] * qscale, acc[mt][nt][3] * qscale);
            } else {
                float2 bv = *(const float2*)&bias[n];
                *(float2*)&outp[(size_t)r0 * Cv + n] =
                    make_float2(acc[mt][nt][0] + bv.x, acc[mt][nt][1] + bv.y);
                *(float2*)&outp[(size_t)r1 * Cv + n] =
                    make_float2(acc[mt][nt][2] + bv.x, acc[mt][nt][3] + bv.y);
            }
        }
    }
}

// ---------------------------------------------------------------------------
// HMMA causal flash attention. CTA = 128 queries, 8 warps x 16 rows.
// KV tiles of 64 keys, double-buffered cp.async.
// S = qh*kh + qh*kl + ql*kh ; P split hi/lo ; O += ph*vh + ph*vl + pl*vh.
// smem: [2 stages][4 tiles: Khi,Klo,Vhi,Vlo][64 rows x 144B] = 73728 B
// (stage 0 is reused once at start to stage Q hi/lo: 128 rows across tile pairs)
// ---------------------------------------------------------------------------
__global__ __launch_bounds__(256) void flash_kernel()
{
    extern __shared__ char smem[];
    const uint32_t sb = smem_u32(smem);
    const int tid = threadIdx.x, lane = tid & 31, w = tid >> 5;
    const int bx = blockIdx.x, bh = blockIdx.y;
    const int q0 = bx * 128;
    const int qb = q0 + w * 16;
    const int g = lane >> 2, tig = lane & 3;

    // ---- stage Q (hi -> tiles 0/1, lo -> tiles 2/3 of stage 0) ----
    {
        #pragma unroll
        for (int i = 0; i < 8; i++) {
            int s = tid + i * 256;
            int half = s >> 10, r = (s >> 3) & 127, c = s & 7;
            const __nv_bfloat16* src = half ? g_qlo : g_qhi;
            const void* gp = src + ((size_t)bh * Tv + q0 + r) * 64 + c * 8;
            uint32_t d = sb + (uint32_t)(half * 2 + (r >= 64)) * 9216u
                       + (uint32_t)((r & 63) * 144 + c * 16);
            CP_ASYNC(d, gp);
        }
        CP_COMMIT(); CP_WAIT0();
        __syncthreads();
    }
    uint32_t qh[4][4], ql[4][4];
    {
        const int row = w * 16 + (lane & 15);
        const uint32_t hb = sb + ((row >= 64) ? 9216u : 0u);
        const uint32_t lb = sb + 18432u + ((row >= 64) ? 9216u : 0u);
        const int rl = row & 63;
        #pragma unroll
        for (int ks = 0; ks < 4; ks++) {
            uint32_t off = (uint32_t)(rl * 144 + (ks * 16 + (lane >> 4) * 8) * 2);
            ldm_x4(qh[ks], hb + off);
            ldm_x4(ql[ks], lb + off);
        }
    }
    __syncthreads();

    float acc[8][4] = {};
    float m0 = -1e30f, m1 = -1e30f, l0 = 0.0f, l1 = 0.0f;
    const int ntl = 2 * bx + 2;

    auto issueKV = [&](int jt, int stg) {
        const int kv0 = jt * 64;
        #pragma unroll
        for (int i = 0; i < 8; i++) {
            int s = tid + i * 256;
            int tile = s >> 9, r = (s >> 3) & 63, c = s & 7;
            const __nv_bfloat16* src = (tile == 0) ? g_khi : (tile == 1) ? g_klo
                                     : (tile == 2) ? g_vhi : g_vlo;
            const void* gp = src + ((size_t)bh * Tv + kv0 + r) * 64 + c * 8;
            uint32_t d = sb + (uint32_t)stg * 36864u + (uint32_t)tile * 9216u
                       + (uint32_t)(r * 144 + c * 16);
            CP_ASYNC(d, gp);
        }
        CP_COMMIT();
    };
    issueKV(0, 0);
    issueKV(1, 1);

    for (int jt = 0; jt < ntl; jt++) {
        if (jt + 1 < ntl) CP_WAIT1(); else CP_WAIT0();
        __syncthreads();
        const int kv0 = jt * 64;
        const uint32_t stg = sb + (uint32_t)(jt & 1) * 36864u;

        if (kv0 <= qb + 15) {   // warp has at least one unmasked element
            // ---- S = Q K^T (3-term) ----
            float s[8][4] = {};
            #pragma unroll
            for (int ks = 0; ks < 4; ks++) {
                #pragma unroll
                for (int p = 0; p < 4; p++) {
                    uint32_t th[4], tl[4];
                    uint32_t koff = (uint32_t)(
                        (p * 16 + (lane & 7) + ((lane >> 4) & 1) * 8) * 144
                        + (ks * 16 + ((lane >> 3) & 1) * 8) * 2);
                    ldm_x4(th, stg + koff);
                    ldm_x4(tl, stg + 9216u + koff);
                    mma16816(s[2*p],   qh[ks], th);     mma16816(s[2*p],   qh[ks], tl);
                    mma16816(s[2*p],   ql[ks], th);
                    mma16816(s[2*p+1], qh[ks], th + 2); mma16816(s[2*p+1], qh[ks], tl + 2);
                    mma16816(s[2*p+1], ql[ks], th + 2);
                }
            }
            // ---- causal mask ----
            const int row0 = qb + g, row1 = row0 + 8;
            if (kv0 + 63 > row0) {
                #pragma unroll
                for (int nt = 0; nt < 8; nt++) {
                    int c0 = kv0 + nt * 8 + tig * 2;
                    if (c0     > row0) s[nt][0] = -1e30f;
                    if (c0 + 1 > row0) s[nt][1] = -1e30f;
                    if (c0     > row1) s[nt][2] = -1e30f;
                    if (c0 + 1 > row1) s[nt][3] = -1e30f;
                }
            }
            // ---- online softmax ----
            float mx0 = -1e30f, mx1 = -1e30f;
            #pragma unroll
            for (int nt = 0; nt < 8; nt++) {
                mx0 = fmaxf(mx0, fmaxf(s[nt][0], s[nt][1]));
                mx1 = fmaxf(mx1, fmaxf(s[nt][2], s[nt][3]));
            }
            mx0 = fmaxf(mx0, __shfl_xor_sync(0xffffffffu, mx0, 1));
            mx0 = fmaxf(mx0, __shfl_xor_sync(0xffffffffu, mx0, 2));
            mx1 = fmaxf(mx1, __shfl_xor_sync(0xffffffffu, mx1, 1));
            mx1 = fmaxf(mx1, __shfl_xor_sync(0xffffffffu, mx1, 2));
            const float mn0 = fmaxf(m0, mx0), mn1 = fmaxf(m1, mx1);
            const float f0 = __expf(m0 - mn0), f1 = __expf(m1 - mn1);
            m0 = mn0; m1 = mn1;

            uint32_t phi[8][2], plo[8][2];
            float rs0 = 0.0f, rs1 = 0.0f;
            #pragma unroll
            for (int nt = 0; nt < 8; nt++) {
                float p0 = __expf(s[nt][0] - mn0);
                float p1 = __expf(s[nt][1] - mn0);
                float p2 = __expf(s[nt][2] - mn1);
                float p3 = __expf(s[nt][3] - mn1);
                rs0 += p0 + p1; rs1 += p2 + p3;
                __nv_bfloat16 h0 = __float2bfloat16(p0), h1 = __float2bfloat16(p1);
                __nv_bfloat16 h2 = __float2bfloat16(p2), h3 = __float2bfloat16(p3);
                __nv_bfloat162 t01; t01.x = h0; t01.y = h1;
                __nv_bfloat162 t23; t23.x = h2; t23.y = h3;
                phi[nt][0] = *(uint32_t*)&t01;
                phi[nt][1] = *(uint32_t*)&t23;
                plo[nt][0] = pack_bf16x2(p0 - __bfloat162float(h0), p1 - __bfloat162float(h1));
                plo[nt][1] = pack_bf16x2(p2 - __bfloat162float(h2), p3 - __bfloat162float(h3));
            }
            rs0 += __shfl_xor_sync(0xffffffffu, rs0, 1);
            rs0 += __shfl_xor_sync(0xffffffffu, rs0, 2);
            rs1 += __shfl_xor_sync(0xffffffffu, rs1, 1);
            rs1 += __shfl_xor_sync(0xffffffffu, rs1, 2);
            l0 = l0 * f0 + rs0;
            l1 = l1 * f1 + rs1;
            #pragma unroll
            for (int dt = 0; dt < 8; dt++) {
                acc[dt][0] *= f0; acc[dt][1] *= f0;
                acc[dt][2] *= f1; acc[dt][3] *= f1;
            }
            // ---- O += P V (3-term), V via ldmatrix.trans ----
            #pragma unroll
            for (int ks = 0; ks < 4; ks++) {
                uint32_t ah[4] = { phi[2*ks][0], phi[2*ks][1], phi[2*ks+1][0], phi[2*ks+1][1] };
                uint32_t al[4] = { plo[2*ks][0], plo[2*ks][1], plo[2*ks+1][0], plo[2*ks+1][1] };
                #pragma unroll
                for (int dp = 0; dp < 4; dp++) {
                    uint32_t vh[4], vl[4];
                    uint32_t voff = (uint32_t)(
                        (ks * 16 + (lane & 7) + ((lane >> 3) & 1) * 8) * 144
                        + (dp * 16 + (lane >> 4) * 8) * 2);
                    ldm_x4t(vh, stg + 18432u + voff);
                    ldm_x4t(vl, stg + 27648u + voff);
                    mma16816(acc[2*dp],   ah, vh);     mma16816(acc[2*dp],   ah, vl);
                    mma16816(acc[2*dp],   al, vh);
                    mma16816(acc[2*dp+1], ah, vh + 2); mma16816(acc[2*dp+1], ah, vl + 2);
                    mma16816(acc[2*dp+1], al, vh + 2);
                }
            }
        }
        __syncthreads();
        if (jt + 2 < ntl) issueKV(jt + 2, jt & 1);
    }

    // ---- epilogue: combo hi/lo ----
    const float inv0 = 1.0f / l0, inv1 = 1.0f / l1;
    const int b = bh >> 4, h = bh & 15;
    const int t0 = qb + g, t1 = t0 + 8;
    #pragma unroll
    for (int dt = 0; dt < 8; dt++) {
        const int col = h * 64 + dt * 8 + tig * 2;
        wr_hilo(g_chi, g_clo, ((size_t)b * Tv + t0) * Cv + col,
                acc[dt][0] * inv0, acc[dt][1] * inv0);
        wr_hilo(g_chi, g_clo, ((size_t)b * Tv + t1) * Cv + col,
                acc[dt][2] * inv1, acc[dt][3] * inv1);
    }
}

// ---------------------------------------------------------------------------
extern "C" void kernel_launch(void* const* d_in, const int* in_sizes, int n_in,
                              void* d_out, int out_size)
{
    const float* x  = (const float*)d_in[0];
    const float* Wq = (const float*)d_in[1];
    const float* Wk = (const float*)d_in[2];
    const float* Wv = (const float*)d_in[3];
    const float* Wp = (const float*)d_in[4];
    const float* bp = (const float*)d_in[5];
    float* out = (float*)d_out;

    __nv_bfloat16 *xhi, *xlo, *wphi, *wplo;
    cudaGetSymbolAddress((void**)&xhi,  g_xhi);
    cudaGetSymbolAddress((void**)&xlo,  g_xlo);
    cudaGetSymbolAddress((void**)&wphi, g_wphi);
    cudaGetSymbolAddress((void**)&wplo, g_wplo);

    const int gemm_smem = 2 * 40960;   // 81920 B
    cudaFuncSetAttribute(gemm_kernel<0>, cudaFuncAttributeMaxDynamicSharedMemorySize, gemm_smem);
    cudaFuncSetAttribute(gemm_kernel<1>, cudaFuncAttributeMaxDynamicSharedMemorySize, gemm_smem);
    const int fl_smem = 2 * 4 * 9216;  // 73728 B
    cudaFuncSetAttribute(flash_kernel, cudaFuncAttributeMaxDynamicSharedMemorySize, fl_smem);

    // 1. decompose x, Wproj; transpose+decompose Wq/k/v
    decomp_kernel<<<(Mv * Cv / 4 + 255) / 256, 256>>>(x, xhi, xlo, Mv * Cv / 4);
    decomp_kernel<<<(Cv * Cv / 4 + 255) / 256, 256>>>(Wp, wphi, wplo, Cv * Cv / 4);
    wtrans_kernel<<<dim3(Cv / 64, Hv, 3), 256>>>(Wq, Wk, Wv);

    // 2. QKV projections (HMMA bf16x3) -> bf16 hi/lo q,k,v directly
    gemm_kernel<0><<<dim3(Cv / 128, Mv / 128, 3), 256, gemm_smem>>>(nullptr, nullptr);

    // 3. HMMA causal flash attention -> combo bf16 hi/lo directly
    flash_kernel<<<dim3(Tv / 128, Bv * Hv), 256, fl_smem>>>();

    // 4. output projection (HMMA bf16x3) + bias
    gemm_kernel<1><<<dim3(Cv / 128, Mv / 128, 1), 256, gemm_smem>>>(bp, out);
}

// round 6
// speedup vs baseline: 2.7863x; 1.0744x over previous
#include <cuda_runtime.h>
#include <cuda_bf16.h>
#include <stdint.h>

#define Bv 4
#define Tv 2048
#define Cv 1024
#define Hv 16
#define HSv 64
#define Mv (Bv*Tv)   /* 8192 */
#define NC 32        /* K=1024 / BK=32 */

// ---------------------------------------------------------------------------
// Static device scratch (no runtime allocation)
// ---------------------------------------------------------------------------
__device__ __nv_bfloat16 g_xhi[(size_t)Mv*Cv],  g_xlo[(size_t)Mv*Cv];
__device__ __nv_bfloat16 g_chi[(size_t)Mv*Cv],  g_clo[(size_t)Mv*Cv];
__device__ __nv_bfloat16 g_wthi[(size_t)3*Hv*HSv*Cv], g_wtlo[(size_t)3*Hv*HSv*Cv];
__device__ __nv_bfloat16 g_wphi[(size_t)Cv*Cv], g_wplo[(size_t)Cv*Cv];
__device__ __nv_bfloat16 g_qhi[(size_t)Bv*Hv*Tv*HSv], g_qlo[(size_t)Bv*Hv*Tv*HSv];
__device__ __nv_bfloat16 g_khi[(size_t)Bv*Hv*Tv*HSv], g_klo[(size_t)Bv*Hv*Tv*HSv];
__device__ __nv_bfloat16 g_vhi[(size_t)Bv*Hv*Tv*HSv], g_vlo[(size_t)Bv*Hv*Tv*HSv];

// ---------------------------------------------------------------------------
// Helpers
// ---------------------------------------------------------------------------
__device__ __forceinline__ uint32_t smem_u32(const void* p) {
    uint32_t a;
    asm("{ .reg .u64 t; cvta.to.shared.u64 t, %1; cvt.u32.u64 %0, t; }" : "=r"(a) : "l"(p));
    return a;
}
__device__ __forceinline__ void ldm_x4(uint32_t* r, uint32_t a) {
    asm volatile("ldmatrix.sync.aligned.m8n8.x4.shared.b16 {%0,%1,%2,%3}, [%4];"
        : "=r"(r[0]), "=r"(r[1]), "=r"(r[2]), "=r"(r[3]) : "r"(a));
}
__device__ __forceinline__ void ldm_x4t(uint32_t* r, uint32_t a) {
    asm volatile("ldmatrix.sync.aligned.m8n8.x4.trans.shared.b16 {%0,%1,%2,%3}, [%4];"
        : "=r"(r[0]), "=r"(r[1]), "=r"(r[2]), "=r"(r[3]) : "r"(a));
}
__device__ __forceinline__ void ldm_x2(uint32_t* r, uint32_t a) {
    asm volatile("ldmatrix.sync.aligned.m8n8.x2.shared.b16 {%0,%1}, [%2];"
        : "=r"(r[0]), "=r"(r[1]) : "r"(a));
}
__device__ __forceinline__ void mma16816(float* d, const uint32_t* a, const uint32_t* b) {
    asm volatile(
        "mma.sync.aligned.m16n8k16.row.col.f32.bf16.bf16.f32 "
        "{%0,%1,%2,%3}, {%4,%5,%6,%7}, {%8,%9}, {%0,%1,%2,%3};"
        : "+f"(d[0]), "+f"(d[1]), "+f"(d[2]), "+f"(d[3])
        : "r"(a[0]), "r"(a[1]), "r"(a[2]), "r"(a[3]), "r"(b[0]), "r"(b[1]));
}
#define CP_ASYNC(dst, src) \
    asm volatile("cp.async.cg.shared.global [%0], [%1], 16;" :: "r"(dst), "l"(src) : "memory")
#define CP_COMMIT() asm volatile("cp.async.commit_group;" ::: "memory")
#define CP_WAIT1()  asm volatile("cp.async.wait_group 1;" ::: "memory")
#define CP_WAIT0()  asm volatile("cp.async.wait_group 0;" ::: "memory")

__device__ __forceinline__ uint32_t pack_bf16x2(float a, float b) {
    __nv_bfloat162 t = __floats2bfloat162_rn(a, b);
    return *(uint32_t*)&t;
}
// write fp32 pair (a,b) as bf16 hi/lo pairs at hi[idx],lo[idx]
__device__ __forceinline__ void wr_hilo(__nv_bfloat16* hi, __nv_bfloat16* lo,
                                        size_t idx, float a, float b) {
    __nv_bfloat16 ha = __float2bfloat16(a), hb = __float2bfloat16(b);
    __nv_bfloat162 h2; h2.x = ha; h2.y = hb;
    *(__nv_bfloat162*)&hi[idx] = h2;
    __nv_bfloat162 l2;
    l2.x = __float2bfloat16(a - __bfloat162float(ha));
    l2.y = __float2bfloat16(b - __bfloat162float(hb));
    *(__nv_bfloat162*)&lo[idx] = l2;
}

// ---------------------------------------------------------------------------
// Decompose fp32 -> bf16 hi + bf16 lo
// ---------------------------------------------------------------------------
__global__ void decomp_kernel(const float* __restrict__ src,
                              __nv_bfloat16* __restrict__ hi,
                              __nv_bfloat16* __restrict__ lo, int n4)
{
    int i = blockIdx.x * blockDim.x + threadIdx.x;
    if (i >= n4) return;
    float4 v = ((const float4*)src)[i];
    __nv_bfloat16 h0 = __float2bfloat16(v.x);
    __nv_bfloat16 h1 = __float2bfloat16(v.y);
    __nv_bfloat16 h2 = __float2bfloat16(v.z);
    __nv_bfloat16 h3 = __float2bfloat16(v.w);
    __nv_bfloat162* hp = (__nv_bfloat162*)hi;
    __nv_bfloat162* lp = (__nv_bfloat162*)lo;
    hp[2*i]   = __nv_bfloat162(h0, h1);
    hp[2*i+1] = __nv_bfloat162(h2, h3);
    lp[2*i]   = __nv_bfloat162(__float2bfloat16(v.x - __bfloat162float(h0)),
                               __float2bfloat16(v.y - __bfloat162float(h1)));
    lp[2*i+1] = __nv_bfloat162(__float2bfloat16(v.z - __bfloat162float(h2)),
                               __float2bfloat16(v.w - __bfloat162float(h3)));
}

// ---------------------------------------------------------------------------
// Transpose + decompose Wq/Wk/Wv: W[h][c][d] -> Wt[mat][h][d][c]  (bf16 hi/lo)
// Wq is pre-scaled by 0.125 (folds attention scale into the Q projection).
// ---------------------------------------------------------------------------
__global__ __launch_bounds__(256) void wtrans_kernel(
    const float* __restrict__ Wq, const float* __restrict__ Wk, const float* __restrict__ Wv)
{
    __shared__ float ts[64][65];
    const int c0 = blockIdx.x * 64;
    const int h  = blockIdx.y;
    const int mat = blockIdx.z;
    const float* W = (mat == 0) ? Wq : (mat == 1 ? Wk : Wv);
    const float scl = (mat == 0) ? 0.125f : 1.0f;
    const int tid = threadIdx.x;

    #pragma unroll
    for (int i = 0; i < 16; i++) {
        int idx = tid + i * 256;
        int r = idx >> 6, d = idx & 63;
        ts[r][d] = W[(size_t)h * (Cv * HSv) + (size_t)(c0 + r) * HSv + d] * scl;
    }
    __syncthreads();
    #pragma unroll
    for (int i = 0; i < 16; i++) {
        int idx = tid + i * 256;
        int dd = idx >> 6, cc = idx & 63;
        float v = ts[cc][dd];
        __nv_bfloat16 hv = __float2bfloat16(v);
        size_t o = ((size_t)(mat * Hv + h) * HSv + dd) * Cv + c0 + cc;
        g_wthi[o] = hv;
        g_wtlo[o] = __float2bfloat16(v - __bfloat162float(hv));
    }
}

// ---------------------------------------------------------------------------
// bf16x3 GEMM on mma.sync (HMMA).
// MODE 0: QKV  -> writes q/k/v as bf16 hi/lo in (b,h,t,d)
// MODE 1: proj -> fp32 out + bias
// CTA 128x128, BK=32, 8 warps (2x4), warp tile 64x32.
// __launch_bounds__(256,2): cap regs at 128 so 2 CTAs co-reside per SM.
// ---------------------------------------------------------------------------
template<int MODE>
__global__ __launch_bounds__(256, 2) void gemm_kernel(const float* __restrict__ bias,
                                                      float* __restrict__ outp)
{
    extern __shared__ char smem[];
    const uint32_t sb = smem_u32(smem);
    const int tid = threadIdx.x, lane = tid & 31, wid = tid >> 5;
    const int wm = wid & 1, wn = wid >> 1;
    const int nb = blockIdx.x, m0 = blockIdx.y * 128, mat = blockIdx.z;

    const __nv_bfloat16 *ahi, *alo, *bhi, *blo;
    if (MODE == 0) {
        ahi = g_xhi; alo = g_xlo;
        bhi = g_wthi + (size_t)mat * (Hv * HSv * Cv);
        blo = g_wtlo + (size_t)mat * (Hv * HSv * Cv);
    } else {
        ahi = g_chi; alo = g_clo;
        bhi = g_wphi; blo = g_wplo;
    }

    auto issue = [&](int c, int stg) {
        const int kc0 = c * 32;
        const uint32_t sbase = sb + (uint32_t)stg * 40960u;
        #pragma unroll
        for (int i = 0; i < 8; i++) {
            int s = tid + i * 256;
            int ms = s >> 9, r = (s >> 2) & 127, c4 = s & 3;
            const __nv_bfloat16* src = (ms == 0) ? ahi : (ms == 1) ? alo : (ms == 2) ? bhi : blo;
            int row = ((ms < 2) ? m0 : nb * 128) + r;
            const void* g = src + (size_t)row * Cv + kc0 + c4 * 8;
            uint32_t d = sbase + (uint32_t)ms * 10240u + (uint32_t)(r * 40 + c4 * 8) * 2u;
            CP_ASYNC(d, g);
        }
        CP_COMMIT();
    };

    issue(0, 0);
    issue(1, 1);

    float acc[4][4][4] = {};

    for (int c = 0; c < NC; c++) {
        if (c + 1 < NC) CP_WAIT1(); else CP_WAIT0();
        __syncthreads();
        const uint32_t stg = sb + (uint32_t)(c & 1) * 40960u;

        #pragma unroll
        for (int ks = 0; ks < 2; ks++) {
            uint32_t a_hi[4][4], a_lo[4][4], b_hi[4][2], b_lo[4][2];
            const int arow = (lane & 7) + ((lane >> 3) & 1) * 8;
            const int acol = ks * 16 + (lane >> 4) * 8;
            #pragma unroll
            for (int mt = 0; mt < 4; mt++) {
                uint32_t off = (uint32_t)(((wm * 64 + mt * 16 + arow) * 40 + acol) * 2);
                ldm_x4(a_hi[mt], stg + off);
                ldm_x4(a_lo[mt], stg + 10240u + off);
            }
            const int brow = lane & 7;
            const int bcol = ks * 16 + ((lane >> 3) & 1) * 8;
            #pragma unroll
            for (int nt = 0; nt < 4; nt++) {
                uint32_t off = (uint32_t)(((wn * 32 + nt * 8 + brow) * 40 + bcol) * 2);
                ldm_x2(b_hi[nt], stg + 20480u + off);
                ldm_x2(b_lo[nt], stg + 30720u + off);
            }
            #pragma unroll
            for (int mt = 0; mt < 4; mt++)
                #pragma unroll
                for (int nt = 0; nt < 4; nt++) {
                    mma16816(acc[mt][nt], a_hi[mt], b_hi[nt]);
                    mma16816(acc[mt][nt], a_hi[mt], b_lo[nt]);
                    mma16816(acc[mt][nt], a_lo[mt], b_hi[nt]);
                }
        }
        __syncthreads();
        if (c + 2 < NC) issue(c + 2, c & 1);
    }

    const int g = lane >> 2, tig = lane & 3;
    #pragma unroll
    for (int mt = 0; mt < 4; mt++) {
        const int r0 = m0 + wm * 64 + mt * 16 + g;
        const int r1 = r0 + 8;
        #pragma unroll
        for (int nt = 0; nt < 4; nt++) {
            const int n = nb * 128 + wn * 32 + nt * 8 + tig * 2;
            if (MODE == 0) {
                const int h = n >> 6, dd = n & 63;
                __nv_bfloat16 *ghi, *glo;
                if (mat == 0)      { ghi = g_qhi; glo = g_qlo; }
                else if (mat == 1) { ghi = g_khi; glo = g_klo; }
                else               { ghi = g_vhi; glo = g_vlo; }
                int b0 = r0 >> 11, t0 = r0 & (Tv - 1);
                int b1 = r1 >> 11, t1 = r1 & (Tv - 1);
                wr_hilo(ghi, glo, (((size_t)(b0 * Hv + h)) * Tv + t0) * HSv + dd,
                        acc[mt][nt][0], acc[mt][nt][1]);
                wr_hilo(ghi, glo, (((size_t)(b1 * Hv + h)) * Tv + t1) * HSv + dd,
                        acc[mt][nt][2], acc[mt][nt][3]);
            } else {
                float2 bv = *(const float2*)&bias[n];
                *(float2*)&outp[(size_t)r0 * Cv + n] =
                    make_float2(acc[mt][nt][0] + bv.x, acc[mt][nt][1] + bv.y);
                *(float2*)&outp[(size_t)r1 * Cv + n] =
                    make_float2(acc[mt][nt][2] + bv.x, acc[mt][nt][3] + bv.y);
            }
        }
    }
}

// ---------------------------------------------------------------------------
// HMMA causal flash attention. CTA = 128 queries, 8 warps x 16 rows.
// KV tiles of 64 keys, double-buffered cp.async.
// S = qh*kh + qh*kl + ql*kh ; P split hi/lo ; O += ph*vh + ph*vl + pl*vh.
// smem: [2 stages][4 tiles: Khi,Klo,Vhi,Vlo][64 rows x 144B] = 73728 B
// ---------------------------------------------------------------------------
__global__ __launch_bounds__(256) void flash_kernel()
{
    extern __shared__ char smem[];
    const uint32_t sb = smem_u32(smem);
    const int tid = threadIdx.x, lane = tid & 31, w = tid >> 5;
    const int bx = blockIdx.x, bh = blockIdx.y;
    const int q0 = bx * 128;
    const int qb = q0 + w * 16;
    const int g = lane >> 2, tig = lane & 3;

    // ---- stage Q (hi -> tiles 0/1, lo -> tiles 2/3 of stage 0) ----
    {
        #pragma unroll
        for (int i = 0; i < 8; i++) {
            int s = tid + i * 256;
            int half = s >> 10, r = (s >> 3) & 127, c = s & 7;
            const __nv_bfloat16* src = half ? g_qlo : g_qhi;
            const void* gp = src + ((size_t)bh * Tv + q0 + r) * 64 + c * 8;
            uint32_t d = sb + (uint32_t)(half * 2 + (r >= 64)) * 9216u
                       + (uint32_t)((r & 63) * 144 + c * 16);
            CP_ASYNC(d, gp);
        }
        CP_COMMIT(); CP_WAIT0();
        __syncthreads();
    }
    uint32_t qh[4][4], ql[4][4];
    {
        const int row = w * 16 + (lane & 15);
        const uint32_t hb = sb + ((row >= 64) ? 9216u : 0u);
        const uint32_t lb = sb + 18432u + ((row >= 64) ? 9216u : 0u);
        const int rl = row & 63;
        #pragma unroll
        for (int ks = 0; ks < 4; ks++) {
            uint32_t off = (uint32_t)(rl * 144 + (ks * 16 + (lane >> 4) * 8) * 2);
            ldm_x4(qh[ks], hb + off);
            ldm_x4(ql[ks], lb + off);
        }
    }
    __syncthreads();

    float acc[8][4] = {};
    float m0 = -1e30f, m1 = -1e30f, l0 = 0.0f, l1 = 0.0f;
    const int ntl = 2 * bx + 2;

    auto issueKV = [&](int jt, int stg) {
        const int kv0 = jt * 64;
        #pragma unroll
        for (int i = 0; i < 8; i++) {
            int s = tid + i * 256;
            int tile = s >> 9, r = (s >> 3) & 63, c = s & 7;
            const __nv_bfloat16* src = (tile == 0) ? g_khi : (tile == 1) ? g_klo
                                     : (tile == 2) ? g_vhi : g_vlo;
            const void* gp = src + ((size_t)bh * Tv + kv0 + r) * 64 + c * 8;
            uint32_t d = sb + (uint32_t)stg * 36864u + (uint32_t)tile * 9216u
                       + (uint32_t)(r * 144 + c * 16);
            CP_ASYNC(d, gp);
        }
        CP_COMMIT();
    };
    issueKV(0, 0);
    issueKV(1, 1);

    for (int jt = 0; jt < ntl; jt++) {
        if (jt + 1 < ntl) CP_WAIT1(); else CP_WAIT0();
        __syncthreads();
        const int kv0 = jt * 64;
        const uint32_t stg = sb + (uint32_t)(jt & 1) * 36864u;

        if (kv0 <= qb + 15) {   // warp has at least one unmasked element
            // ---- S = Q K^T (3-term) ----
            float s[8][4] = {};
            #pragma unroll
            for (int ks = 0; ks < 4; ks++) {
                #pragma unroll
                for (int p = 0; p < 4; p++) {
                    uint32_t th[4], tl[4];
                    uint32_t koff = (uint32_t)(
                        (p * 16 + (lane & 7) + ((lane >> 4) & 1) * 8) * 144
                        + (ks * 16 + ((lane >> 3) & 1) * 8) * 2);
                    ldm_x4(th, stg + koff);
                    ldm_x4(tl, stg + 9216u + koff);
                    mma16816(s[2*p],   qh[ks], th);     mma16816(s[2*p],   qh[ks], tl);
                    mma16816(s[2*p],   ql[ks], th);
                    mma16816(s[2*p+1], qh[ks], th + 2); mma16816(s[2*p+1], qh[ks], tl + 2);
                    mma16816(s[2*p+1], ql[ks], th + 2);
                }
            }
            // ---- causal mask ----
            const int row0 = qb + g, row1 = row0 + 8;
            if (kv0 + 63 > row0) {
                #pragma unroll
                for (int nt = 0; nt < 8; nt++) {
                    int c0 = kv0 + nt * 8 + tig * 2;
                    if (c0     > row0) s[nt][0] = -1e30f;
                    if (c0 + 1 > row0) s[nt][1] = -1e30f;
                    if (c0     > row1) s[nt][2] = -1e30f;
                    if (c0 + 1 > row1) s[nt][3] = -1e30f;
                }
            }
            // ---- online softmax ----
            float mx0 = -1e30f, mx1 = -1e30f;
            #pragma unroll
            for (int nt = 0; nt < 8; nt++) {
                mx0 = fmaxf(mx0, fmaxf(s[nt][0], s[nt][1]));
                mx1 = fmaxf(mx1, fmaxf(s[nt][2], s[nt][3]));
            }
            mx0 = fmaxf(mx0, __shfl_xor_sync(0xffffffffu, mx0, 1));
            mx0 = fmaxf(mx0, __shfl_xor_sync(0xffffffffu, mx0, 2));
            mx1 = fmaxf(mx1, __shfl_xor_sync(0xffffffffu, mx1, 1));
            mx1 = fmaxf(mx1, __shfl_xor_sync(0xffffffffu, mx1, 2));
            const float mn0 = fmaxf(m0, mx0), mn1 = fmaxf(m1, mx1);
            const float f0 = __expf(m0 - mn0), f1 = __expf(m1 - mn1);
            m0 = mn0; m1 = mn1;

            uint32_t phi[8][2], plo[8][2];
            float rs0 = 0.0f, rs1 = 0.0f;
            #pragma unroll
            for (int nt = 0; nt < 8; nt++) {
                float p0 = __expf(s[nt][0] - mn0);
                float p1 = __expf(s[nt][1] - mn0);
                float p2 = __expf(s[nt][2] - mn1);
                float p3 = __expf(s[nt][3] - mn1);
                rs0 += p0 + p1; rs1 += p2 + p3;
                __nv_bfloat16 h0 = __float2bfloat16(p0), h1 = __float2bfloat16(p1);
                __nv_bfloat16 h2 = __float2bfloat16(p2), h3 = __float2bfloat16(p3);
                __nv_bfloat162 t01; t01.x = h0; t01.y = h1;
                __nv_bfloat162 t23; t23.x = h2; t23.y = h3;
                phi[nt][0] = *(uint32_t*)&t01;
                phi[nt][1] = *(uint32_t*)&t23;
                plo[nt][0] = pack_bf16x2(p0 - __bfloat162float(h0), p1 - __bfloat162float(h1));
                plo[nt][1] = pack_bf16x2(p2 - __bfloat162float(h2), p3 - __bfloat162float(h3));
            }
            rs0 += __shfl_xor_sync(0xffffffffu, rs0, 1);
            rs0 += __shfl_xor_sync(0xffffffffu, rs0, 2);
            rs1 += __shfl_xor_sync(0xffffffffu, rs1, 1);
            rs1 += __shfl_xor_sync(0xffffffffu, rs1, 2);
            l0 = l0 * f0 + rs0;
            l1 = l1 * f1 + rs1;
            #pragma unroll
            for (int dt = 0; dt < 8; dt++) {
                acc[dt][0] *= f0; acc[dt][1] *= f0;
                acc[dt][2] *= f1; acc[dt][3] *= f1;
            }
            // ---- O += P V (3-term), V via ldmatrix.trans ----
            #pragma unroll
            for (int ks = 0; ks < 4; ks++) {
                uint32_t ah[4] = { phi[2*ks][0], phi[2*ks][1], phi[2*ks+1][0], phi[2*ks+1][1] };
                uint32_t al[4] = { plo[2*ks][0], plo[2*ks][1], plo[2*ks+1][0], plo[2*ks+1][1] };
                #pragma unroll
                for (int dp = 0; dp < 4; dp++) {
                    uint32_t vh[4], vl[4];
                    uint32_t voff = (uint32_t)(
                        (ks * 16 + (lane & 7) + ((lane >> 3) & 1) * 8) * 144
                        + (dp * 16 + (lane >> 4) * 8) * 2);
                    ldm_x4t(vh, stg + 18432u + voff);
                    ldm_x4t(vl, stg + 27648u + voff);
                    mma16816(acc[2*dp],   ah, vh);     mma16816(acc[2*dp],   ah, vl);
                    mma16816(acc[2*dp],   al, vh);
                    mma16816(acc[2*dp+1], ah, vh + 2); mma16816(acc[2*dp+1], ah, vl + 2);
                    mma16816(acc[2*dp+1], al, vh + 2);
                }
            }
        }
        __syncthreads();
        if (jt + 2 < ntl) issueKV(jt + 2, jt & 1);
    }

    // ---- epilogue: combo hi/lo ----
    const float inv0 = 1.0f / l0, inv1 = 1.0f / l1;
    const int b = bh >> 4, h = bh & 15;
    const int t0 = qb + g, t1 = t0 + 8;
    #pragma unroll
    for (int dt = 0; dt < 8; dt++) {
        const int col = h * 64 + dt * 8 + tig * 2;
        wr_hilo(g_chi, g_clo, ((size_t)b * Tv + t0) * Cv + col,
                acc[dt][0] * inv0, acc[dt][1] * inv0);
        wr_hilo(g_chi, g_clo, ((size_t)b * Tv + t1) * Cv + col,
                acc[dt][2] * inv1, acc[dt][3] * inv1);
    }
}

// ---------------------------------------------------------------------------
extern "C" void kernel_launch(void* const* d_in, const int* in_sizes, int n_in,
                              void* d_out, int out_size)
{
    const float* x  = (const float*)d_in[0];
    const float* Wq = (const float*)d_in[1];
    const float* Wk = (const float*)d_in[2];
    const float* Wv = (const float*)d_in[3];
    const float* Wp = (const float*)d_in[4];
    const float* bp = (const float*)d_in[5];
    float* out = (float*)d_out;

    __nv_bfloat16 *xhi, *xlo, *wphi, *wplo;
    cudaGetSymbolAddress((void**)&xhi,  g_xhi);
    cudaGetSymbolAddress((void**)&xlo,  g_xlo);
    cudaGetSymbolAddress((void**)&wphi, g_wphi);
    cudaGetSymbolAddress((void**)&wplo, g_wplo);

    const int gemm_smem = 2 * 40960;   // 81920 B
    cudaFuncSetAttribute(gemm_kernel<0>, cudaFuncAttributeMaxDynamicSharedMemorySize, gemm_smem);
    cudaFuncSetAttribute(gemm_kernel<1>, cudaFuncAttributeMaxDynamicSharedMemorySize, gemm_smem);
    const int fl_smem = 2 * 4 * 9216;  // 73728 B
    cudaFuncSetAttribute(flash_kernel, cudaFuncAttributeMaxDynamicSharedMemorySize, fl_smem);

    // 1. decompose x, Wproj; transpose+decompose Wq/k/v (Wq pre-scaled 0.125)
    decomp_kernel<<<(Mv * Cv / 4 + 255) / 256, 256>>>(x, xhi, xlo, Mv * Cv / 4);
    decomp_kernel<<<(Cv * Cv / 4 + 255) / 256, 256>>>(Wp, wphi, wplo, Cv * Cv / 4);
    wtrans_kernel<<<dim3(Cv / 64, Hv, 3), 256>>>(Wq, Wk, Wv);

    // 2. QKV projections (HMMA bf16x3) -> bf16 hi/lo q,k,v directly
    gemm_kernel<0><<<dim3(Cv / 128, Mv / 128, 3), 256, gemm_smem>>>(nullptr, nullptr);

    // 3. HMMA causal flash attention -> combo bf16 hi/lo directly
    flash_kernel<<<dim3(Tv / 128, Bv * Hv), 256, fl_smem>>>();

    // 4. output projection (HMMA bf16x3) + bias
    gemm_kernel<1><<<dim3(Cv / 128, Mv / 128, 1), 256, gemm_smem>>>(bp, out);
}

// round 7
// speedup vs baseline: 3.6519x; 1.3107x over previous
#include <cuda_runtime.h>
#include <cuda_fp16.h>
#include <stdint.h>

#define Bv 4
#define Tv 2048
#define Cv 1024
#define Hv 16
#define HSv 64
#define Mv (Bv*Tv)   /* 8192 */
#define NC 32        /* K=1024 / BK=32 */

// ---------------------------------------------------------------------------
// Static device scratch (no runtime allocation) — all fp16 now
// ---------------------------------------------------------------------------
__device__ __half g_xhi[(size_t)Mv*Cv],  g_xlo[(size_t)Mv*Cv];
__device__ __half g_chi[(size_t)Mv*Cv],  g_clo[(size_t)Mv*Cv];
__device__ __half g_wt[(size_t)3*Hv*HSv*Cv];           // truncated W^T (mat0 pre-scaled)
__device__ __half g_wp[(size_t)Cv*Cv];                 // truncated Wproj
__device__ __half g_qhi[(size_t)Bv*Hv*Tv*HSv], g_qlo[(size_t)Bv*Hv*Tv*HSv];
__device__ __half g_khi[(size_t)Bv*Hv*Tv*HSv], g_klo[(size_t)Bv*Hv*Tv*HSv];
__device__ __half g_vh [(size_t)Bv*Hv*Tv*HSv];         // V hi only (PV is 2-term)

// ---------------------------------------------------------------------------
// Helpers
// ---------------------------------------------------------------------------
__device__ __forceinline__ uint32_t smem_u32(const void* p) {
    uint32_t a;
    asm("{ .reg .u64 t; cvta.to.shared.u64 t, %1; cvt.u32.u64 %0, t; }" : "=r"(a) : "l"(p));
    return a;
}
__device__ __forceinline__ void ldm_x4(uint32_t* r, uint32_t a) {
    asm volatile("ldmatrix.sync.aligned.m8n8.x4.shared.b16 {%0,%1,%2,%3}, [%4];"
        : "=r"(r[0]), "=r"(r[1]), "=r"(r[2]), "=r"(r[3]) : "r"(a));
}
__device__ __forceinline__ void ldm_x4t(uint32_t* r, uint32_t a) {
    asm volatile("ldmatrix.sync.aligned.m8n8.x4.trans.shared.b16 {%0,%1,%2,%3}, [%4];"
        : "=r"(r[0]), "=r"(r[1]), "=r"(r[2]), "=r"(r[3]) : "r"(a));
}
__device__ __forceinline__ void mma16816(float* d, const uint32_t* a, const uint32_t* b) {
    asm volatile(
        "mma.sync.aligned.m16n8k16.row.col.f32.f16.f16.f32 "
        "{%0,%1,%2,%3}, {%4,%5,%6,%7}, {%8,%9}, {%0,%1,%2,%3};"
        : "+f"(d[0]), "+f"(d[1]), "+f"(d[2]), "+f"(d[3])
        : "r"(a[0]), "r"(a[1]), "r"(a[2]), "r"(a[3]), "r"(b[0]), "r"(b[1]));
}
#define CP_ASYNC(dst, src) \
    asm volatile("cp.async.cg.shared.global [%0], [%1], 16;" :: "r"(dst), "l"(src) : "memory")
#define CP_COMMIT() asm volatile("cp.async.commit_group;" ::: "memory")
#define CP_WAIT1()  asm volatile("cp.async.wait_group 1;" ::: "memory")
#define CP_WAIT0()  asm volatile("cp.async.wait_group 0;" ::: "memory")

__device__ __forceinline__ uint32_t pack_h2(float a, float b) {
    __half2 t = __floats2half2_rn(a, b);
    return *(uint32_t*)&t;
}
// write fp32 pair (a,b) as fp16 hi/lo pairs
__device__ __forceinline__ void wr_hilo(__half* hi, __half* lo, size_t idx, float a, float b) {
    __half ha = __float2half_rn(a), hb = __float2half_rn(b);
    *(__half2*)&hi[idx] = __halves2half2(ha, hb);
    *(__half2*)&lo[idx] = __halves2half2(__float2half_rn(a - __half2float(ha)),
                                         __float2half_rn(b - __half2float(hb)));
}

// ---------------------------------------------------------------------------
// Decompose fp32 -> fp16 hi + fp16 lo
// ---------------------------------------------------------------------------
__global__ void decomp_kernel(const float* __restrict__ src,
                              __half* __restrict__ hi, __half* __restrict__ lo, int n4)
{
    int i = blockIdx.x * blockDim.x + threadIdx.x;
    if (i >= n4) return;
    float4 v = ((const float4*)src)[i];
    __half h0 = __float2half_rn(v.x), h1 = __float2half_rn(v.y);
    __half h2 = __float2half_rn(v.z), h3 = __float2half_rn(v.w);
    __half2* hp = (__half2*)hi;
    __half2* lp = (__half2*)lo;
    hp[2*i]   = __halves2half2(h0, h1);
    hp[2*i+1] = __halves2half2(h2, h3);
    lp[2*i]   = __halves2half2(__float2half_rn(v.x - __half2float(h0)),
                               __float2half_rn(v.y - __half2float(h1)));
    lp[2*i+1] = __halves2half2(__float2half_rn(v.z - __half2float(h2)),
                               __float2half_rn(v.w - __half2float(h3)));
}

// Truncate fp32 -> fp16
__global__ void trunc_kernel(const float* __restrict__ src, __half* __restrict__ dst, int n4)
{
    int i = blockIdx.x * blockDim.x + threadIdx.x;
    if (i >= n4) return;
    float4 v = ((const float4*)src)[i];
    __half2* dp = (__half2*)dst;
    dp[2*i]   = __floats2half2_rn(v.x, v.y);
    dp[2*i+1] = __floats2half2_rn(v.z, v.w);
}

// ---------------------------------------------------------------------------
// Transpose + truncate Wq/Wk/Wv: W[h][c][d] -> Wt[mat][h][d][c]  (fp16)
// Wq pre-scaled by 0.125.
// ---------------------------------------------------------------------------
__global__ __launch_bounds__(256) void wtrans_kernel(
    const float* __restrict__ Wq, const float* __restrict__ Wk, const float* __restrict__ Wv)
{
    __shared__ float ts[64][65];
    const int c0 = blockIdx.x * 64;
    const int h  = blockIdx.y;
    const int mat = blockIdx.z;
    const float* W = (mat == 0) ? Wq : (mat == 1 ? Wk : Wv);
    const float scl = (mat == 0) ? 0.125f : 1.0f;
    const int tid = threadIdx.x;

    #pragma unroll
    for (int i = 0; i < 16; i++) {
        int idx = tid + i * 256;
        int r = idx >> 6, d = idx & 63;
        ts[r][d] = W[(size_t)h * (Cv * HSv) + (size_t)(c0 + r) * HSv + d] * scl;
    }
    __syncthreads();
    #pragma unroll
    for (int i = 0; i < 16; i++) {
        int idx = tid + i * 256;
        int dd = idx >> 6, cc = idx & 63;
        g_wt[((size_t)(mat * Hv + h) * HSv + dd) * Cv + c0 + cc] = __float2half_rn(ts[cc][dd]);
    }
}

// ---------------------------------------------------------------------------
// fp16 2-term GEMM on mma.sync.  C = (A_hi + A_lo) * B_hi
// MODE 0: QKV  -> q,k as fp16 hi/lo; v as fp16 hi only (b,h,t,d layout)
// MODE 1: proj -> fp32 out + bias
// CTA 128x128, BK=32, 8 warps (2x4), warp tile 64x32, 2-stage cp.async.
// smem/stage (30720 B): Ahi | Alo | B, each 128 rows x 40 fp16 (80B).
// ---------------------------------------------------------------------------
template<int MODE>
__global__ __launch_bounds__(256, 2) void gemm_kernel(const float* __restrict__ bias,
                                                      float* __restrict__ outp)
{
    extern __shared__ char smem[];
    const uint32_t sb = smem_u32(smem);
    const int tid = threadIdx.x, lane = tid & 31, wid = tid >> 5;
    const int wm = wid & 1, wn = wid >> 1;
    const int nb = blockIdx.x, m0 = blockIdx.y * 128, mat = blockIdx.z;

    const __half *ahi, *alo, *bm;
    if (MODE == 0) {
        ahi = g_xhi; alo = g_xlo;
        bm  = g_wt + (size_t)mat * (Hv * HSv * Cv);
    } else {
        ahi = g_chi; alo = g_clo;
        bm  = g_wp;
    }

    // loader: 1536 16B slots per stage, 6 per thread
    auto issue = [&](int c, int stg) {
        const int kc0 = c * 32;
        const uint32_t sbase = sb + (uint32_t)stg * 30720u;
        #pragma unroll
        for (int i = 0; i < 6; i++) {
            int s = tid + i * 256;
            int ms = s >> 9, r = (s >> 2) & 127, c4 = s & 3;
            const __half* src = (ms == 0) ? ahi : (ms == 1) ? alo : bm;
            int row = ((ms < 2) ? m0 : nb * 128) + r;
            const void* g = src + (size_t)row * Cv + kc0 + c4 * 8;
            uint32_t d = sbase + (uint32_t)ms * 10240u + (uint32_t)(r * 40 + c4 * 8) * 2u;
            CP_ASYNC(d, g);
        }
        CP_COMMIT();
    };

    issue(0, 0);
    issue(1, 1);

    float acc[4][4][4] = {};

    for (int c = 0; c < NC; c++) {
        if (c + 1 < NC) CP_WAIT1(); else CP_WAIT0();
        __syncthreads();
        const uint32_t stg = sb + (uint32_t)(c & 1) * 30720u;

        #pragma unroll
        for (int ks = 0; ks < 2; ks++) {
            uint32_t a_hi[4][4], a_lo[4][4], b_[2][4];
            const int arow = (lane & 7) + ((lane >> 3) & 1) * 8;
            const int acol = ks * 16 + (lane >> 4) * 8;
            #pragma unroll
            for (int mt = 0; mt < 4; mt++) {
                uint32_t off = (uint32_t)(((wm * 64 + mt * 16 + arow) * 40 + acol) * 2);
                ldm_x4(a_hi[mt], stg + off);
                ldm_x4(a_lo[mt], stg + 10240u + off);
            }
            // B: x4 pair loads — rows cover two n-subtiles of 8
            #pragma unroll
            for (int ntp = 0; ntp < 2; ntp++) {
                uint32_t off = (uint32_t)(
                    ((wn * 32 + ntp * 16 + (lane & 7) + ((lane >> 4) & 1) * 8) * 40
                     + ks * 16 + ((lane >> 3) & 1) * 8) * 2);
                ldm_x4(b_[ntp], stg + 20480u + off);
            }
            #pragma unroll
            for (int mt = 0; mt < 4; mt++)
                #pragma unroll
                for (int ntp = 0; ntp < 2; ntp++) {
                    mma16816(acc[mt][2*ntp],   a_hi[mt], b_[ntp]);
                    mma16816(acc[mt][2*ntp],   a_lo[mt], b_[ntp]);
                    mma16816(acc[mt][2*ntp+1], a_hi[mt], b_[ntp] + 2);
                    mma16816(acc[mt][2*ntp+1], a_lo[mt], b_[ntp] + 2);
                }
        }
        __syncthreads();
        if (c + 2 < NC) issue(c + 2, c & 1);
    }

    const int g = lane >> 2, tig = lane & 3;
    #pragma unroll
    for (int mt = 0; mt < 4; mt++) {
        const int r0 = m0 + wm * 64 + mt * 16 + g;
        const int r1 = r0 + 8;
        #pragma unroll
        for (int nt = 0; nt < 4; nt++) {
            const int n = nb * 128 + wn * 32 + nt * 8 + tig * 2;
            if (MODE == 0) {
                const int h = n >> 6, dd = n & 63;
                int b0 = r0 >> 11, t0 = r0 & (Tv - 1);
                int b1 = r1 >> 11, t1 = r1 & (Tv - 1);
                size_t i0 = (((size_t)(b0 * Hv + h)) * Tv + t0) * HSv + dd;
                size_t i1 = (((size_t)(b1 * Hv + h)) * Tv + t1) * HSv + dd;
                if (mat == 0) {
                    wr_hilo(g_qhi, g_qlo, i0, acc[mt][nt][0], acc[mt][nt][1]);
                    wr_hilo(g_qhi, g_qlo, i1, acc[mt][nt][2], acc[mt][nt][3]);
                } else if (mat == 1) {
                    wr_hilo(g_khi, g_klo, i0, acc[mt][nt][0], acc[mt][nt][1]);
                    wr_hilo(g_khi, g_klo, i1, acc[mt][nt][2], acc[mt][nt][3]);
                } else {
                    *(__half2*)&g_vh[i0] = __floats2half2_rn(acc[mt][nt][0], acc[mt][nt][1]);
                    *(__half2*)&g_vh[i1] = __floats2half2_rn(acc[mt][nt][2], acc[mt][nt][3]);
                }
            } else {
                float2 bv = *(const float2*)&bias[n];
                *(float2*)&outp[(size_t)r0 * Cv + n] =
                    make_float2(acc[mt][nt][0] + bv.x, acc[mt][nt][1] + bv.y);
                *(float2*)&outp[(size_t)r1 * Cv + n] =
                    make_float2(acc[mt][nt][2] + bv.x, acc[mt][nt][3] + bv.y);
            }
        }
    }
}

// ---------------------------------------------------------------------------
// fp16 HMMA causal flash attention. CTA = 128 queries, 8 warps x 16 rows.
// S = qh*kh + qh*kl + ql*kh  (3-term, error ~2^-22)
// PV = ph*vh + pl*vh = p*v_hi (2-term, error ~2^-12 on V only)
// smem: [2 stages][3 tiles: Khi,Klo,Vh][64 rows x 144B] = 55296 B
// Q staged once through stage region (4 tiles), read before first KV load.
// ---------------------------------------------------------------------------
__global__ __launch_bounds__(256) void flash_kernel()
{
    extern __shared__ char smem[];
    const uint32_t sb = smem_u32(smem);
    const int tid = threadIdx.x, lane = tid & 31, w = tid >> 5;
    const int bx = blockIdx.x, bh = blockIdx.y;
    const int q0 = bx * 128;
    const int qb = q0 + w * 16;
    const int g = lane >> 2, tig = lane & 3;

    // ---- stage Q: hi -> tiles 0/1, lo -> tiles 2/3 ----
    {
        #pragma unroll
        for (int i = 0; i < 8; i++) {
            int s = tid + i * 256;
            int half_ = s >> 10, r = (s >> 3) & 127, c = s & 7;
            const __half* src = half_ ? g_qlo : g_qhi;
            const void* gp = src + ((size_t)bh * Tv + q0 + r) * 64 + c * 8;
            uint32_t d = sb + (uint32_t)(half_ * 2 + (r >= 64)) * 9216u
                       + (uint32_t)((r & 63) * 144 + c * 16);
            CP_ASYNC(d, gp);
        }
        CP_COMMIT(); CP_WAIT0();
        __syncthreads();
    }
    uint32_t qh[4][4], ql[4][4];
    {
        const int row = w * 16 + (lane & 15);
        const uint32_t hb = sb + ((row >= 64) ? 9216u : 0u);
        const uint32_t lb = sb + 18432u + ((row >= 64) ? 9216u : 0u);
        const int rl = row & 63;
        #pragma unroll
        for (int ks = 0; ks < 4; ks++) {
            uint32_t off = (uint32_t)(rl * 144 + (ks * 16 + (lane >> 4) * 8) * 2);
            ldm_x4(qh[ks], hb + off);
            ldm_x4(ql[ks], lb + off);
        }
    }
    __syncthreads();

    float acc[8][4] = {};
    float m0 = -1e30f, m1 = -1e30f, l0 = 0.0f, l1 = 0.0f;
    const int ntl = 2 * bx + 2;

    auto issueKV = [&](int jt, int stg) {
        const int kv0 = jt * 64;
        #pragma unroll
        for (int i = 0; i < 6; i++) {
            int s = tid + i * 256;
            int tile = s >> 9, r = (s >> 3) & 63, c = s & 7;
            const __half* src = (tile == 0) ? g_khi : (tile == 1) ? g_klo : g_vh;
            const void* gp = src + ((size_t)bh * Tv + kv0 + r) * 64 + c * 8;
            uint32_t d = sb + (uint32_t)stg * 27648u + (uint32_t)tile * 9216u
                       + (uint32_t)(r * 144 + c * 16);
            CP_ASYNC(d, gp);
        }
        CP_COMMIT();
    };
    issueKV(0, 0);
    issueKV(1, 1);

    for (int jt = 0; jt < ntl; jt++) {
        if (jt + 1 < ntl) CP_WAIT1(); else CP_WAIT0();
        __syncthreads();
        const int kv0 = jt * 64;
        const uint32_t stg = sb + (uint32_t)(jt & 1) * 27648u;

        if (kv0 <= qb + 15) {
            // ---- S = Q K^T (3-term fp16) ----
            float s[8][4] = {};
            #pragma unroll
            for (int ks = 0; ks < 4; ks++) {
                #pragma unroll
                for (int p = 0; p < 4; p++) {
                    uint32_t th[4], tl[4];
                    uint32_t koff = (uint32_t)(
                        (p * 16 + (lane & 7) + ((lane >> 4) & 1) * 8) * 144
                        + (ks * 16 + ((lane >> 3) & 1) * 8) * 2);
                    ldm_x4(th, stg + koff);
                    ldm_x4(tl, stg + 9216u + koff);
                    mma16816(s[2*p],   qh[ks], th);     mma16816(s[2*p],   qh[ks], tl);
                    mma16816(s[2*p],   ql[ks], th);
                    mma16816(s[2*p+1], qh[ks], th + 2); mma16816(s[2*p+1], qh[ks], tl + 2);
                    mma16816(s[2*p+1], ql[ks], th + 2);
                }
            }
            // ---- causal mask ----
            const int row0 = qb + g, row1 = row0 + 8;
            if (kv0 + 63 > row0) {
                #pragma unroll
                for (int nt = 0; nt < 8; nt++) {
                    int c0 = kv0 + nt * 8 + tig * 2;
                    if (c0     > row0) s[nt][0] = -1e30f;
                    if (c0 + 1 > row0) s[nt][1] = -1e30f;
                    if (c0     > row1) s[nt][2] = -1e30f;
                    if (c0 + 1 > row1) s[nt][3] = -1e30f;
                }
            }
            // ---- online softmax ----
            float mx0 = -1e30f, mx1 = -1e30f;
            #pragma unroll
            for (int nt = 0; nt < 8; nt++) {
                mx0 = fmaxf(mx0, fmaxf(s[nt][0], s[nt][1]));
                mx1 = fmaxf(mx1, fmaxf(s[nt][2], s[nt][3]));
            }
            mx0 = fmaxf(mx0, __shfl_xor_sync(0xffffffffu, mx0, 1));
            mx0 = fmaxf(mx0, __shfl_xor_sync(0xffffffffu, mx0, 2));
            mx1 = fmaxf(mx1, __shfl_xor_sync(0xffffffffu, mx1, 1));
            mx1 = fmaxf(mx1, __shfl_xor_sync(0xffffffffu, mx1, 2));
            const float mn0 = fmaxf(m0, mx0), mn1 = fmaxf(m1, mx1);
            const float f0 = __expf(m0 - mn0), f1 = __expf(m1 - mn1);
            m0 = mn0; m1 = mn1;

            uint32_t phi[8][2], plo[8][2];
            float rs0 = 0.0f, rs1 = 0.0f;
            #pragma unroll
            for (int nt = 0; nt < 8; nt++) {
                float p0 = __expf(s[nt][0] - mn0);
                float p1 = __expf(s[nt][1] - mn0);
                float p2 = __expf(s[nt][2] - mn1);
                float p3 = __expf(s[nt][3] - mn1);
                rs0 += p0 + p1; rs1 += p2 + p3;
                __half h0 = __float2half_rn(p0), h1 = __float2half_rn(p1);
                __half h2 = __float2half_rn(p2), h3 = __float2half_rn(p3);
                __half2 t01 = __halves2half2(h0, h1);
                __half2 t23 = __halves2half2(h2, h3);
                phi[nt][0] = *(uint32_t*)&t01;
                phi[nt][1] = *(uint32_t*)&t23;
                plo[nt][0] = pack_h2(p0 - __half2float(h0), p1 - __half2float(h1));
                plo[nt][1] = pack_h2(p2 - __half2float(h2), p3 - __half2float(h3));
            }
            rs0 += __shfl_xor_sync(0xffffffffu, rs0, 1);
            rs0 += __shfl_xor_sync(0xffffffffu, rs0, 2);
            rs1 += __shfl_xor_sync(0xffffffffu, rs1, 1);
            rs1 += __shfl_xor_sync(0xffffffffu, rs1, 2);
            l0 = l0 * f0 + rs0;
            l1 = l1 * f1 + rs1;
            #pragma unroll
            for (int dt = 0; dt < 8; dt++) {
                acc[dt][0] *= f0; acc[dt][1] *= f0;
                acc[dt][2] *= f1; acc[dt][3] *= f1;
            }
            // ---- O += P V_hi (2-term: p exact as hi+lo) ----
            #pragma unroll
            for (int ks = 0; ks < 4; ks++) {
                uint32_t ah[4] = { phi[2*ks][0], phi[2*ks][1], phi[2*ks+1][0], phi[2*ks+1][1] };
                uint32_t al[4] = { plo[2*ks][0], plo[2*ks][1], plo[2*ks+1][0], plo[2*ks+1][1] };
                #pragma unroll
                for (int dp = 0; dp < 4; dp++) {
                    uint32_t vh[4];
                    uint32_t voff = (uint32_t)(
                        (ks * 16 + (lane & 7) + ((lane >> 3) & 1) * 8) * 144
                        + (dp * 16 + (lane >> 4) * 8) * 2);
                    ldm_x4t(vh, stg + 18432u + voff);
                    mma16816(acc[2*dp],   ah, vh);     mma16816(acc[2*dp],   al, vh);
                    mma16816(acc[2*dp+1], ah, vh + 2); mma16816(acc[2*dp+1], al, vh + 2);
                }
            }
        }
        __syncthreads();
        if (jt + 2 < ntl) issueKV(jt + 2, jt & 1);
    }

    // ---- epilogue: combo hi/lo fp16 ----
    const float inv0 = 1.0f / l0, inv1 = 1.0f / l1;
    const int b = bh >> 4, h = bh & 15;
    const int t0 = qb + g, t1 = t0 + 8;
    #pragma unroll
    for (int dt = 0; dt < 8; dt++) {
        const int col = h * 64 + dt * 8 + tig * 2;
        wr_hilo(g_chi, g_clo, ((size_t)b * Tv + t0) * Cv + col,
                acc[dt][0] * inv0, acc[dt][1] * inv0);
        wr_hilo(g_chi, g_clo, ((size_t)b * Tv + t1) * Cv + col,
                acc[dt][2] * inv1, acc[dt][3] * inv1);
    }
}

// ---------------------------------------------------------------------------
extern "C" void kernel_launch(void* const* d_in, const int* in_sizes, int n_in,
                              void* d_out, int out_size)
{
    const float* x  = (const float*)d_in[0];
    const float* Wq = (const float*)d_in[1];
    const float* Wk = (const float*)d_in[2];
    const float* Wv = (const float*)d_in[3];
    const float* Wp = (const float*)d_in[4];
    const float* bp = (const float*)d_in[5];
    float* out = (float*)d_out;

    __half *xhi, *xlo, *wp;
    cudaGetSymbolAddress((void**)&xhi, g_xhi);
    cudaGetSymbolAddress((void**)&xlo, g_xlo);
    cudaGetSymbolAddress((void**)&wp,  g_wp);

    const int gemm_smem = 2 * 30720;   // 61440 B
    cudaFuncSetAttribute(gemm_kernel<0>, cudaFuncAttributeMaxDynamicSharedMemorySize, gemm_smem);
    cudaFuncSetAttribute(gemm_kernel<1>, cudaFuncAttributeMaxDynamicSharedMemorySize, gemm_smem);
    const int fl_smem = 2 * 27648;     // 55296 B
    cudaFuncSetAttribute(flash_kernel, cudaFuncAttributeMaxDynamicSharedMemorySize, fl_smem);

    // 1. split x; truncate Wproj; transpose+truncate Wq/k/v (Wq pre-scaled)
    decomp_kernel<<<(Mv * Cv / 4 + 255) / 256, 256>>>(x, xhi, xlo, Mv * Cv / 4);
    trunc_kernel<<<(Cv * Cv / 4 + 255) / 256, 256>>>(Wp, wp, Cv * Cv / 4);
    wtrans_kernel<<<dim3(Cv / 64, Hv, 3), 256>>>(Wq, Wk, Wv);

    // 2. QKV projections (fp16 2-term) -> q,k hi/lo; v hi
    gemm_kernel<0><<<dim3(Cv / 128, Mv / 128, 3), 256, gemm_smem>>>(nullptr, nullptr);

    // 3. flash attention (S 3-term fp16, PV 2-term) -> combo hi/lo
    flash_kernel<<<dim3(Tv / 128, Bv * Hv), 256, fl_smem>>>();

    // 4. output projection (fp16 2-term) + bias
    gemm_kernel<1><<<dim3(Cv / 128, Mv / 128, 1), 256, gemm_smem>>>(bp, out);
}

// round 8
// speedup vs baseline: 3.9353x; 1.0776x over previous
#include <cuda_runtime.h>
#include <cuda_fp16.h>
#include <stdint.h>

#define Bv 4
#define Tv 2048
#define Cv 1024
#define Hv 16
#define HSv 64
#define Mv (Bv*Tv)   /* 8192 */
#define NC 16        /* K=1024 / BK=64 */

// ---------------------------------------------------------------------------
// Static device scratch (no runtime allocation)
// ---------------------------------------------------------------------------
__device__ __half g_xhi[(size_t)Mv*Cv],  g_xlo[(size_t)Mv*Cv];
__device__ __half g_chi[(size_t)Mv*Cv],  g_clo[(size_t)Mv*Cv];
__device__ __half g_wt[(size_t)3*Hv*HSv*Cv];           // truncated W^T (mat0 pre-scaled)
__device__ __half g_wp[(size_t)Cv*Cv];                 // truncated Wproj
__device__ __half g_qhi[(size_t)Bv*Hv*Tv*HSv], g_qlo[(size_t)Bv*Hv*Tv*HSv];
__device__ __half g_khi[(size_t)Bv*Hv*Tv*HSv], g_klo[(size_t)Bv*Hv*Tv*HSv];
__device__ __half g_vh [(size_t)Bv*Hv*Tv*HSv];         // V hi only (PV is 2-term)

// ---------------------------------------------------------------------------
// Helpers
// ---------------------------------------------------------------------------
__device__ __forceinline__ uint32_t smem_u32(const void* p) {
    uint32_t a;
    asm("{ .reg .u64 t; cvta.to.shared.u64 t, %1; cvt.u32.u64 %0, t; }" : "=r"(a) : "l"(p));
    return a;
}
__device__ __forceinline__ void ldm_x4(uint32_t* r, uint32_t a) {
    asm volatile("ldmatrix.sync.aligned.m8n8.x4.shared.b16 {%0,%1,%2,%3}, [%4];"
        : "=r"(r[0]), "=r"(r[1]), "=r"(r[2]), "=r"(r[3]) : "r"(a));
}
__device__ __forceinline__ void ldm_x4t(uint32_t* r, uint32_t a) {
    asm volatile("ldmatrix.sync.aligned.m8n8.x4.trans.shared.b16 {%0,%1,%2,%3}, [%4];"
        : "=r"(r[0]), "=r"(r[1]), "=r"(r[2]), "=r"(r[3]) : "r"(a));
}
__device__ __forceinline__ void mma16816(float* d, const uint32_t* a, const uint32_t* b) {
    asm volatile(
        "mma.sync.aligned.m16n8k16.row.col.f32.f16.f16.f32 "
        "{%0,%1,%2,%3}, {%4,%5,%6,%7}, {%8,%9}, {%0,%1,%2,%3};"
        : "+f"(d[0]), "+f"(d[1]), "+f"(d[2]), "+f"(d[3])
        : "r"(a[0]), "r"(a[1]), "r"(a[2]), "r"(a[3]), "r"(b[0]), "r"(b[1]));
}
#define CP_ASYNC(dst, src) \
    asm volatile("cp.async.cg.shared.global [%0], [%1], 16;" :: "r"(dst), "l"(src) : "memory")
#define CP_COMMIT() asm volatile("cp.async.commit_group;" ::: "memory")
#define CP_WAIT1()  asm volatile("cp.async.wait_group 1;" ::: "memory")
#define CP_WAIT0()  asm volatile("cp.async.wait_group 0;" ::: "memory")

__device__ __forceinline__ uint32_t pack_h2(float a, float b) {
    __half2 t = __floats2half2_rn(a, b);
    return *(uint32_t*)&t;
}
__device__ __forceinline__ void wr_hilo(__half* hi, __half* lo, size_t idx, float a, float b) {
    __half ha = __float2half_rn(a), hb = __float2half_rn(b);
    *(__half2*)&hi[idx] = __halves2half2(ha, hb);
    *(__half2*)&lo[idx] = __halves2half2(__float2half_rn(a - __half2float(ha)),
                                         __float2half_rn(b - __half2float(hb)));
}

// ---------------------------------------------------------------------------
// Decompose fp32 -> fp16 hi + fp16 lo
// ---------------------------------------------------------------------------
__global__ void decomp_kernel(const float* __restrict__ src,
                              __half* __restrict__ hi, __half* __restrict__ lo, int n4)
{
    int i = blockIdx.x * blockDim.x + threadIdx.x;
    if (i >= n4) return;
    float4 v = ((const float4*)src)[i];
    __half h0 = __float2half_rn(v.x), h1 = __float2half_rn(v.y);
    __half h2 = __float2half_rn(v.z), h3 = __float2half_rn(v.w);
    __half2* hp = (__half2*)hi;
    __half2* lp = (__half2*)lo;
    hp[2*i]   = __halves2half2(h0, h1);
    hp[2*i+1] = __halves2half2(h2, h3);
    lp[2*i]   = __halves2half2(__float2half_rn(v.x - __half2float(h0)),
                               __float2half_rn(v.y - __half2float(h1)));
    lp[2*i+1] = __halves2half2(__float2half_rn(v.z - __half2float(h2)),
                               __float2half_rn(v.w - __half2float(h3)));
}

// Truncate fp32 -> fp16
__global__ void trunc_kernel(const float* __restrict__ src, __half* __restrict__ dst, int n4)
{
    int i = blockIdx.x * blockDim.x + threadIdx.x;
    if (i >= n4) return;
    float4 v = ((const float4*)src)[i];
    __half2* dp = (__half2*)dst;
    dp[2*i]   = __floats2half2_rn(v.x, v.y);
    dp[2*i+1] = __floats2half2_rn(v.z, v.w);
}

// ---------------------------------------------------------------------------
// Transpose + truncate Wq/Wk/Wv: W[h][c][d] -> Wt[mat][h][d][c]  (fp16)
// Wq pre-scaled by 0.125.
// ---------------------------------------------------------------------------
__global__ __launch_bounds__(256) void wtrans_kernel(
    const float* __restrict__ Wq, const float* __restrict__ Wk, const float* __restrict__ Wv)
{
    __shared__ float ts[64][65];
    const int c0 = blockIdx.x * 64;
    const int h  = blockIdx.y;
    const int mat = blockIdx.z;
    const float* W = (mat == 0) ? Wq : (mat == 1 ? Wk : Wv);
    const float scl = (mat == 0) ? 0.125f : 1.0f;
    const int tid = threadIdx.x;

    #pragma unroll
    for (int i = 0; i < 16; i++) {
        int idx = tid + i * 256;
        int r = idx >> 6, d = idx & 63;
        ts[r][d] = W[(size_t)h * (Cv * HSv) + (size_t)(c0 + r) * HSv + d] * scl;
    }
    __syncthreads();
    #pragma unroll
    for (int i = 0; i < 16; i++) {
        int idx = tid + i * 256;
        int dd = idx >> 6, cc = idx & 63;
        g_wt[((size_t)(mat * Hv + h) * HSv + dd) * Cv + c0 + cc] = __float2half_rn(ts[cc][dd]);
    }
}

// ---------------------------------------------------------------------------
// fp16 2-term GEMM on mma.sync.  C = (A_hi + A_lo) * B_hi
// MODE 0: QKV  -> q,k as fp16 hi/lo; v as fp16 hi only (b,h,t,d layout)
// MODE 1: proj -> fp32 out + bias
// CTA 128x128, BK=64, 8 warps (2x4), warp tile 64x32, 2-stage cp.async.
// smem/stage (55296 B): Ahi | Alo | B, each 128 rows x 144B (64 fp16 + pad).
// ---------------------------------------------------------------------------
template<int MODE>
__global__ __launch_bounds__(256, 2) void gemm_kernel(const float* __restrict__ bias,
                                                      float* __restrict__ outp)
{
    extern __shared__ char smem[];
    const uint32_t sb = smem_u32(smem);
    const int tid = threadIdx.x, lane = tid & 31, wid = tid >> 5;
    const int wm = wid & 1, wn = wid >> 1;
    const int nb = blockIdx.x, m0 = blockIdx.y * 128, mat = blockIdx.z;

    const __half *ahi, *alo, *bm;
    if (MODE == 0) {
        ahi = g_xhi; alo = g_xlo;
        bm  = g_wt + (size_t)mat * (Hv * HSv * Cv);
    } else {
        ahi = g_chi; alo = g_clo;
        bm  = g_wp;
    }

    // loader: 3072 16B data slots per stage (3 tiles x 128 rows x 8), 12/thread
    auto issue = [&](int c, int stg) {
        const int kc0 = c * 64;
        const uint32_t sbase = sb + (uint32_t)stg * 55296u;
        #pragma unroll
        for (int i = 0; i < 12; i++) {
            int s = tid + i * 256;
            int ms = s >> 10, r = (s >> 3) & 127, c8 = s & 7;
            const __half* src = (ms == 0) ? ahi : (ms == 1) ? alo : bm;
            int row = ((ms < 2) ? m0 : nb * 128) + r;
            const void* g = src + (size_t)row * Cv + kc0 + c8 * 8;
            uint32_t d = sbase + (uint32_t)ms * 18432u + (uint32_t)(r * 144 + c8 * 16);
            CP_ASYNC(d, g);
        }
        CP_COMMIT();
    };

    issue(0, 0);
    issue(1, 1);

    float acc[4][4][4] = {};

    for (int c = 0; c < NC; c++) {
        if (c + 1 < NC) CP_WAIT1(); else CP_WAIT0();
        __syncthreads();
        const uint32_t stg = sb + (uint32_t)(c & 1) * 55296u;

        #pragma unroll
        for (int ks = 0; ks < 4; ks++) {
            uint32_t a_hi[4][4], a_lo[4][4], b_[2][4];
            const int arow = (lane & 7) + ((lane >> 3) & 1) * 8;
            const int acol = ks * 16 + (lane >> 4) * 8;
            #pragma unroll
            for (int mt = 0; mt < 4; mt++) {
                uint32_t off = (uint32_t)((wm * 64 + mt * 16 + arow) * 144 + acol * 2);
                ldm_x4(a_hi[mt], stg + off);
                ldm_x4(a_lo[mt], stg + 18432u + off);
            }
            #pragma unroll
            for (int ntp = 0; ntp < 2; ntp++) {
                uint32_t off = (uint32_t)(
                    (wn * 32 + ntp * 16 + (lane & 7) + ((lane >> 4) & 1) * 8) * 144
                    + (ks * 16 + ((lane >> 3) & 1) * 8) * 2);
                ldm_x4(b_[ntp], stg + 36864u + off);
            }
            #pragma unroll
            for (int mt = 0; mt < 4; mt++)
                #pragma unroll
                for (int ntp = 0; ntp < 2; ntp++) {
                    mma16816(acc[mt][2*ntp],   a_hi[mt], b_[ntp]);
                    mma16816(acc[mt][2*ntp],   a_lo[mt], b_[ntp]);
                    mma16816(acc[mt][2*ntp+1], a_hi[mt], b_[ntp] + 2);
                    mma16816(acc[mt][2*ntp+1], a_lo[mt], b_[ntp] + 2);
                }
        }
        __syncthreads();
        if (c + 2 < NC) issue(c + 2, c & 1);
    }

    const int g = lane >> 2, tig = lane & 3;
    #pragma unroll
    for (int mt = 0; mt < 4; mt++) {
        const int r0 = m0 + wm * 64 + mt * 16 + g;
        const int r1 = r0 + 8;
        #pragma unroll
        for (int nt = 0; nt < 4; nt++) {
            const int n = nb * 128 + wn * 32 + nt * 8 + tig * 2;
            if (MODE == 0) {
                const int h = n >> 6, dd = n & 63;
                int b0 = r0 >> 11, t0 = r0 & (Tv - 1);
                int b1 = r1 >> 11, t1 = r1 & (Tv - 1);
                size_t i0 = (((size_t)(b0 * Hv + h)) * Tv + t0) * HSv + dd;
                size_t i1 = (((size_t)(b1 * Hv + h)) * Tv + t1) * HSv + dd;
                if (mat == 0) {
                    wr_hilo(g_qhi, g_qlo, i0, acc[mt][nt][0], acc[mt][nt][1]);
                    wr_hilo(g_qhi, g_qlo, i1, acc[mt][nt][2], acc[mt][nt][3]);
                } else if (mat == 1) {
                    wr_hilo(g_khi, g_klo, i0, acc[mt][nt][0], acc[mt][nt][1]);
                    wr_hilo(g_khi, g_klo, i1, acc[mt][nt][2], acc[mt][nt][3]);
                } else {
                    *(__half2*)&g_vh[i0] = __floats2half2_rn(acc[mt][nt][0], acc[mt][nt][1]);
                    *(__half2*)&g_vh[i1] = __floats2half2_rn(acc[mt][nt][2], acc[mt][nt][3]);
                }
            } else {
                float2 bv = *(const float2*)&bias[n];
                *(float2*)&outp[(size_t)r0 * Cv + n] =
                    make_float2(acc[mt][nt][0] + bv.x, acc[mt][nt][1] + bv.y);
                *(float2*)&outp[(size_t)r1 * Cv + n] =
                    make_float2(acc[mt][nt][2] + bv.x, acc[mt][nt][3] + bv.y);
            }
        }
    }
}

// ---------------------------------------------------------------------------
// fp16 HMMA causal flash attention (unchanged from R7 — at tensor floor).
// CTA = 128 queries, 8 warps x 16 rows. KV tiles 64, 2-stage cp.async.
// S = qh*kh + qh*kl + ql*kh ; PV = (ph+pl)*vh.
// smem: [2 stages][3 tiles: Khi,Klo,Vh][64 rows x 144B] = 55296 B
// ---------------------------------------------------------------------------
__global__ __launch_bounds__(256) void flash_kernel()
{
    extern __shared__ char smem[];
    const uint32_t sb = smem_u32(smem);
    const int tid = threadIdx.x, lane = tid & 31, w = tid >> 5;
    const int bx = blockIdx.x, bh = blockIdx.y;
    const int q0 = bx * 128;
    const int qb = q0 + w * 16;
    const int g = lane >> 2, tig = lane & 3;

    // ---- stage Q: hi -> tiles 0/1, lo -> tiles 2/3 ----
    {
        #pragma unroll
        for (int i = 0; i < 8; i++) {
            int s = tid + i * 256;
            int half_ = s >> 10, r = (s >> 3) & 127, c = s & 7;
            const __half* src = half_ ? g_qlo : g_qhi;
            const void* gp = src + ((size_t)bh * Tv + q0 + r) * 64 + c * 8;
            uint32_t d = sb + (uint32_t)(half_ * 2 + (r >= 64)) * 9216u
                       + (uint32_t)((r & 63) * 144 + c * 16);
            CP_ASYNC(d, gp);
        }
        CP_COMMIT(); CP_WAIT0();
        __syncthreads();
    }
    uint32_t qh[4][4], ql[4][4];
    {
        const int row = w * 16 + (lane & 15);
        const uint32_t hb = sb + ((row >= 64) ? 9216u : 0u);
        const uint32_t lb = sb + 18432u + ((row >= 64) ? 9216u : 0u);
        const int rl = row & 63;
        #pragma unroll
        for (int ks = 0; ks < 4; ks++) {
            uint32_t off = (uint32_t)(rl * 144 + (ks * 16 + (lane >> 4) * 8) * 2);
            ldm_x4(qh[ks], hb + off);
            ldm_x4(ql[ks], lb + off);
        }
    }
    __syncthreads();

    float acc[8][4] = {};
    float m0 = -1e30f, m1 = -1e30f, l0 = 0.0f, l1 = 0.0f;
    const int ntl = 2 * bx + 2;

    auto issueKV = [&](int jt, int stg) {
        const int kv0 = jt * 64;
        #pragma unroll
        for (int i = 0; i < 6; i++) {
            int s = tid + i * 256;
            int tile = s >> 9, r = (s >> 3) & 63, c = s & 7;
            const __half* src = (tile == 0) ? g_khi : (tile == 1) ? g_klo : g_vh;
            const void* gp = src + ((size_t)bh * Tv + kv0 + r) * 64 + c * 8;
            uint32_t d = sb + (uint32_t)stg * 27648u + (uint32_t)tile * 9216u
                       + (uint32_t)(r * 144 + c * 16);
            CP_ASYNC(d, gp);
        }
        CP_COMMIT();
    };
    issueKV(0, 0);
    issueKV(1, 1);

    for (int jt = 0; jt < ntl; jt++) {
        if (jt + 1 < ntl) CP_WAIT1(); else CP_WAIT0();
        __syncthreads();
        const int kv0 = jt * 64;
        const uint32_t stg = sb + (uint32_t)(jt & 1) * 27648u;

        if (kv0 <= qb + 15) {
            // ---- S = Q K^T (3-term fp16) ----
            float s[8][4] = {};
            #pragma unroll
            for (int ks = 0; ks < 4; ks++) {
                #pragma unroll
                for (int p = 0; p < 4; p++) {
                    uint32_t th[4], tl[4];
                    uint32_t koff = (uint32_t)(
                        (p * 16 + (lane & 7) + ((lane >> 4) & 1) * 8) * 144
                        + (ks * 16 + ((lane >> 3) & 1) * 8) * 2);
                    ldm_x4(th, stg + koff);
                    ldm_x4(tl, stg + 9216u + koff);
                    mma16816(s[2*p],   qh[ks], th);     mma16816(s[2*p],   qh[ks], tl);
                    mma16816(s[2*p],   ql[ks], th);
                    mma16816(s[2*p+1], qh[ks], th + 2); mma16816(s[2*p+1], qh[ks], tl + 2);
                    mma16816(s[2*p+1], ql[ks], th + 2);
                }
            }
            // ---- causal mask ----
            const int row0 = qb + g, row1 = row0 + 8;
            if (kv0 + 63 > row0) {
                #pragma unroll
                for (int nt = 0; nt < 8; nt++) {
                    int c0 = kv0 + nt * 8 + tig * 2;
                    if (c0     > row0) s[nt][0] = -1e30f;
                    if (c0 + 1 > row0) s[nt][1] = -1e30f;
                    if (c0     > row1) s[nt][2] = -1e30f;
                    if (c0 + 1 > row1) s[nt][3] = -1e30f;
                }
            }
            // ---- online softmax ----
            float mx0 = -1e30f, mx1 = -1e30f;
            #pragma unroll
            for (int nt = 0; nt < 8; nt++) {
                mx0 = fmaxf(mx0, fmaxf(s[nt][0], s[nt][1]));
                mx1 = fmaxf(mx1, fmaxf(s[nt][2], s[nt][3]));
            }
            mx0 = fmaxf(mx0, __shfl_xor_sync(0xffffffffu, mx0, 1));
            mx0 = fmaxf(mx0, __shfl_xor_sync(0xffffffffu, mx0, 2));
            mx1 = fmaxf(mx1, __shfl_xor_sync(0xffffffffu, mx1, 1));
            mx1 = fmaxf(mx1, __shfl_xor_sync(0xffffffffu, mx1, 2));
            const float mn0 = fmaxf(m0, mx0), mn1 = fmaxf(m1, mx1);
            const float f0 = __expf(m0 - mn0), f1 = __expf(m1 - mn1);
            m0 = mn0; m1 = mn1;

            uint32_t phi[8][2], plo[8][2];
            float rs0 = 0.0f, rs1 = 0.0f;
            #pragma unroll
            for (int nt = 0; nt < 8; nt++) {
                float p0 = __expf(s[nt][0] - mn0);
                float p1 = __expf(s[nt][1] - mn0);
                float p2 = __expf(s[nt][2] - mn1);
                float p3 = __expf(s[nt][3] - mn1);
                rs0 += p0 + p1; rs1 += p2 + p3;
                __half h0 = __float2half_rn(p0), h1 = __float2half_rn(p1);
                __half h2 = __float2half_rn(p2), h3 = __float2half_rn(p3);
                __half2 t01 = __halves2half2(h0, h1);
                __half2 t23 = __halves2half2(h2, h3);
                phi[nt][0] = *(uint32_t*)&t01;
                phi[nt][1] = *(uint32_t*)&t23;
                plo[nt][0] = pack_h2(p0 - __half2float(h0), p1 - __half2float(h1));
                plo[nt][1] = pack_h2(p2 - __half2float(h2), p3 - __half2float(h3));
            }
            rs0 += __shfl_xor_sync(0xffffffffu, rs0, 1);
            rs0 += __shfl_xor_sync(0xffffffffu, rs0, 2);
            rs1 += __shfl_xor_sync(0xffffffffu, rs1, 1);
            rs1 += __shfl_xor_sync(0xffffffffu, rs1, 2);
            l0 = l0 * f0 + rs0;
            l1 = l1 * f1 + rs1;
            #pragma unroll
            for (int dt = 0; dt < 8; dt++) {
                acc[dt][0] *= f0; acc[dt][1] *= f0;
                acc[dt][2] *= f1; acc[dt][3] *= f1;
            }
            // ---- O += P V_hi (2-term: p exact as hi+lo) ----
            #pragma unroll
            for (int ks = 0; ks < 4; ks++) {
                uint32_t ah[4] = { phi[2*ks][0], phi[2*ks][1], phi[2*ks+1][0], phi[2*ks+1][1] };
                uint32_t al[4] = { plo[2*ks][0], plo[2*ks][1], plo[2*ks+1][0], plo[2*ks+1][1] };
                #pragma unroll
                for (int dp = 0; dp < 4; dp++) {
                    uint32_t vh[4];
                    uint32_t voff = (uint32_t)(
                        (ks * 16 + (lane & 7) + ((lane >> 3) & 1) * 8) * 144
                        + (dp * 16 + (lane >> 4) * 8) * 2);
                    ldm_x4t(vh, stg + 18432u + voff);
                    mma16816(acc[2*dp],   ah, vh);     mma16816(acc[2*dp],   al, vh);
                    mma16816(acc[2*dp+1], ah, vh + 2); mma16816(acc[2*dp+1], al, vh + 2);
                }
            }
        }
        __syncthreads();
        if (jt + 2 < ntl) issueKV(jt + 2, jt & 1);
    }

    // ---- epilogue: combo hi/lo fp16 ----
    const float inv0 = 1.0f / l0, inv1 = 1.0f / l1;
    const int b = bh >> 4, h = bh & 15;
    const int t0 = qb + g, t1 = t0 + 8;
    #pragma unroll
    for (int dt = 0; dt < 8; dt++) {
        const int col = h * 64 + dt * 8 + tig * 2;
        wr_hilo(g_chi, g_clo, ((size_t)b * Tv + t0) * Cv + col,
                acc[dt][0] * inv0, acc[dt][1] * inv0);
        wr_hilo(g_chi, g_clo, ((size_t)b * Tv + t1) * Cv + col,
                acc[dt][2] * inv1, acc[dt][3] * inv1);
    }
}

// ---------------------------------------------------------------------------
extern "C" void kernel_launch(void* const* d_in, const int* in_sizes, int n_in,
                              void* d_out, int out_size)
{
    const float* x  = (const float*)d_in[0];
    const float* Wq = (const float*)d_in[1];
    const float* Wk = (const float*)d_in[2];
    const float* Wv = (const float*)d_in[3];
    const float* Wp = (const float*)d_in[4];
    const float* bp = (const float*)d_in[5];
    float* out = (float*)d_out;

    __half *xhi, *xlo, *wp;
    cudaGetSymbolAddress((void**)&xhi, g_xhi);
    cudaGetSymbolAddress((void**)&xlo, g_xlo);
    cudaGetSymbolAddress((void**)&wp,  g_wp);

    const int gemm_smem = 2 * 55296;   // 110592 B
    cudaFuncSetAttribute(gemm_kernel<0>, cudaFuncAttributeMaxDynamicSharedMemorySize, gemm_smem);
    cudaFuncSetAttribute(gemm_kernel<1>, cudaFuncAttributeMaxDynamicSharedMemorySize, gemm_smem);
    const int fl_smem = 2 * 27648;     // 55296 B
    cudaFuncSetAttribute(flash_kernel, cudaFuncAttributeMaxDynamicSharedMemorySize, fl_smem);

    // 1. split x; truncate Wproj; transpose+truncate Wq/k/v (Wq pre-scaled)
    decomp_kernel<<<(Mv * Cv / 4 + 255) / 256, 256>>>(x, xhi, xlo, Mv * Cv / 4);
    trunc_kernel<<<(Cv * Cv / 4 + 255) / 256, 256>>>(Wp, wp, Cv * Cv / 4);
    wtrans_kernel<<<dim3(Cv / 64, Hv, 3), 256>>>(Wq, Wk, Wv);

    // 2. QKV projections (fp16 2-term, BK=64) -> q,k hi/lo; v hi
    gemm_kernel<0><<<dim3(Cv / 128, Mv / 128, 3), 256, gemm_smem>>>(nullptr, nullptr);

    // 3. flash attention (S 3-term fp16, PV 2-term) -> combo hi/lo
    flash_kernel<<<dim3(Tv / 128, Bv * Hv), 256, fl_smem>>>();

    // 4. output projection (fp16 2-term, BK=64) + bias
    gemm_kernel<1><<<dim3(Cv / 128, Mv / 128, 1), 256, gemm_smem>>>(bp, out);
}

// round 9
// speedup vs baseline: 4.5714x; 1.1616x over previous
#include <cuda_runtime.h>
#include <cuda_fp16.h>
#include <stdint.h>

#define Bv 4
#define Tv 2048
#define Cv 1024
#define Hv 16
#define HSv 64
#define Mv (Bv*Tv)   /* 8192 */
#define NC 16        /* K=1024 / BK=64 */

// ---------------------------------------------------------------------------
// Static device scratch (no runtime allocation)
// ---------------------------------------------------------------------------
__device__ __half g_xhi[(size_t)Mv*Cv],  g_xlo[(size_t)Mv*Cv];
__device__ __half g_chi[(size_t)Mv*Cv],  g_clo[(size_t)Mv*Cv];
__device__ __half g_wt[(size_t)3*Hv*HSv*Cv];           // truncated W^T (mat0 pre-scaled)
__device__ __half g_wp[(size_t)Cv*Cv];                 // truncated Wproj
__device__ __half g_qh [(size_t)Bv*Hv*Tv*HSv];         // Q fp16 (1-term)
__device__ __half g_khi[(size_t)Bv*Hv*Tv*HSv], g_klo[(size_t)Bv*Hv*Tv*HSv];
__device__ __half g_vh [(size_t)Bv*Hv*Tv*HSv];         // V fp16 (1-term)

// ---------------------------------------------------------------------------
// Helpers
// ---------------------------------------------------------------------------
__device__ __forceinline__ uint32_t smem_u32(const void* p) {
    uint32_t a;
    asm("{ .reg .u64 t; cvta.to.shared.u64 t, %1; cvt.u32.u64 %0, t; }" : "=r"(a) : "l"(p));
    return a;
}
__device__ __forceinline__ void ldm_x4(uint32_t* r, uint32_t a) {
    asm volatile("ldmatrix.sync.aligned.m8n8.x4.shared.b16 {%0,%1,%2,%3}, [%4];"
        : "=r"(r[0]), "=r"(r[1]), "=r"(r[2]), "=r"(r[3]) : "r"(a));
}
__device__ __forceinline__ void ldm_x4t(uint32_t* r, uint32_t a) {
    asm volatile("ldmatrix.sync.aligned.m8n8.x4.trans.shared.b16 {%0,%1,%2,%3}, [%4];"
        : "=r"(r[0]), "=r"(r[1]), "=r"(r[2]), "=r"(r[3]) : "r"(a));
}
__device__ __forceinline__ void mma16816(float* d, const uint32_t* a, const uint32_t* b) {
    asm volatile(
        "mma.sync.aligned.m16n8k16.row.col.f32.f16.f16.f32 "
        "{%0,%1,%2,%3}, {%4,%5,%6,%7}, {%8,%9}, {%0,%1,%2,%3};"
        : "+f"(d[0]), "+f"(d[1]), "+f"(d[2]), "+f"(d[3])
        : "r"(a[0]), "r"(a[1]), "r"(a[2]), "r"(a[3]), "r"(b[0]), "r"(b[1]));
}
#define CP_ASYNC(dst, src) \
    asm volatile("cp.async.cg.shared.global [%0], [%1], 16;" :: "r"(dst), "l"(src) : "memory")
#define CP_COMMIT() asm volatile("cp.async.commit_group;" ::: "memory")
#define CP_WAIT1()  asm volatile("cp.async.wait_group 1;" ::: "memory")
#define CP_WAIT0()  asm volatile("cp.async.wait_group 0;" ::: "memory")

__device__ __forceinline__ uint32_t pack_h2(float a, float b) {
    __half2 t = __floats2half2_rn(a, b);
    return *(uint32_t*)&t;
}
__device__ __forceinline__ void wr_hilo(__half* hi, __half* lo, size_t idx, float a, float b) {
    __half ha = __float2half_rn(a), hb = __float2half_rn(b);
    *(__half2*)&hi[idx] = __halves2half2(ha, hb);
    *(__half2*)&lo[idx] = __halves2half2(__float2half_rn(a - __half2float(ha)),
                                         __float2half_rn(b - __half2float(hb)));
}

// ---------------------------------------------------------------------------
// Decompose fp32 -> fp16 hi + fp16 lo
// ---------------------------------------------------------------------------
__global__ void decomp_kernel(const float* __restrict__ src,
                              __half* __restrict__ hi, __half* __restrict__ lo, int n4)
{
    int i = blockIdx.x * blockDim.x + threadIdx.x;
    if (i >= n4) return;
    float4 v = ((const float4*)src)[i];
    __half h0 = __float2half_rn(v.x), h1 = __float2half_rn(v.y);
    __half h2 = __float2half_rn(v.z), h3 = __float2half_rn(v.w);
    __half2* hp = (__half2*)hi;
    __half2* lp = (__half2*)lo;
    hp[2*i]   = __halves2half2(h0, h1);
    hp[2*i+1] = __halves2half2(h2, h3);
    lp[2*i]   = __halves2half2(__float2half_rn(v.x - __half2float(h0)),
                               __float2half_rn(v.y - __half2float(h1)));
    lp[2*i+1] = __halves2half2(__float2half_rn(v.z - __half2float(h2)),
                               __float2half_rn(v.w - __half2float(h3)));
}

// Truncate fp32 -> fp16
__global__ void trunc_kernel(const float* __restrict__ src, __half* __restrict__ dst, int n4)
{
    int i = blockIdx.x * blockDim.x + threadIdx.x;
    if (i >= n4) return;
    float4 v = ((const float4*)src)[i];
    __half2* dp = (__half2*)dst;
    dp[2*i]   = __floats2half2_rn(v.x, v.y);
    dp[2*i+1] = __floats2half2_rn(v.z, v.w);
}

// ---------------------------------------------------------------------------
// Transpose + truncate Wq/Wk/Wv: W[h][c][d] -> Wt[mat][h][d][c]  (fp16)
// Wq pre-scaled by 0.125.
// ---------------------------------------------------------------------------
__global__ __launch_bounds__(256) void wtrans_kernel(
    const float* __restrict__ Wq, const float* __restrict__ Wk, const float* __restrict__ Wv)
{
    __shared__ float ts[64][65];
    const int c0 = blockIdx.x * 64;
    const int h  = blockIdx.y;
    const int mat = blockIdx.z;
    const float* W = (mat == 0) ? Wq : (mat == 1 ? Wk : Wv);
    const float scl = (mat == 0) ? 0.125f : 1.0f;
    const int tid = threadIdx.x;

    #pragma unroll
    for (int i = 0; i < 16; i++) {
        int idx = tid + i * 256;
        int r = idx >> 6, d = idx & 63;
        ts[r][d] = W[(size_t)h * (Cv * HSv) + (size_t)(c0 + r) * HSv + d] * scl;
    }
    __syncthreads();
    #pragma unroll
    for (int i = 0; i < 16; i++) {
        int idx = tid + i * 256;
        int dd = idx >> 6, cc = idx & 63;
        g_wt[((size_t)(mat * Hv + h) * HSv + dd) * Cv + c0 + cc] = __float2half_rn(ts[cc][dd]);
    }
}

// ---------------------------------------------------------------------------
// fp16 GEMM on mma.sync.
// MODE 0: QKV. mat1 (K): 2-term (x hi/lo), stored hi/lo.
//              mat0/2 (Q,V): 1-term (x_hi only), stored fp16.
// MODE 1: proj: 2-term (combo hi/lo) -> fp32 out + bias.
// CTA 128x128, BK=64, 8 warps (2x4), warp tile 64x32, 2-stage cp.async.
// smem/stage (55296 B): Ahi | Alo | B, each 128 rows x 144B.
// ---------------------------------------------------------------------------
template<int MODE>
__global__ __launch_bounds__(256, 2) void gemm_kernel(const float* __restrict__ bias,
                                                      float* __restrict__ outp)
{
    extern __shared__ char smem[];
    const uint32_t sb = smem_u32(smem);
    const int tid = threadIdx.x, lane = tid & 31, wid = tid >> 5;
    const int wm = wid & 1, wn = wid >> 1;
    const int nb = blockIdx.x, m0 = blockIdx.y * 128, mat = blockIdx.z;
    const bool two_term = (MODE == 1) || (mat == 1);

    const __half *ahi, *alo, *bm;
    if (MODE == 0) {
        ahi = g_xhi; alo = g_xlo;
        bm  = g_wt + (size_t)mat * (Hv * HSv * Cv);
    } else {
        ahi = g_chi; alo = g_clo;
        bm  = g_wp;
    }

    auto issue = [&](int c, int stg) {
        const int kc0 = c * 64;
        const uint32_t sbase = sb + (uint32_t)stg * 55296u;
        #pragma unroll
        for (int i = 0; i < 12; i++) {
            int s = tid + i * 256;
            int ms = s >> 10, r = (s >> 3) & 127, c8 = s & 7;
            if (ms == 1 && !two_term) continue;   // skip A_lo tile for 1-term mats
            const __half* src = (ms == 0) ? ahi : (ms == 1) ? alo : bm;
            int row = ((ms < 2) ? m0 : nb * 128) + r;
            const void* g = src + (size_t)row * Cv + kc0 + c8 * 8;
            uint32_t d = sbase + (uint32_t)ms * 18432u + (uint32_t)(r * 144 + c8 * 16);
            CP_ASYNC(d, g);
        }
        CP_COMMIT();
    };

    issue(0, 0);
    issue(1, 1);

    float acc[4][4][4] = {};

    for (int c = 0; c < NC; c++) {
        if (c + 1 < NC) CP_WAIT1(); else CP_WAIT0();
        __syncthreads();
        const uint32_t stg = sb + (uint32_t)(c & 1) * 55296u;

        #pragma unroll
        for (int ks = 0; ks < 4; ks++) {
            uint32_t a_hi[4][4], a_lo[4][4], b_[2][4];
            const int arow = (lane & 7) + ((lane >> 3) & 1) * 8;
            const int acol = ks * 16 + (lane >> 4) * 8;
            #pragma unroll
            for (int mt = 0; mt < 4; mt++) {
                uint32_t off = (uint32_t)((wm * 64 + mt * 16 + arow) * 144 + acol * 2);
                ldm_x4(a_hi[mt], stg + off);
                if (two_term) ldm_x4(a_lo[mt], stg + 18432u + off);
            }
            #pragma unroll
            for (int ntp = 0; ntp < 2; ntp++) {
                uint32_t off = (uint32_t)(
                    (wn * 32 + ntp * 16 + (lane & 7) + ((lane >> 4) & 1) * 8) * 144
                    + (ks * 16 + ((lane >> 3) & 1) * 8) * 2);
                ldm_x4(b_[ntp], stg + 36864u + off);
            }
            #pragma unroll
            for (int mt = 0; mt < 4; mt++)
                #pragma unroll
                for (int ntp = 0; ntp < 2; ntp++) {
                    mma16816(acc[mt][2*ntp],   a_hi[mt], b_[ntp]);
                    mma16816(acc[mt][2*ntp+1], a_hi[mt], b_[ntp] + 2);
                    if (two_term) {
                        mma16816(acc[mt][2*ntp],   a_lo[mt], b_[ntp]);
                        mma16816(acc[mt][2*ntp+1], a_lo[mt], b_[ntp] + 2);
                    }
                }
        }
        __syncthreads();
        if (c + 2 < NC) issue(c + 2, c & 1);
    }

    const int g = lane >> 2, tig = lane & 3;
    #pragma unroll
    for (int mt = 0; mt < 4; mt++) {
        const int r0 = m0 + wm * 64 + mt * 16 + g;
        const int r1 = r0 + 8;
        #pragma unroll
        for (int nt = 0; nt < 4; nt++) {
            const int n = nb * 128 + wn * 32 + nt * 8 + tig * 2;
            if (MODE == 0) {
                const int h = n >> 6, dd = n & 63;
                int b0 = r0 >> 11, t0 = r0 & (Tv - 1);
                int b1 = r1 >> 11, t1 = r1 & (Tv - 1);
                size_t i0 = (((size_t)(b0 * Hv + h)) * Tv + t0) * HSv + dd;
                size_t i1 = (((size_t)(b1 * Hv + h)) * Tv + t1) * HSv + dd;
                if (mat == 1) {
                    wr_hilo(g_khi, g_klo, i0, acc[mt][nt][0], acc[mt][nt][1]);
                    wr_hilo(g_khi, g_klo, i1, acc[mt][nt][2], acc[mt][nt][3]);
                } else {
                    __half* dst = (mat == 0) ? g_qh : g_vh;
                    *(__half2*)&dst[i0] = __floats2half2_rn(acc[mt][nt][0], acc[mt][nt][1]);
                    *(__half2*)&dst[i1] = __floats2half2_rn(acc[mt][nt][2], acc[mt][nt][3]);
                }
            } else {
                float2 bv = *(const float2*)&bias[n];
                *(float2*)&outp[(size_t)r0 * Cv + n] =
                    make_float2(acc[mt][nt][0] + bv.x, acc[mt][nt][1] + bv.y);
                *(float2*)&outp[(size_t)r1 * Cv + n] =
                    make_float2(acc[mt][nt][2] + bv.x, acc[mt][nt][3] + bv.y);
            }
        }
    }
}

// ---------------------------------------------------------------------------
// fp16 HMMA causal flash attention. CTA = 128 queries, 8 warps x 16 rows.
// S = q*kh + q*kl  (2-term; q plain fp16)
// PV = (ph+pl)*vh  (2-term: p exact as hi+lo)
// smem: [2 stages][3 tiles: Khi,Klo,Vh][64 rows x 144B] = 55296 B
// ---------------------------------------------------------------------------
__global__ __launch_bounds__(256) void flash_kernel()
{
    extern __shared__ char smem[];
    const uint32_t sb = smem_u32(smem);
    const int tid = threadIdx.x, lane = tid & 31, w = tid >> 5;
    const int bx = blockIdx.x, bh = blockIdx.y;
    const int q0 = bx * 128;
    const int qb = q0 + w * 16;
    const int g = lane >> 2, tig = lane & 3;

    // ---- stage Q (fp16, 128 rows -> tiles 0/1 of stage 0) ----
    {
        #pragma unroll
        for (int i = 0; i < 4; i++) {
            int s = tid + i * 256;
            int r = s >> 3, c = s & 7;
            const void* gp = g_qh + ((size_t)bh * Tv + q0 + r) * 64 + c * 8;
            uint32_t d = sb + (uint32_t)((r >= 64) ? 9216 : 0)
                       + (uint32_t)((r & 63) * 144 + c * 16);
            CP_ASYNC(d, gp);
        }
        CP_COMMIT(); CP_WAIT0();
        __syncthreads();
    }
    uint32_t qh[4][4];
    {
        const int row = w * 16 + (lane & 15);
        const uint32_t hb = sb + ((row >= 64) ? 9216u : 0u);
        const int rl = row & 63;
        #pragma unroll
        for (int ks = 0; ks < 4; ks++) {
            uint32_t off = (uint32_t)(rl * 144 + (ks * 16 + (lane >> 4) * 8) * 2);
            ldm_x4(qh[ks], hb + off);
        }
    }
    __syncthreads();

    float acc[8][4] = {};
    float m0 = -1e30f, m1 = -1e30f, l0 = 0.0f, l1 = 0.0f;
    const int ntl = 2 * bx + 2;

    auto issueKV = [&](int jt, int stg) {
        const int kv0 = jt * 64;
        #pragma unroll
        for (int i = 0; i < 6; i++) {
            int s = tid + i * 256;
            int tile = s >> 9, r = (s >> 3) & 63, c = s & 7;
            const __half* src = (tile == 0) ? g_khi : (tile == 1) ? g_klo : g_vh;
            const void* gp = src + ((size_t)bh * Tv + kv0 + r) * 64 + c * 8;
            uint32_t d = sb + (uint32_t)stg * 27648u + (uint32_t)tile * 9216u
                       + (uint32_t)(r * 144 + c * 16);
            CP_ASYNC(d, gp);
        }
        CP_COMMIT();
    };
    issueKV(0, 0);
    issueKV(1, 1);

    for (int jt = 0; jt < ntl; jt++) {
        if (jt + 1 < ntl) CP_WAIT1(); else CP_WAIT0();
        __syncthreads();
        const int kv0 = jt * 64;
        const uint32_t stg = sb + (uint32_t)(jt & 1) * 27648u;

        if (kv0 <= qb + 15) {
            // ---- S = q*(kh+kl) (2-term fp16) ----
            float s[8][4] = {};
            #pragma unroll
            for (int ks = 0; ks < 4; ks++) {
                #pragma unroll
                for (int p = 0; p < 4; p++) {
                    uint32_t th[4], tl[4];
                    uint32_t koff = (uint32_t)(
                        (p * 16 + (lane & 7) + ((lane >> 4) & 1) * 8) * 144
                        + (ks * 16 + ((lane >> 3) & 1) * 8) * 2);
                    ldm_x4(th, stg + koff);
                    ldm_x4(tl, stg + 9216u + koff);
                    mma16816(s[2*p],   qh[ks], th);     mma16816(s[2*p],   qh[ks], tl);
                    mma16816(s[2*p+1], qh[ks], th + 2); mma16816(s[2*p+1], qh[ks], tl + 2);
                }
            }
            // ---- causal mask ----
            const int row0 = qb + g, row1 = row0 + 8;
            if (kv0 + 63 > row0) {
                #pragma unroll
                for (int nt = 0; nt < 8; nt++) {
                    int c0 = kv0 + nt * 8 + tig * 2;
                    if (c0     > row0) s[nt][0] = -1e30f;
                    if (c0 + 1 > row0) s[nt][1] = -1e30f;
                    if (c0     > row1) s[nt][2] = -1e30f;
                    if (c0 + 1 > row1) s[nt][3] = -1e30f;
                }
            }
            // ---- online softmax ----
            float mx0 = -1e30f, mx1 = -1e30f;
            #pragma unroll
            for (int nt = 0; nt < 8; nt++) {
                mx0 = fmaxf(mx0, fmaxf(s[nt][0], s[nt][1]));
                mx1 = fmaxf(mx1, fmaxf(s[nt][2], s[nt][3]));
            }
            mx0 = fmaxf(mx0, __shfl_xor_sync(0xffffffffu, mx0, 1));
            mx0 = fmaxf(mx0, __shfl_xor_sync(0xffffffffu, mx0, 2));
            mx1 = fmaxf(mx1, __shfl_xor_sync(0xffffffffu, mx1, 1));
            mx1 = fmaxf(mx1, __shfl_xor_sync(0xffffffffu, mx1, 2));
            const float mn0 = fmaxf(m0, mx0), mn1 = fmaxf(m1, mx1);
            const float f0 = __expf(m0 - mn0), f1 = __expf(m1 - mn1);
            m0 = mn0; m1 = mn1;

            uint32_t phi[8][2], plo[8][2];
            float rs0 = 0.0f, rs1 = 0.0f;
            #pragma unroll
            for (int nt = 0; nt < 8; nt++) {
                float p0 = __expf(s[nt][0] - mn0);
                float p1 = __expf(s[nt][1] - mn0);
                float p2 = __expf(s[nt][2] - mn1);
                float p3 = __expf(s[nt][3] - mn1);
                rs0 += p0 + p1; rs1 += p2 + p3;
                __half h0 = __float2half_rn(p0), h1 = __float2half_rn(p1);
                __half h2 = __float2half_rn(p2), h3 = __float2half_rn(p3);
                __half2 t01 = __halves2half2(h0, h1);
                __half2 t23 = __halves2half2(h2, h3);
                phi[nt][0] = *(uint32_t*)&t01;
                phi[nt][1] = *(uint32_t*)&t23;
                plo[nt][0] = pack_h2(p0 - __half2float(h0), p1 - __half2float(h1));
                plo[nt][1] = pack_h2(p2 - __half2float(h2), p3 - __half2float(h3));
            }
            rs0 += __shfl_xor_sync(0xffffffffu, rs0, 1);
            rs0 += __shfl_xor_sync(0xffffffffu, rs0, 2);
            rs1 += __shfl_xor_sync(0xffffffffu, rs1, 1);
            rs1 += __shfl_xor_sync(0xffffffffu, rs1, 2);
            l0 = l0 * f0 + rs0;
            l1 = l1 * f1 + rs1;
            #pragma unroll
            for (int dt = 0; dt < 8; dt++) {
                acc[dt][0] *= f0; acc[dt][1] *= f0;
                acc[dt][2] *= f1; acc[dt][3] *= f1;
            }
            // ---- O += P V_hi (2-term: p exact as hi+lo) ----
            #pragma unroll
            for (int ks = 0; ks < 4; ks++) {
                uint32_t ah[4] = { phi[2*ks][0], phi[2*ks][1], phi[2*ks+1][0], phi[2*ks+1][1] };
                uint32_t al[4] = { plo[2*ks][0], plo[2*ks][1], plo[2*ks+1][0], plo[2*ks+1][1] };
                #pragma unroll
                for (int dp = 0; dp < 4; dp++) {
                    uint32_t vh[4];
                    uint32_t voff = (uint32_t)(
                        (ks * 16 + (lane & 7) + ((lane >> 3) & 1) * 8) * 144
                        + (dp * 16 + (lane >> 4) * 8) * 2);
                    ldm_x4t(vh, stg + 18432u + voff);
                    mma16816(acc[2*dp],   ah, vh);     mma16816(acc[2*dp],   al, vh);
                    mma16816(acc[2*dp+1], ah, vh + 2); mma16816(acc[2*dp+1], al, vh + 2);
                }
            }
        }
        __syncthreads();
        if (jt + 2 < ntl) issueKV(jt + 2, jt & 1);
    }

    // ---- epilogue: combo hi/lo fp16 ----
    const float inv0 = 1.0f / l0, inv1 = 1.0f / l1;
    const int b = bh >> 4, h = bh & 15;
    const int t0 = qb + g, t1 = t0 + 8;
    #pragma unroll
    for (int dt = 0; dt < 8; dt++) {
        const int col = h * 64 + dt * 8 + tig * 2;
        wr_hilo(g_chi, g_clo, ((size_t)b * Tv + t0) * Cv + col,
                acc[dt][0] * inv0, acc[dt][1] * inv0);
        wr_hilo(g_chi, g_clo, ((size_t)b * Tv + t1) * Cv + col,
                acc[dt][2] * inv1, acc[dt][3] * inv1);
    }
}

// ---------------------------------------------------------------------------
extern "C" void kernel_launch(void* const* d_in, const int* in_sizes, int n_in,
                              void* d_out, int out_size)
{
    const float* x  = (const float*)d_in[0];
    const float* Wq = (const float*)d_in[1];
    const float* Wk = (const float*)d_in[2];
    const float* Wv = (const float*)d_in[3];
    const float* Wp = (const float*)d_in[4];
    const float* bp = (const float*)d_in[5];
    float* out = (float*)d_out;

    __half *xhi, *xlo, *wp;
    cudaGetSymbolAddress((void**)&xhi, g_xhi);
    cudaGetSymbolAddress((void**)&xlo, g_xlo);
    cudaGetSymbolAddress((void**)&wp,  g_wp);

    const int gemm_smem = 2 * 55296;   // 110592 B
    cudaFuncSetAttribute(gemm_kernel<0>, cudaFuncAttributeMaxDynamicSharedMemorySize, gemm_smem);
    cudaFuncSetAttribute(gemm_kernel<1>, cudaFuncAttributeMaxDynamicSharedMemorySize, gemm_smem);
    const int fl_smem = 2 * 27648;     // 55296 B
    cudaFuncSetAttribute(flash_kernel, cudaFuncAttributeMaxDynamicSharedMemorySize, fl_smem);

    // 1. split x; truncate Wproj; transpose+truncate Wq/k/v (Wq pre-scaled)
    decomp_kernel<<<(Mv * Cv / 4 + 255) / 256, 256>>>(x, xhi, xlo, Mv * Cv / 4);
    trunc_kernel<<<(Cv * Cv / 4 + 255) / 256, 256>>>(Wp, wp, Cv * Cv / 4);
    wtrans_kernel<<<dim3(Cv / 64, Hv, 3), 256>>>(Wq, Wk, Wv);

    // 2. QKV projections: q,v 1-term; k 2-term
    gemm_kernel<0><<<dim3(Cv / 128, Mv / 128, 3), 256, gemm_smem>>>(nullptr, nullptr);

    // 3. flash attention (S 2-term, PV 2-term) -> combo hi/lo
    flash_kernel<<<dim3(Tv / 128, Bv * Hv), 256, fl_smem>>>();

    // 4. output projection (2-term) + bias
    gemm_kernel<1><<<dim3(Cv / 128, Mv / 128, 1), 256, gemm_smem>>>(bp, out);
}

// round 10
// speedup vs baseline: 5.2669x; 1.1522x over previous
#include <cuda_runtime.h>
#include <cuda_fp16.h>
#include <stdint.h>

#define Bv 4
#define Tv 2048
#define Cv 1024
#define Hv 16
#define HSv 64
#define Mv (Bv*Tv)   /* 8192 */
#define NC 16        /* K=1024 / BK=64 */

// ---------------------------------------------------------------------------
// Static device scratch (no runtime allocation)
// ---------------------------------------------------------------------------
__device__ __half g_xhi[(size_t)Mv*Cv],  g_xlo[(size_t)Mv*Cv];
__device__ __half g_ch [(size_t)Mv*Cv];                // combo fp16 (1-term proj)
__device__ __half g_wt[(size_t)3*Hv*HSv*Cv];           // truncated W^T (mat0 pre-scaled)
__device__ __half g_wp[(size_t)Cv*Cv];                 // truncated Wproj
__device__ __half g_qh [(size_t)Bv*Hv*Tv*HSv];         // Q fp16 (1-term)
__device__ __half g_khi[(size_t)Bv*Hv*Tv*HSv], g_klo[(size_t)Bv*Hv*Tv*HSv];
__device__ __half g_vh [(size_t)Bv*Hv*Tv*HSv];         // V fp16 (1-term)

// ---------------------------------------------------------------------------
// Helpers
// ---------------------------------------------------------------------------
__device__ __forceinline__ uint32_t smem_u32(const void* p) {
    uint32_t a;
    asm("{ .reg .u64 t; cvta.to.shared.u64 t, %1; cvt.u32.u64 %0, t; }" : "=r"(a) : "l"(p));
    return a;
}
__device__ __forceinline__ void ldm_x4(uint32_t* r, uint32_t a) {
    asm volatile("ldmatrix.sync.aligned.m8n8.x4.shared.b16 {%0,%1,%2,%3}, [%4];"
        : "=r"(r[0]), "=r"(r[1]), "=r"(r[2]), "=r"(r[3]) : "r"(a));
}
__device__ __forceinline__ void ldm_x4t(uint32_t* r, uint32_t a) {
    asm volatile("ldmatrix.sync.aligned.m8n8.x4.trans.shared.b16 {%0,%1,%2,%3}, [%4];"
        : "=r"(r[0]), "=r"(r[1]), "=r"(r[2]), "=r"(r[3]) : "r"(a));
}
__device__ __forceinline__ void mma16816(float* d, const uint32_t* a, const uint32_t* b) {
    asm volatile(
        "mma.sync.aligned.m16n8k16.row.col.f32.f16.f16.f32 "
        "{%0,%1,%2,%3}, {%4,%5,%6,%7}, {%8,%9}, {%0,%1,%2,%3};"
        : "+f"(d[0]), "+f"(d[1]), "+f"(d[2]), "+f"(d[3])
        : "r"(a[0]), "r"(a[1]), "r"(a[2]), "r"(a[3]), "r"(b[0]), "r"(b[1]));
}
#define CP_ASYNC(dst, src) \
    asm volatile("cp.async.cg.shared.global [%0], [%1], 16;" :: "r"(dst), "l"(src) : "memory")
#define CP_COMMIT() asm volatile("cp.async.commit_group;" ::: "memory")
#define CP_WAIT1()  asm volatile("cp.async.wait_group 1;" ::: "memory")
#define CP_WAIT0()  asm volatile("cp.async.wait_group 0;" ::: "memory")

__device__ __forceinline__ void wr_hilo(__half* hi, __half* lo, size_t idx, float a, float b) {
    __half ha = __float2half_rn(a), hb = __float2half_rn(b);
    *(__half2*)&hi[idx] = __halves2half2(ha, hb);
    *(__half2*)&lo[idx] = __halves2half2(__float2half_rn(a - __half2float(ha)),
                                         __float2half_rn(b - __half2float(hb)));
}

// ---------------------------------------------------------------------------
// Decompose fp32 -> fp16 hi + fp16 lo
// ---------------------------------------------------------------------------
__global__ void decomp_kernel(const float* __restrict__ src,
                              __half* __restrict__ hi, __half* __restrict__ lo, int n4)
{
    int i = blockIdx.x * blockDim.x + threadIdx.x;
    if (i >= n4) return;
    float4 v = ((const float4*)src)[i];
    __half h0 = __float2half_rn(v.x), h1 = __float2half_rn(v.y);
    __half h2 = __float2half_rn(v.z), h3 = __float2half_rn(v.w);
    __half2* hp = (__half2*)hi;
    __half2* lp = (__half2*)lo;
    hp[2*i]   = __halves2half2(h0, h1);
    hp[2*i+1] = __halves2half2(h2, h3);
    lp[2*i]   = __halves2half2(__float2half_rn(v.x - __half2float(h0)),
                               __float2half_rn(v.y - __half2float(h1)));
    lp[2*i+1] = __halves2half2(__float2half_rn(v.z - __half2float(h2)),
                               __float2half_rn(v.w - __half2float(h3)));
}

// Truncate fp32 -> fp16
__global__ void trunc_kernel(const float* __restrict__ src, __half* __restrict__ dst, int n4)
{
    int i = blockIdx.x * blockDim.x + threadIdx.x;
    if (i >= n4) return;
    float4 v = ((const float4*)src)[i];
    __half2* dp = (__half2*)dst;
    dp[2*i]   = __floats2half2_rn(v.x, v.y);
    dp[2*i+1] = __floats2half2_rn(v.z, v.w);
}

// ---------------------------------------------------------------------------
// Transpose + truncate Wq/Wk/Wv: W[h][c][d] -> Wt[mat][h][d][c]  (fp16)
// Wq pre-scaled by 0.125.
// ---------------------------------------------------------------------------
__global__ __launch_bounds__(256) void wtrans_kernel(
    const float* __restrict__ Wq, const float* __restrict__ Wk, const float* __restrict__ Wv)
{
    __shared__ float ts[64][65];
    const int c0 = blockIdx.x * 64;
    const int h  = blockIdx.y;
    const int mat = blockIdx.z;
    const float* W = (mat == 0) ? Wq : (mat == 1 ? Wk : Wv);
    const float scl = (mat == 0) ? 0.125f : 1.0f;
    const int tid = threadIdx.x;

    #pragma unroll
    for (int i = 0; i < 16; i++) {
        int idx = tid + i * 256;
        int r = idx >> 6, d = idx & 63;
        ts[r][d] = W[(size_t)h * (Cv * HSv) + (size_t)(c0 + r) * HSv + d] * scl;
    }
    __syncthreads();
    #pragma unroll
    for (int i = 0; i < 16; i++) {
        int idx = tid + i * 256;
        int dd = idx >> 6, cc = idx & 63;
        g_wt[((size_t)(mat * Hv + h) * HSv + dd) * Cv + c0 + cc] = __float2half_rn(ts[cc][dd]);
    }
}

// ---------------------------------------------------------------------------
// fp16 GEMM on mma.sync.
// MODE 0: QKV. mat1 (K): 2-term (x hi/lo), stored hi/lo.
//              mat0/2 (Q,V): 1-term (x_hi only), stored fp16.
// MODE 1: proj: 1-term (combo fp16) -> fp32 out + bias.
// CTA 128x128, BK=64, 8 warps (2x4), warp tile 64x32, 2-stage cp.async.
// smem/stage (55296 B): Ahi | Alo | B, each 128 rows x 144B.
// ---------------------------------------------------------------------------
template<int MODE>
__global__ __launch_bounds__(256, 2) void gemm_kernel(const float* __restrict__ bias,
                                                      float* __restrict__ outp)
{
    extern __shared__ char smem[];
    const uint32_t sb = smem_u32(smem);
    const int tid = threadIdx.x, lane = tid & 31, wid = tid >> 5;
    const int wm = wid & 1, wn = wid >> 1;
    const int nb = blockIdx.x, m0 = blockIdx.y * 128, mat = blockIdx.z;
    const bool two_term = (MODE == 0) && (mat == 1);

    const __half *ahi, *alo, *bm;
    if (MODE == 0) {
        ahi = g_xhi; alo = g_xlo;
        bm  = g_wt + (size_t)mat * (Hv * HSv * Cv);
    } else {
        ahi = g_ch; alo = g_ch;   // alo unused (1-term)
        bm  = g_wp;
    }

    auto issue = [&](int c, int stg) {
        const int kc0 = c * 64;
        const uint32_t sbase = sb + (uint32_t)stg * 55296u;
        #pragma unroll
        for (int i = 0; i < 12; i++) {
            int s = tid + i * 256;
            int ms = s >> 10, r = (s >> 3) & 127, c8 = s & 7;
            if (ms == 1 && !two_term) continue;   // skip A_lo tile for 1-term mats
            const __half* src = (ms == 0) ? ahi : (ms == 1) ? alo : bm;
            int row = ((ms < 2) ? m0 : nb * 128) + r;
            const void* g = src + (size_t)row * Cv + kc0 + c8 * 8;
            uint32_t d = sbase + (uint32_t)ms * 18432u + (uint32_t)(r * 144 + c8 * 16);
            CP_ASYNC(d, g);
        }
        CP_COMMIT();
    };

    issue(0, 0);
    issue(1, 1);

    float acc[4][4][4] = {};

    for (int c = 0; c < NC; c++) {
        if (c + 1 < NC) CP_WAIT1(); else CP_WAIT0();
        __syncthreads();
        const uint32_t stg = sb + (uint32_t)(c & 1) * 55296u;

        #pragma unroll
        for (int ks = 0; ks < 4; ks++) {
            uint32_t a_hi[4][4], a_lo[4][4], b_[2][4];
            const int arow = (lane & 7) + ((lane >> 3) & 1) * 8;
            const int acol = ks * 16 + (lane >> 4) * 8;
            #pragma unroll
            for (int mt = 0; mt < 4; mt++) {
                uint32_t off = (uint32_t)((wm * 64 + mt * 16 + arow) * 144 + acol * 2);
                ldm_x4(a_hi[mt], stg + off);
                if (two_term) ldm_x4(a_lo[mt], stg + 18432u + off);
            }
            #pragma unroll
            for (int ntp = 0; ntp < 2; ntp++) {
                uint32_t off = (uint32_t)(
                    (wn * 32 + ntp * 16 + (lane & 7) + ((lane >> 4) & 1) * 8) * 144
                    + (ks * 16 + ((lane >> 3) & 1) * 8) * 2);
                ldm_x4(b_[ntp], stg + 36864u + off);
            }
            #pragma unroll
            for (int mt = 0; mt < 4; mt++)
                #pragma unroll
                for (int ntp = 0; ntp < 2; ntp++) {
                    mma16816(acc[mt][2*ntp],   a_hi[mt], b_[ntp]);
                    mma16816(acc[mt][2*ntp+1], a_hi[mt], b_[ntp] + 2);
                    if (two_term) {
                        mma16816(acc[mt][2*ntp],   a_lo[mt], b_[ntp]);
                        mma16816(acc[mt][2*ntp+1], a_lo[mt], b_[ntp] + 2);
                    }
                }
        }
        __syncthreads();
        if (c + 2 < NC) issue(c + 2, c & 1);
    }

    const int g = lane >> 2, tig = lane & 3;
    #pragma unroll
    for (int mt = 0; mt < 4; mt++) {
        const int r0 = m0 + wm * 64 + mt * 16 + g;
        const int r1 = r0 + 8;
        #pragma unroll
        for (int nt = 0; nt < 4; nt++) {
            const int n = nb * 128 + wn * 32 + nt * 8 + tig * 2;
            if (MODE == 0) {
                const int h = n >> 6, dd = n & 63;
                int b0 = r0 >> 11, t0 = r0 & (Tv - 1);
                int b1 = r1 >> 11, t1 = r1 & (Tv - 1);
                size_t i0 = (((size_t)(b0 * Hv + h)) * Tv + t0) * HSv + dd;
                size_t i1 = (((size_t)(b1 * Hv + h)) * Tv + t1) * HSv + dd;
                if (mat == 1) {
                    wr_hilo(g_khi, g_klo, i0, acc[mt][nt][0], acc[mt][nt][1]);
                    wr_hilo(g_khi, g_klo, i1, acc[mt][nt][2], acc[mt][nt][3]);
                } else {
                    __half* dst = (mat == 0) ? g_qh : g_vh;
                    *(__half2*)&dst[i0] = __floats2half2_rn(acc[mt][nt][0], acc[mt][nt][1]);
                    *(__half2*)&dst[i1] = __floats2half2_rn(acc[mt][nt][2], acc[mt][nt][3]);
                }
            } else {
                float2 bv = *(const float2*)&bias[n];
                *(float2*)&outp[(size_t)r0 * Cv + n] =
                    make_float2(acc[mt][nt][0] + bv.x, acc[mt][nt][1] + bv.y);
                *(float2*)&outp[(size_t)r1 * Cv + n] =
                    make_float2(acc[mt][nt][2] + bv.x, acc[mt][nt][3] + bv.y);
            }
        }
    }
}

// ---------------------------------------------------------------------------
// fp16 HMMA causal flash attention. CTA = 128 queries, 8 warps x 16 rows.
// S = q*kh + q*kl  (2-term; q plain fp16)
// PV = p_hi * v_hi (1-term; p in [0,1], clean truncation)
// smem: [2 stages][3 tiles: Khi,Klo,Vh][64 rows x 144B] = 55296 B
// ---------------------------------------------------------------------------
__global__ __launch_bounds__(256) void flash_kernel()
{
    extern __shared__ char smem[];
    const uint32_t sb = smem_u32(smem);
    const int tid = threadIdx.x, lane = tid & 31, w = tid >> 5;
    const int bx = blockIdx.x, bh = blockIdx.y;
    const int q0 = bx * 128;
    const int qb = q0 + w * 16;
    const int g = lane >> 2, tig = lane & 3;

    // ---- stage Q (fp16, 128 rows -> tiles 0/1 of stage 0) ----
    {
        #pragma unroll
        for (int i = 0; i < 4; i++) {
            int s = tid + i * 256;
            int r = s >> 3, c = s & 7;
            const void* gp = g_qh + ((size_t)bh * Tv + q0 + r) * 64 + c * 8;
            uint32_t d = sb + (uint32_t)((r >= 64) ? 9216 : 0)
                       + (uint32_t)((r & 63) * 144 + c * 16);
            CP_ASYNC(d, gp);
        }
        CP_COMMIT(); CP_WAIT0();
        __syncthreads();
    }
    uint32_t qh[4][4];
    {
        const int row = w * 16 + (lane & 15);
        const uint32_t hb = sb + ((row >= 64) ? 9216u : 0u);
        const int rl = row & 63;
        #pragma unroll
        for (int ks = 0; ks < 4; ks++) {
            uint32_t off = (uint32_t)(rl * 144 + (ks * 16 + (lane >> 4) * 8) * 2);
            ldm_x4(qh[ks], hb + off);
        }
    }
    __syncthreads();

    float acc[8][4] = {};
    float m0 = -1e30f, m1 = -1e30f, l0 = 0.0f, l1 = 0.0f;
    const int ntl = 2 * bx + 2;

    auto issueKV = [&](int jt, int stg) {
        const int kv0 = jt * 64;
        #pragma unroll
        for (int i = 0; i < 6; i++) {
            int s = tid + i * 256;
            int tile = s >> 9, r = (s >> 3) & 63, c = s & 7;
            const __half* src = (tile == 0) ? g_khi : (tile == 1) ? g_klo : g_vh;
            const void* gp = src + ((size_t)bh * Tv + kv0 + r) * 64 + c * 8;
            uint32_t d = sb + (uint32_t)stg * 27648u + (uint32_t)tile * 9216u
                       + (uint32_t)(r * 144 + c * 16);
            CP_ASYNC(d, gp);
        }
        CP_COMMIT();
    };
    issueKV(0, 0);
    issueKV(1, 1);

    for (int jt = 0; jt < ntl; jt++) {
        if (jt + 1 < ntl) CP_WAIT1(); else CP_WAIT0();
        __syncthreads();
        const int kv0 = jt * 64;
        const uint32_t stg = sb + (uint32_t)(jt & 1) * 27648u;

        if (kv0 <= qb + 15) {
            // ---- S = q*(kh+kl) (2-term fp16) ----
            float s[8][4] = {};
            #pragma unroll
            for (int ks = 0; ks < 4; ks++) {
                #pragma unroll
                for (int p = 0; p < 4; p++) {
                    uint32_t th[4], tl[4];
                    uint32_t koff = (uint32_t)(
                        (p * 16 + (lane & 7) + ((lane >> 4) & 1) * 8) * 144
                        + (ks * 16 + ((lane >> 3) & 1) * 8) * 2);
                    ldm_x4(th, stg + koff);
                    ldm_x4(tl, stg + 9216u + koff);
                    mma16816(s[2*p],   qh[ks], th);     mma16816(s[2*p],   qh[ks], tl);
                    mma16816(s[2*p+1], qh[ks], th + 2); mma16816(s[2*p+1], qh[ks], tl + 2);
                }
            }
            // ---- causal mask ----
            const int row0 = qb + g, row1 = row0 + 8;
            if (kv0 + 63 > row0) {
                #pragma unroll
                for (int nt = 0; nt < 8; nt++) {
                    int c0 = kv0 + nt * 8 + tig * 2;
                    if (c0     > row0) s[nt][0] = -1e30f;
                    if (c0 + 1 > row0) s[nt][1] = -1e30f;
                    if (c0     > row1) s[nt][2] = -1e30f;
                    if (c0 + 1 > row1) s[nt][3] = -1e30f;
                }
            }
            // ---- online softmax ----
            float mx0 = -1e30f, mx1 = -1e30f;
            #pragma unroll
            for (int nt = 0; nt < 8; nt++) {
                mx0 = fmaxf(mx0, fmaxf(s[nt][0], s[nt][1]));
                mx1 = fmaxf(mx1, fmaxf(s[nt][2], s[nt][3]));
            }
            mx0 = fmaxf(mx0, __shfl_xor_sync(0xffffffffu, mx0, 1));
            mx0 = fmaxf(mx0, __shfl_xor_sync(0xffffffffu, mx0, 2));
            mx1 = fmaxf(mx1, __shfl_xor_sync(0xffffffffu, mx1, 1));
            mx1 = fmaxf(mx1, __shfl_xor_sync(0xffffffffu, mx1, 2));
            const float mn0 = fmaxf(m0, mx0), mn1 = fmaxf(m1, mx1);
            const float f0 = __expf(m0 - mn0), f1 = __expf(m1 - mn1);
            m0 = mn0; m1 = mn1;

            uint32_t phi[8][2];
            float rs0 = 0.0f, rs1 = 0.0f;
            #pragma unroll
            for (int nt = 0; nt < 8; nt++) {
                float p0 = __expf(s[nt][0] - mn0);
                float p1 = __expf(s[nt][1] - mn0);
                float p2 = __expf(s[nt][2] - mn1);
                float p3 = __expf(s[nt][3] - mn1);
                rs0 += p0 + p1; rs1 += p2 + p3;
                __half2 t01 = __floats2half2_rn(p0, p1);
                __half2 t23 = __floats2half2_rn(p2, p3);
                phi[nt][0] = *(uint32_t*)&t01;
                phi[nt][1] = *(uint32_t*)&t23;
            }
            rs0 += __shfl_xor_sync(0xffffffffu, rs0, 1);
            rs0 += __shfl_xor_sync(0xffffffffu, rs0, 2);
            rs1 += __shfl_xor_sync(0xffffffffu, rs1, 1);
            rs1 += __shfl_xor_sync(0xffffffffu, rs1, 2);
            l0 = l0 * f0 + rs0;
            l1 = l1 * f1 + rs1;
            #pragma unroll
            for (int dt = 0; dt < 8; dt++) {
                acc[dt][0] *= f0; acc[dt][1] *= f0;
                acc[dt][2] *= f1; acc[dt][3] *= f1;
            }
            // ---- O += P_hi V_hi (1-term) ----
            #pragma unroll
            for (int ks = 0; ks < 4; ks++) {
                uint32_t ah[4] = { phi[2*ks][0], phi[2*ks][1], phi[2*ks+1][0], phi[2*ks+1][1] };
                #pragma unroll
                for (int dp = 0; dp < 4; dp++) {
                    uint32_t vh[4];
                    uint32_t voff = (uint32_t)(
                        (ks * 16 + (lane & 7) + ((lane >> 3) & 1) * 8) * 144
                        + (dp * 16 + (lane >> 4) * 8) * 2);
                    ldm_x4t(vh, stg + 18432u + voff);
                    mma16816(acc[2*dp],   ah, vh);
                    mma16816(acc[2*dp+1], ah, vh + 2);
                }
            }
        }
        __syncthreads();
        if (jt + 2 < ntl) issueKV(jt + 2, jt & 1);
    }

    // ---- epilogue: combo fp16 ----
    const float inv0 = 1.0f / l0, inv1 = 1.0f / l1;
    const int b = bh >> 4, h = bh & 15;
    const int t0 = qb + g, t1 = t0 + 8;
    #pragma unroll
    for (int dt = 0; dt < 8; dt++) {
        const int col = h * 64 + dt * 8 + tig * 2;
        *(__half2*)&g_ch[((size_t)b * Tv + t0) * Cv + col] =
            __floats2half2_rn(acc[dt][0] * inv0, acc[dt][1] * inv0);
        *(__half2*)&g_ch[((size_t)b * Tv + t1) * Cv + col] =
            __floats2half2_rn(acc[dt][2] * inv1, acc[dt][3] * inv1);
    }
}

// ---------------------------------------------------------------------------
extern "C" void kernel_launch(void* const* d_in, const int* in_sizes, int n_in,
                              void* d_out, int out_size)
{
    const float* x  = (const float*)d_in[0];
    const float* Wq = (const float*)d_in[1];
    const float* Wk = (const float*)d_in[2];
    const float* Wv = (const float*)d_in[3];
    const float* Wp = (const float*)d_in[4];
    const float* bp = (const float*)d_in[5];
    float* out = (float*)d_out;

    __half *xhi, *xlo, *wp;
    cudaGetSymbolAddress((void**)&xhi, g_xhi);
    cudaGetSymbolAddress((void**)&xlo, g_xlo);
    cudaGetSymbolAddress((void**)&wp,  g_wp);

    const int gemm_smem = 2 * 55296;   // 110592 B
    cudaFuncSetAttribute(gemm_kernel<0>, cudaFuncAttributeMaxDynamicSharedMemorySize, gemm_smem);
    cudaFuncSetAttribute(gemm_kernel<1>, cudaFuncAttributeMaxDynamicSharedMemorySize, gemm_smem);
    const int fl_smem = 2 * 27648;     // 55296 B
    cudaFuncSetAttribute(flash_kernel, cudaFuncAttributeMaxDynamicSharedMemorySize, fl_smem);

    // 1. split x; truncate Wproj; transpose+truncate Wq/k/v (Wq pre-scaled)
    decomp_kernel<<<(Mv * Cv / 4 + 255) / 256, 256>>>(x, xhi, xlo, Mv * Cv / 4);
    trunc_kernel<<<(Cv * Cv / 4 + 255) / 256, 256>>>(Wp, wp, Cv * Cv / 4);
    wtrans_kernel<<<dim3(Cv / 64, Hv, 3), 256>>>(Wq, Wk, Wv);

    // 2. QKV projections: q,v 1-term; k 2-term
    gemm_kernel<0><<<dim3(Cv / 128, Mv / 128, 3), 256, gemm_smem>>>(nullptr, nullptr);

    // 3. flash attention (S 2-term, PV 1-term) -> combo fp16
    flash_kernel<<<dim3(Tv / 128, Bv * Hv), 256, fl_smem>>>();

    // 4. output projection (1-term) + bias
    gemm_kernel<1><<<dim3(Cv / 128, Mv / 128, 1), 256, gemm_smem>>>(bp, out);
}

// round 11
// speedup vs baseline: 7.1484x; 1.3572x over previous
#include <cuda_runtime.h>
#include <cuda_fp16.h>
#include <stdint.h>

#define Bv 4
#define Tv 2048
#define Cv 1024
#define Hv 16
#define HSv 64
#define Mv (Bv*Tv)   /* 8192 */
#define NC 16        /* K=1024 / BK=64 */

// ---------------------------------------------------------------------------
// Static device scratch (no runtime allocation) — all 1-term fp16
// ---------------------------------------------------------------------------
__device__ __half g_xh[(size_t)Mv*Cv];                 // x fp16
__device__ __half g_ch[(size_t)Mv*Cv];                 // combo fp16
__device__ __half g_wt[(size_t)3*Hv*HSv*Cv];           // W^T fp16 (mat0 pre-scaled)
__device__ __half g_wp[(size_t)Cv*Cv];                 // Wproj fp16
__device__ __half g_qh[(size_t)Bv*Hv*Tv*HSv];
__device__ __half g_kh[(size_t)Bv*Hv*Tv*HSv];
__device__ __half g_vh[(size_t)Bv*Hv*Tv*HSv];

// ---------------------------------------------------------------------------
// Helpers
// ---------------------------------------------------------------------------
__device__ __forceinline__ uint32_t smem_u32(const void* p) {
    uint32_t a;
    asm("{ .reg .u64 t; cvta.to.shared.u64 t, %1; cvt.u32.u64 %0, t; }" : "=r"(a) : "l"(p));
    return a;
}
__device__ __forceinline__ void ldm_x4(uint32_t* r, uint32_t a) {
    asm volatile("ldmatrix.sync.aligned.m8n8.x4.shared.b16 {%0,%1,%2,%3}, [%4];"
        : "=r"(r[0]), "=r"(r[1]), "=r"(r[2]), "=r"(r[3]) : "r"(a));
}
__device__ __forceinline__ void ldm_x4t(uint32_t* r, uint32_t a) {
    asm volatile("ldmatrix.sync.aligned.m8n8.x4.trans.shared.b16 {%0,%1,%2,%3}, [%4];"
        : "=r"(r[0]), "=r"(r[1]), "=r"(r[2]), "=r"(r[3]) : "r"(a));
}
__device__ __forceinline__ void mma16816(float* d, const uint32_t* a, const uint32_t* b) {
    asm volatile(
        "mma.sync.aligned.m16n8k16.row.col.f32.f16.f16.f32 "
        "{%0,%1,%2,%3}, {%4,%5,%6,%7}, {%8,%9}, {%0,%1,%2,%3};"
        : "+f"(d[0]), "+f"(d[1]), "+f"(d[2]), "+f"(d[3])
        : "r"(a[0]), "r"(a[1]), "r"(a[2]), "r"(a[3]), "r"(b[0]), "r"(b[1]));
}
#define CP_ASYNC(dst, src) \
    asm volatile("cp.async.cg.shared.global [%0], [%1], 16;" :: "r"(dst), "l"(src) : "memory")
#define CP_COMMIT() asm volatile("cp.async.commit_group;" ::: "memory")
#define CP_WAIT2()  asm volatile("cp.async.wait_group 2;" ::: "memory")
#define CP_WAIT1()  asm volatile("cp.async.wait_group 1;" ::: "memory")
#define CP_WAIT0()  asm volatile("cp.async.wait_group 0;" ::: "memory")

// ---------------------------------------------------------------------------
// Truncate fp32 -> fp16
// ---------------------------------------------------------------------------
__global__ void trunc_kernel(const float* __restrict__ src, __half* __restrict__ dst, int n4)
{
    int i = blockIdx.x * blockDim.x + threadIdx.x;
    if (i >= n4) return;
    float4 v = ((const float4*)src)[i];
    __half2* dp = (__half2*)dst;
    dp[2*i]   = __floats2half2_rn(v.x, v.y);
    dp[2*i+1] = __floats2half2_rn(v.z, v.w);
}

// ---------------------------------------------------------------------------
// Transpose + truncate Wq/Wk/Wv: W[h][c][d] -> Wt[mat][h][d][c]  (fp16)
// Wq pre-scaled by 0.125.
// ---------------------------------------------------------------------------
__global__ __launch_bounds__(256) void wtrans_kernel(
    const float* __restrict__ Wq, const float* __restrict__ Wk, const float* __restrict__ Wv)
{
    __shared__ float ts[64][65];
    const int c0 = blockIdx.x * 64;
    const int h  = blockIdx.y;
    const int mat = blockIdx.z;
    const float* W = (mat == 0) ? Wq : (mat == 1 ? Wk : Wv);
    const float scl = (mat == 0) ? 0.125f : 1.0f;
    const int tid = threadIdx.x;

    #pragma unroll
    for (int i = 0; i < 16; i++) {
        int idx = tid + i * 256;
        int r = idx >> 6, d = idx & 63;
        ts[r][d] = W[(size_t)h * (Cv * HSv) + (size_t)(c0 + r) * HSv + d] * scl;
    }
    __syncthreads();
    #pragma unroll
    for (int i = 0; i < 16; i++) {
        int idx = tid + i * 256;
        int dd = idx >> 6, cc = idx & 63;
        g_wt[((size_t)(mat * Hv + h) * HSv + dd) * Cv + c0 + cc] = __float2half_rn(ts[cc][dd]);
    }
}

// ---------------------------------------------------------------------------
// fp16 1-term GEMM on mma.sync.  C = A_fp16 * B_fp16  (fp32 accum)
// MODE 0: QKV -> q/k/v plain fp16 (b,h,t,d).   MODE 1: proj -> fp32 out + bias.
// CTA 128x128, BK=64, 8 warps (2x4), warp tile 64x32, 3-stage cp.async.
// smem/stage (36864 B): A | B, each 128 rows x 144B.
// ---------------------------------------------------------------------------
template<int MODE>
__global__ __launch_bounds__(256, 2) void gemm_kernel(const float* __restrict__ bias,
                                                      float* __restrict__ outp)
{
    extern __shared__ char smem[];
    const uint32_t sb = smem_u32(smem);
    const int tid = threadIdx.x, lane = tid & 31, wid = tid >> 5;
    const int wm = wid & 1, wn = wid >> 1;
    const int nb = blockIdx.x, m0 = blockIdx.y * 128, mat = blockIdx.z;

    const __half *am, *bm;
    if (MODE == 0) {
        am = g_xh;
        bm = g_wt + (size_t)mat * (Hv * HSv * Cv);
    } else {
        am = g_ch;
        bm = g_wp;
    }

    // loader: 2048 16B slots per stage (2 tiles x 128 rows x 8), 8 per thread
    auto issue = [&](int c, int stg) {
        const int kc0 = c * 64;
        const uint32_t sbase = sb + (uint32_t)stg * 36864u;
        #pragma unroll
        for (int i = 0; i < 8; i++) {
            int s = tid + i * 256;
            int ms = s >> 10, r = (s >> 3) & 127, c8 = s & 7;
            const __half* src = ms ? bm : am;
            int row = (ms ? nb * 128 : m0) + r;
            const void* g = src + (size_t)row * Cv + kc0 + c8 * 8;
            uint32_t d = sbase + (uint32_t)ms * 18432u + (uint32_t)(r * 144 + c8 * 16);
            CP_ASYNC(d, g);
        }
        CP_COMMIT();
    };

    issue(0, 0);
    issue(1, 1);
    issue(2, 2);

    float acc[4][4][4] = {};

    for (int c = 0; c < NC; c++) {
        if (c + 2 < NC) CP_WAIT2(); else if (c + 1 < NC) CP_WAIT1(); else CP_WAIT0();
        __syncthreads();
        const uint32_t stg = sb + (uint32_t)(c % 3) * 36864u;

        #pragma unroll
        for (int ks = 0; ks < 4; ks++) {
            uint32_t a_[4][4], b_[2][4];
            const int arow = (lane & 7) + ((lane >> 3) & 1) * 8;
            const int acol = ks * 16 + (lane >> 4) * 8;
            #pragma unroll
            for (int mt = 0; mt < 4; mt++) {
                uint32_t off = (uint32_t)((wm * 64 + mt * 16 + arow) * 144 + acol * 2);
                ldm_x4(a_[mt], stg + off);
            }
            #pragma unroll
            for (int ntp = 0; ntp < 2; ntp++) {
                uint32_t off = (uint32_t)(
                    (wn * 32 + ntp * 16 + (lane & 7) + ((lane >> 4) & 1) * 8) * 144
                    + (ks * 16 + ((lane >> 3) & 1) * 8) * 2);
                ldm_x4(b_[ntp], stg + 18432u + off);
            }
            #pragma unroll
            for (int mt = 0; mt < 4; mt++)
                #pragma unroll
                for (int ntp = 0; ntp < 2; ntp++) {
                    mma16816(acc[mt][2*ntp],   a_[mt], b_[ntp]);
                    mma16816(acc[mt][2*ntp+1], a_[mt], b_[ntp] + 2);
                }
        }
        __syncthreads();
        if (c + 3 < NC) issue(c + 3, c % 3);
    }

    const int g = lane >> 2, tig = lane & 3;
    #pragma unroll
    for (int mt = 0; mt < 4; mt++) {
        const int r0 = m0 + wm * 64 + mt * 16 + g;
        const int r1 = r0 + 8;
        #pragma unroll
        for (int nt = 0; nt < 4; nt++) {
            const int n = nb * 128 + wn * 32 + nt * 8 + tig * 2;
            if (MODE == 0) {
                const int h = n >> 6, dd = n & 63;
                int b0 = r0 >> 11, t0 = r0 & (Tv - 1);
                int b1 = r1 >> 11, t1 = r1 & (Tv - 1);
                size_t i0 = (((size_t)(b0 * Hv + h)) * Tv + t0) * HSv + dd;
                size_t i1 = (((size_t)(b1 * Hv + h)) * Tv + t1) * HSv + dd;
                __half* dst = (mat == 0) ? g_qh : (mat == 1) ? g_kh : g_vh;
                *(__half2*)&dst[i0] = __floats2half2_rn(acc[mt][nt][0], acc[mt][nt][1]);
                *(__half2*)&dst[i1] = __floats2half2_rn(acc[mt][nt][2], acc[mt][nt][3]);
            } else {
                float2 bv = *(const float2*)&bias[n];
                *(float2*)&outp[(size_t)r0 * Cv + n] =
                    make_float2(acc[mt][nt][0] + bv.x, acc[mt][nt][1] + bv.y);
                *(float2*)&outp[(size_t)r1 * Cv + n] =
                    make_float2(acc[mt][nt][2] + bv.x, acc[mt][nt][3] + bv.y);
            }
        }
    }
}

// ---------------------------------------------------------------------------
// fp16 HMMA causal flash attention (all 1-term).
// CTA = 128 queries, 8 warps x 16 rows. KV tiles 64, 2-stage cp.async.
// S = q * k ; PV = p * v.
// smem: [2 stages][2 tiles: K,V][64 rows x 144B] = 36864 B
// ---------------------------------------------------------------------------
__global__ __launch_bounds__(256) void flash_kernel()
{
    extern __shared__ char smem[];
    const uint32_t sb = smem_u32(smem);
    const int tid = threadIdx.x, lane = tid & 31, w = tid >> 5;
    const int bx = blockIdx.x, bh = blockIdx.y;
    const int q0 = bx * 128;
    const int qb = q0 + w * 16;
    const int g = lane >> 2, tig = lane & 3;

    // ---- stage Q (fp16, 128 rows -> tiles 0/1 of stage 0 region) ----
    {
        #pragma unroll
        for (int i = 0; i < 4; i++) {
            int s = tid + i * 256;
            int r = s >> 3, c = s & 7;
            const void* gp = g_qh + ((size_t)bh * Tv + q0 + r) * 64 + c * 8;
            uint32_t d = sb + (uint32_t)((r >= 64) ? 9216 : 0)
                       + (uint32_t)((r & 63) * 144 + c * 16);
            CP_ASYNC(d, gp);
        }
        CP_COMMIT(); CP_WAIT0();
        __syncthreads();
    }
    uint32_t qh[4][4];
    {
        const int row = w * 16 + (lane & 15);
        const uint32_t hb = sb + ((row >= 64) ? 9216u : 0u);
        const int rl = row & 63;
        #pragma unroll
        for (int ks = 0; ks < 4; ks++) {
            uint32_t off = (uint32_t)(rl * 144 + (ks * 16 + (lane >> 4) * 8) * 2);
            ldm_x4(qh[ks], hb + off);
        }
    }
    __syncthreads();

    float acc[8][4] = {};
    float m0 = -1e30f, m1 = -1e30f, l0 = 0.0f, l1 = 0.0f;
    const int ntl = 2 * bx + 2;

    auto issueKV = [&](int jt, int stg) {
        const int kv0 = jt * 64;
        #pragma unroll
        for (int i = 0; i < 4; i++) {
            int s = tid + i * 256;
            int tile = s >> 9, r = (s >> 3) & 63, c = s & 7;
            const __half* src = tile ? g_vh : g_kh;
            const void* gp = src + ((size_t)bh * Tv + kv0 + r) * 64 + c * 8;
            uint32_t d = sb + (uint32_t)stg * 18432u + (uint32_t)tile * 9216u
                       + (uint32_t)(r * 144 + c * 16);
            CP_ASYNC(d, gp);
        }
        CP_COMMIT();
    };
    issueKV(0, 0);
    issueKV(1, 1);

    for (int jt = 0; jt < ntl; jt++) {
        if (jt + 1 < ntl) CP_WAIT1(); else CP_WAIT0();
        __syncthreads();
        const int kv0 = jt * 64;
        const uint32_t stg = sb + (uint32_t)(jt & 1) * 18432u;

        if (kv0 <= qb + 15) {
            // ---- S = q * k (1-term fp16) ----
            float s[8][4] = {};
            #pragma unroll
            for (int ks = 0; ks < 4; ks++) {
                #pragma unroll
                for (int p = 0; p < 4; p++) {
                    uint32_t th[4];
                    uint32_t koff = (uint32_t)(
                        (p * 16 + (lane & 7) + ((lane >> 4) & 1) * 8) * 144
                        + (ks * 16 + ((lane >> 3) & 1) * 8) * 2);
                    ldm_x4(th, stg + koff);
                    mma16816(s[2*p],   qh[ks], th);
                    mma16816(s[2*p+1], qh[ks], th + 2);
                }
            }
            // ---- causal mask ----
            const int row0 = qb + g, row1 = row0 + 8;
            if (kv0 + 63 > row0) {
                #pragma unroll
                for (int nt = 0; nt < 8; nt++) {
                    int c0 = kv0 + nt * 8 + tig * 2;
                    if (c0     > row0) s[nt][0] = -1e30f;
                    if (c0 + 1 > row0) s[nt][1] = -1e30f;
                    if (c0     > row1) s[nt][2] = -1e30f;
                    if (c0 + 1 > row1) s[nt][3] = -1e30f;
                }
            }
            // ---- online softmax ----
            float mx0 = -1e30f, mx1 = -1e30f;
            #pragma unroll
            for (int nt = 0; nt < 8; nt++) {
                mx0 = fmaxf(mx0, fmaxf(s[nt][0], s[nt][1]));
                mx1 = fmaxf(mx1, fmaxf(s[nt][2], s[nt][3]));
            }
            mx0 = fmaxf(mx0, __shfl_xor_sync(0xffffffffu, mx0, 1));
            mx0 = fmaxf(mx0, __shfl_xor_sync(0xffffffffu, mx0, 2));
            mx1 = fmaxf(mx1, __shfl_xor_sync(0xffffffffu, mx1, 1));
            mx1 = fmaxf(mx1, __shfl_xor_sync(0xffffffffu, mx1, 2));
            const float mn0 = fmaxf(m0, mx0), mn1 = fmaxf(m1, mx1);
            const float f0 = __expf(m0 - mn0), f1 = __expf(m1 - mn1);
            m0 = mn0; m1 = mn1;

            uint32_t phi[8][2];
            float rs0 = 0.0f, rs1 = 0.0f;
            #pragma unroll
            for (int nt = 0; nt < 8; nt++) {
                float p0 = __expf(s[nt][0] - mn0);
                float p1 = __expf(s[nt][1] - mn0);
                float p2 = __expf(s[nt][2] - mn1);
                float p3 = __expf(s[nt][3] - mn1);
                rs0 += p0 + p1; rs1 += p2 + p3;
                __half2 t01 = __floats2half2_rn(p0, p1);
                __half2 t23 = __floats2half2_rn(p2, p3);
                phi[nt][0] = *(uint32_t*)&t01;
                phi[nt][1] = *(uint32_t*)&t23;
            }
            rs0 += __shfl_xor_sync(0xffffffffu, rs0, 1);
            rs0 += __shfl_xor_sync(0xffffffffu, rs0, 2);
            rs1 += __shfl_xor_sync(0xffffffffu, rs1, 1);
            rs1 += __shfl_xor_sync(0xffffffffu, rs1, 2);
            l0 = l0 * f0 + rs0;
            l1 = l1 * f1 + rs1;
            #pragma unroll
            for (int dt = 0; dt < 8; dt++) {
                acc[dt][0] *= f0; acc[dt][1] *= f0;
                acc[dt][2] *= f1; acc[dt][3] *= f1;
            }
            // ---- O += P V (1-term) ----
            #pragma unroll
            for (int ks = 0; ks < 4; ks++) {
                uint32_t ah[4] = { phi[2*ks][0], phi[2*ks][1], phi[2*ks+1][0], phi[2*ks+1][1] };
                #pragma unroll
                for (int dp = 0; dp < 4; dp++) {
                    uint32_t vh[4];
                    uint32_t voff = (uint32_t)(
                        (ks * 16 + (lane & 7) + ((lane >> 3) & 1) * 8) * 144
                        + (dp * 16 + (lane >> 4) * 8) * 2);
                    ldm_x4t(vh, stg + 9216u + voff);
                    mma16816(acc[2*dp],   ah, vh);
                    mma16816(acc[2*dp+1], ah, vh + 2);
                }
            }
        }
        __syncthreads();
        if (jt + 2 < ntl) issueKV(jt + 2, jt & 1);
    }

    // ---- epilogue: combo fp16 ----
    const float inv0 = 1.0f / l0, inv1 = 1.0f / l1;
    const int b = bh >> 4, h = bh & 15;
    const int t0 = qb + g, t1 = t0 + 8;
    #pragma unroll
    for (int dt = 0; dt < 8; dt++) {
        const int col = h * 64 + dt * 8 + tig * 2;
        *(__half2*)&g_ch[((size_t)b * Tv + t0) * Cv + col] =
            __floats2half2_rn(acc[dt][0] * inv0, acc[dt][1] * inv0);
        *(__half2*)&g_ch[((size_t)b * Tv + t1) * Cv + col] =
            __floats2half2_rn(acc[dt][2] * inv1, acc[dt][3] * inv1);
    }
}

// ---------------------------------------------------------------------------
extern "C" void kernel_launch(void* const* d_in, const int* in_sizes, int n_in,
                              void* d_out, int out_size)
{
    const float* x  = (const float*)d_in[0];
    const float* Wq = (const float*)d_in[1];
    const float* Wk = (const float*)d_in[2];
    const float* Wv = (const float*)d_in[3];
    const float* Wp = (const float*)d_in[4];
    const float* bp = (const float*)d_in[5];
    float* out = (float*)d_out;

    __half *xh, *wp;
    cudaGetSymbolAddress((void**)&xh, g_xh);
    cudaGetSymbolAddress((void**)&wp, g_wp);

    const int gemm_smem = 3 * 36864;   // 110592 B
    cudaFuncSetAttribute(gemm_kernel<0>, cudaFuncAttributeMaxDynamicSharedMemorySize, gemm_smem);
    cudaFuncSetAttribute(gemm_kernel<1>, cudaFuncAttributeMaxDynamicSharedMemorySize, gemm_smem);
    const int fl_smem = 2 * 18432;     // 36864 B
    cudaFuncSetAttribute(flash_kernel, cudaFuncAttributeMaxDynamicSharedMemorySize, fl_smem);

    // 1. truncate x, Wproj; transpose+truncate Wq/k/v (Wq pre-scaled)
    trunc_kernel<<<(Mv * Cv / 4 + 255) / 256, 256>>>(x, xh, Mv * Cv / 4);
    trunc_kernel<<<(Cv * Cv / 4 + 255) / 256, 256>>>(Wp, wp, Cv * Cv / 4);
    wtrans_kernel<<<dim3(Cv / 64, Hv, 3), 256>>>(Wq, Wk, Wv);

    // 2. QKV projections (1-term, 3-stage)
    gemm_kernel<0><<<dim3(Cv / 128, Mv / 128, 3), 256, gemm_smem>>>(nullptr, nullptr);

    // 3. flash attention (all 1-term) -> combo fp16
    flash_kernel<<<dim3(Tv / 128, Bv * Hv), 256, fl_smem>>>();

    // 4. output projection (1-term, 3-stage) + bias
    gemm_kernel<1><<<dim3(Cv / 128, Mv / 128, 1), 256, gemm_smem>>>(bp, out);
}

// round 12
// speedup vs baseline: 7.2525x; 1.0146x over previous
#include <cuda_runtime.h>
#include <cuda_fp16.h>
#include <stdint.h>

#define Bv 4
#define Tv 2048
#define Cv 1024
#define Hv 16
#define HSv 64
#define Mv (Bv*Tv)   /* 8192 */
#define NC 16        /* K=1024 / BK=64 */

// ---------------------------------------------------------------------------
// Static device scratch (no runtime allocation) — all 1-term fp16
// ---------------------------------------------------------------------------
__device__ __half g_xh[(size_t)Mv*Cv];                 // x fp16
__device__ __half g_ch[(size_t)Mv*Cv];                 // combo fp16
__device__ __half g_wt[(size_t)3*Hv*HSv*Cv];           // W^T fp16 (mat0 pre-scaled)
__device__ __half g_wp[(size_t)Cv*Cv];                 // Wproj fp16
__device__ __half g_qh[(size_t)Bv*Hv*Tv*HSv];
__device__ __half g_kh[(size_t)Bv*Hv*Tv*HSv];
__device__ __half g_vh[(size_t)Bv*Hv*Tv*HSv];

// ---------------------------------------------------------------------------
// Helpers
// ---------------------------------------------------------------------------
__device__ __forceinline__ uint32_t smem_u32(const void* p) {
    uint32_t a;
    asm("{ .reg .u64 t; cvta.to.shared.u64 t, %1; cvt.u32.u64 %0, t; }" : "=r"(a) : "l"(p));
    return a;
}
__device__ __forceinline__ void ldm_x4(uint32_t* r, uint32_t a) {
    asm volatile("ldmatrix.sync.aligned.m8n8.x4.shared.b16 {%0,%1,%2,%3}, [%4];"
        : "=r"(r[0]), "=r"(r[1]), "=r"(r[2]), "=r"(r[3]) : "r"(a));
}
__device__ __forceinline__ void ldm_x4t(uint32_t* r, uint32_t a) {
    asm volatile("ldmatrix.sync.aligned.m8n8.x4.trans.shared.b16 {%0,%1,%2,%3}, [%4];"
        : "=r"(r[0]), "=r"(r[1]), "=r"(r[2]), "=r"(r[3]) : "r"(a));
}
__device__ __forceinline__ void mma16816(float* d, const uint32_t* a, const uint32_t* b) {
    asm volatile(
        "mma.sync.aligned.m16n8k16.row.col.f32.f16.f16.f32 "
        "{%0,%1,%2,%3}, {%4,%5,%6,%7}, {%8,%9}, {%0,%1,%2,%3};"
        : "+f"(d[0]), "+f"(d[1]), "+f"(d[2]), "+f"(d[3])
        : "r"(a[0]), "r"(a[1]), "r"(a[2]), "r"(a[3]), "r"(b[0]), "r"(b[1]));
}
#define CP_ASYNC(dst, src) \
    asm volatile("cp.async.cg.shared.global [%0], [%1], 16;" :: "r"(dst), "l"(src) : "memory")
#define CP_COMMIT() asm volatile("cp.async.commit_group;" ::: "memory")
#define CP_WAIT2()  asm volatile("cp.async.wait_group 2;" ::: "memory")
#define CP_WAIT1()  asm volatile("cp.async.wait_group 1;" ::: "memory")
#define CP_WAIT0()  asm volatile("cp.async.wait_group 0;" ::: "memory")

// ---------------------------------------------------------------------------
// Truncate fp32 -> fp16
// ---------------------------------------------------------------------------
__global__ void trunc_kernel(const float* __restrict__ src, __half* __restrict__ dst, int n4)
{
    int i = blockIdx.x * blockDim.x + threadIdx.x;
    if (i >= n4) return;
    float4 v = ((const float4*)src)[i];
    __half2* dp = (__half2*)dst;
    dp[2*i]   = __floats2half2_rn(v.x, v.y);
    dp[2*i+1] = __floats2half2_rn(v.z, v.w);
}

// ---------------------------------------------------------------------------
// Transpose + truncate Wq/Wk/Wv: W[h][c][d] -> Wt[mat][h][d][c]  (fp16)
// Wq pre-scaled by 0.125.
// ---------------------------------------------------------------------------
__global__ __launch_bounds__(256) void wtrans_kernel(
    const float* __restrict__ Wq, const float* __restrict__ Wk, const float* __restrict__ Wv)
{
    __shared__ float ts[64][65];
    const int c0 = blockIdx.x * 64;
    const int h  = blockIdx.y;
    const int mat = blockIdx.z;
    const float* W = (mat == 0) ? Wq : (mat == 1 ? Wk : Wv);
    const float scl = (mat == 0) ? 0.125f : 1.0f;
    const int tid = threadIdx.x;

    #pragma unroll
    for (int i = 0; i < 16; i++) {
        int idx = tid + i * 256;
        int r = idx >> 6, d = idx & 63;
        ts[r][d] = W[(size_t)h * (Cv * HSv) + (size_t)(c0 + r) * HSv + d] * scl;
    }
    __syncthreads();
    #pragma unroll
    for (int i = 0; i < 16; i++) {
        int idx = tid + i * 256;
        int dd = idx >> 6, cc = idx & 63;
        g_wt[((size_t)(mat * Hv + h) * HSv + dd) * Cv + c0 + cc] = __float2half_rn(ts[cc][dd]);
    }
}

// ---------------------------------------------------------------------------
// fp16 1-term GEMM on mma.sync.  C = A * B^T  (fp32 accum)
// MODE 0: QKV -> q/k/v fp16 (b,h,t,d).   MODE 1: proj -> fp32 out + bias.
// CTA 128x128, BK=64, 4 warps (2x2), warp tile 64x64, 3-stage cp.async.
// 128 threads; acc = 128 regs/thread; __launch_bounds__(128,2) -> 2 CTA/SM.
// smem/stage (36864 B): A | B, each 128 rows x 144B.
// ---------------------------------------------------------------------------
template<int MODE>
__global__ __launch_bounds__(128, 2) void gemm_kernel(const float* __restrict__ bias,
                                                      float* __restrict__ outp)
{
    extern __shared__ char smem[];
    const uint32_t sb = smem_u32(smem);
    const int tid = threadIdx.x, lane = tid & 31, wid = tid >> 5;
    const int wm = wid & 1, wn = wid >> 1;         // 2x2 warp grid
    const int nb = blockIdx.x, m0 = blockIdx.y * 128, mat = blockIdx.z;

    const __half *am, *bm;
    if (MODE == 0) {
        am = g_xh;
        bm = g_wt + (size_t)mat * (Hv * HSv * Cv);
    } else {
        am = g_ch;
        bm = g_wp;
    }

    // loader: 2048 16B slots per stage (2 tiles x 128 rows x 8), 16 per thread
    auto issue = [&](int c, int stg) {
        const int kc0 = c * 64;
        const uint32_t sbase = sb + (uint32_t)stg * 36864u;
        #pragma unroll
        for (int i = 0; i < 16; i++) {
            int s = tid + i * 128;
            int ms = s >> 10, r = (s >> 3) & 127, c8 = s & 7;
            const __half* src = ms ? bm : am;
            int row = (ms ? nb * 128 : m0) + r;
            const void* g = src + (size_t)row * Cv + kc0 + c8 * 8;
            uint32_t d = sbase + (uint32_t)ms * 18432u + (uint32_t)(r * 144 + c8 * 16);
            CP_ASYNC(d, g);
        }
        CP_COMMIT();
    };

    issue(0, 0);
    issue(1, 1);
    issue(2, 2);

    float acc[4][8][4] = {};   // [mt 16-row][nt 8-col][frag]

    for (int c = 0; c < NC; c++) {
        if (c + 2 < NC) CP_WAIT2(); else if (c + 1 < NC) CP_WAIT1(); else CP_WAIT0();
        __syncthreads();
        const uint32_t stg = sb + (uint32_t)(c % 3) * 36864u;

        #pragma unroll
        for (int ks = 0; ks < 4; ks++) {
            uint32_t a_[4][4], b_[4][4];
            const int arow = (lane & 7) + ((lane >> 3) & 1) * 8;
            const int acol = ks * 16 + (lane >> 4) * 8;
            #pragma unroll
            for (int mt = 0; mt < 4; mt++) {
                uint32_t off = (uint32_t)((wm * 64 + mt * 16 + arow) * 144 + acol * 2);
                ldm_x4(a_[mt], stg + off);
            }
            #pragma unroll
            for (int ntp = 0; ntp < 4; ntp++) {
                uint32_t off = (uint32_t)(
                    (wn * 64 + ntp * 16 + (lane & 7) + ((lane >> 4) & 1) * 8) * 144
                    + (ks * 16 + ((lane >> 3) & 1) * 8) * 2);
                ldm_x4(b_[ntp], stg + 18432u + off);
            }
            #pragma unroll
            for (int mt = 0; mt < 4; mt++)
                #pragma unroll
                for (int ntp = 0; ntp < 4; ntp++) {
                    mma16816(acc[mt][2*ntp],   a_[mt], b_[ntp]);
                    mma16816(acc[mt][2*ntp+1], a_[mt], b_[ntp] + 2);
                }
        }
        __syncthreads();
        if (c + 3 < NC) issue(c + 3, c % 3);
    }

    const int g = lane >> 2, tig = lane & 3;
    #pragma unroll
    for (int mt = 0; mt < 4; mt++) {
        const int r0 = m0 + wm * 64 + mt * 16 + g;
        const int r1 = r0 + 8;
        #pragma unroll
        for (int nt = 0; nt < 8; nt++) {
            const int n = nb * 128 + wn * 64 + nt * 8 + tig * 2;
            if (MODE == 0) {
                const int h = n >> 6, dd = n & 63;
                int b0 = r0 >> 11, t0 = r0 & (Tv - 1);
                int b1 = r1 >> 11, t1 = r1 & (Tv - 1);
                size_t i0 = (((size_t)(b0 * Hv + h)) * Tv + t0) * HSv + dd;
                size_t i1 = (((size_t)(b1 * Hv + h)) * Tv + t1) * HSv + dd;
                __half* dst = (mat == 0) ? g_qh : (mat == 1) ? g_kh : g_vh;
                *(__half2*)&dst[i0] = __floats2half2_rn(acc[mt][nt][0], acc[mt][nt][1]);
                *(__half2*)&dst[i1] = __floats2half2_rn(acc[mt][nt][2], acc[mt][nt][3]);
            } else {
                float2 bv = *(const float2*)&bias[n];
                *(float2*)&outp[(size_t)r0 * Cv + n] =
                    make_float2(acc[mt][nt][0] + bv.x, acc[mt][nt][1] + bv.y);
                *(float2*)&outp[(size_t)r1 * Cv + n] =
                    make_float2(acc[mt][nt][2] + bv.x, acc[mt][nt][3] + bv.y);
            }
        }
    }
}

// ---------------------------------------------------------------------------
// fp16 HMMA causal flash attention (all 1-term, unchanged from R11).
// CTA = 128 queries, 8 warps x 16 rows. KV tiles 64, 2-stage cp.async.
// smem: [2 stages][2 tiles: K,V][64 rows x 144B] = 36864 B
// ---------------------------------------------------------------------------
__global__ __launch_bounds__(256) void flash_kernel()
{
    extern __shared__ char smem[];
    const uint32_t sb = smem_u32(smem);
    const int tid = threadIdx.x, lane = tid & 31, w = tid >> 5;
    const int bx = blockIdx.x, bh = blockIdx.y;
    const int q0 = bx * 128;
    const int qb = q0 + w * 16;
    const int g = lane >> 2, tig = lane & 3;

    // ---- stage Q (fp16, 128 rows -> tiles 0/1 of stage 0 region) ----
    {
        #pragma unroll
        for (int i = 0; i < 4; i++) {
            int s = tid + i * 256;
            int r = s >> 3, c = s & 7;
            const void* gp = g_qh + ((size_t)bh * Tv + q0 + r) * 64 + c * 8;
            uint32_t d = sb + (uint32_t)((r >= 64) ? 9216 : 0)
                       + (uint32_t)((r & 63) * 144 + c * 16);
            CP_ASYNC(d, gp);
        }
        CP_COMMIT(); CP_WAIT0();
        __syncthreads();
    }
    uint32_t qh[4][4];
    {
        const int row = w * 16 + (lane & 15);
        const uint32_t hb = sb + ((row >= 64) ? 9216u : 0u);
        const int rl = row & 63;
        #pragma unroll
        for (int ks = 0; ks < 4; ks++) {
            uint32_t off = (uint32_t)(rl * 144 + (ks * 16 + (lane >> 4) * 8) * 2);
            ldm_x4(qh[ks], hb + off);
        }
    }
    __syncthreads();

    float acc[8][4] = {};
    float m0 = -1e30f, m1 = -1e30f, l0 = 0.0f, l1 = 0.0f;
    const int ntl = 2 * bx + 2;

    auto issueKV = [&](int jt, int stg) {
        const int kv0 = jt * 64;
        #pragma unroll
        for (int i = 0; i < 4; i++) {
            int s = tid + i * 256;
            int tile = s >> 9, r = (s >> 3) & 63, c = s & 7;
            const __half* src = tile ? g_vh : g_kh;
            const void* gp = src + ((size_t)bh * Tv + kv0 + r) * 64 + c * 8;
            uint32_t d = sb + (uint32_t)stg * 18432u + (uint32_t)tile * 9216u
                       + (uint32_t)(r * 144 + c * 16);
            CP_ASYNC(d, gp);
        }
        CP_COMMIT();
    };
    issueKV(0, 0);
    issueKV(1, 1);

    for (int jt = 0; jt < ntl; jt++) {
        if (jt + 1 < ntl) CP_WAIT1(); else CP_WAIT0();
        __syncthreads();
        const int kv0 = jt * 64;
        const uint32_t stg = sb + (uint32_t)(jt & 1) * 18432u;

        if (kv0 <= qb + 15) {
            // ---- S = q * k (1-term fp16) ----
            float s[8][4] = {};
            #pragma unroll
            for (int ks = 0; ks < 4; ks++) {
                #pragma unroll
                for (int p = 0; p < 4; p++) {
                    uint32_t th[4];
                    uint32_t koff = (uint32_t)(
                        (p * 16 + (lane & 7) + ((lane >> 4) & 1) * 8) * 144
                        + (ks * 16 + ((lane >> 3) & 1) * 8) * 2);
                    ldm_x4(th, stg + koff);
                    mma16816(s[2*p],   qh[ks], th);
                    mma16816(s[2*p+1], qh[ks], th + 2);
                }
            }
            // ---- causal mask ----
            const int row0 = qb + g, row1 = row0 + 8;
            if (kv0 + 63 > row0) {
                #pragma unroll
                for (int nt = 0; nt < 8; nt++) {
                    int c0 = kv0 + nt * 8 + tig * 2;
                    if (c0     > row0) s[nt][0] = -1e30f;
                    if (c0 + 1 > row0) s[nt][1] = -1e30f;
                    if (c0     > row1) s[nt][2] = -1e30f;
                    if (c0 + 1 > row1) s[nt][3] = -1e30f;
                }
            }
            // ---- online softmax ----
            float mx0 = -1e30f, mx1 = -1e30f;
            #pragma unroll
            for (int nt = 0; nt < 8; nt++) {
                mx0 = fmaxf(mx0, fmaxf(s[nt][0], s[nt][1]));
                mx1 = fmaxf(mx1, fmaxf(s[nt][2], s[nt][3]));
            }
            mx0 = fmaxf(mx0, __shfl_xor_sync(0xffffffffu, mx0, 1));
            mx0 = fmaxf(mx0, __shfl_xor_sync(0xffffffffu, mx0, 2));
            mx1 = fmaxf(mx1, __shfl_xor_sync(0xffffffffu, mx1, 1));
            mx1 = fmaxf(mx1, __shfl_xor_sync(0xffffffffu, mx1, 2));
            const float mn0 = fmaxf(m0, mx0), mn1 = fmaxf(m1, mx1);
            const float f0 = __expf(m0 - mn0), f1 = __expf(m1 - mn1);
            m0 = mn0; m1 = mn1;

            uint32_t phi[8][2];
            float rs0 = 0.0f, rs1 = 0.0f;
            #pragma unroll
            for (int nt = 0; nt < 8; nt++) {
                float p0 = __expf(s[nt][0] - mn0);
                float p1 = __expf(s[nt][1] - mn0);
                float p2 = __expf(s[nt][2] - mn1);
                float p3 = __expf(s[nt][3] - mn1);
                rs0 += p0 + p1; rs1 += p2 + p3;
                __half2 t01 = __floats2half2_rn(p0, p1);
                __half2 t23 = __floats2half2_rn(p2, p3);
                phi[nt][0] = *(uint32_t*)&t01;
                phi[nt][1] = *(uint32_t*)&t23;
            }
            rs0 += __shfl_xor_sync(0xffffffffu, rs0, 1);
            rs0 += __shfl_xor_sync(0xffffffffu, rs0, 2);
            rs1 += __shfl_xor_sync(0xffffffffu, rs1, 1);
            rs1 += __shfl_xor_sync(0xffffffffu, rs1, 2);
            l0 = l0 * f0 + rs0;
            l1 = l1 * f1 + rs1;
            #pragma unroll
            for (int dt = 0; dt < 8; dt++) {
                acc[dt][0] *= f0; acc[dt][1] *= f0;
                acc[dt][2] *= f1; acc[dt][3] *= f1;
            }
            // ---- O += P V (1-term) ----
            #pragma unroll
            for (int ks = 0; ks < 4; ks++) {
                uint32_t ah[4] = { phi[2*ks][0], phi[2*ks][1], phi[2*ks+1][0], phi[2*ks+1][1] };
                #pragma unroll
                for (int dp = 0; dp < 4; dp++) {
                    uint32_t vh[4];
                    uint32_t voff = (uint32_t)(
                        (ks * 16 + (lane & 7) + ((lane >> 3) & 1) * 8) * 144
                        + (dp * 16 + (lane >> 4) * 8) * 2);
                    ldm_x4t(vh, stg + 9216u + voff);
                    mma16816(acc[2*dp],   ah, vh);
                    mma16816(acc[2*dp+1], ah, vh + 2);
                }
            }
        }
        __syncthreads();
        if (jt + 2 < ntl) issueKV(jt + 2, jt & 1);
    }

    // ---- epilogue: combo fp16 ----
    const float inv0 = 1.0f / l0, inv1 = 1.0f / l1;
    const int b = bh >> 4, h = bh & 15;
    const int t0 = qb + g, t1 = t0 + 8;
    #pragma unroll
    for (int dt = 0; dt < 8; dt++) {
        const int col = h * 64 + dt * 8 + tig * 2;
        *(__half2*)&g_ch[((size_t)b * Tv + t0) * Cv + col] =
            __floats2half2_rn(acc[dt][0] * inv0, acc[dt][1] * inv0);
        *(__half2*)&g_ch[((size_t)b * Tv + t1) * Cv + col] =
            __floats2half2_rn(acc[dt][2] * inv1, acc[dt][3] * inv1);
    }
}

// ---------------------------------------------------------------------------
extern "C" void kernel_launch(void* const* d_in, const int* in_sizes, int n_in,
                              void* d_out, int out_size)
{
    const float* x  = (const float*)d_in[0];
    const float* Wq = (const float*)d_in[1];
    const float* Wk = (const float*)d_in[2];
    const float* Wv = (const float*)d_in[3];
    const float* Wp = (const float*)d_in[4];
    const float* bp = (const float*)d_in[5];
    float* out = (float*)d_out;

    __half *xh, *wp;
    cudaGetSymbolAddress((void**)&xh, g_xh);
    cudaGetSymbolAddress((void**)&wp, g_wp);

    const int gemm_smem = 3 * 36864;   // 110592 B
    cudaFuncSetAttribute(gemm_kernel<0>, cudaFuncAttributeMaxDynamicSharedMemorySize, gemm_smem);
    cudaFuncSetAttribute(gemm_kernel<1>, cudaFuncAttributeMaxDynamicSharedMemorySize, gemm_smem);
    const int fl_smem = 2 * 18432;     // 36864 B
    cudaFuncSetAttribute(flash_kernel, cudaFuncAttributeMaxDynamicSharedMemorySize, fl_smem);

    // 1. truncate x, Wproj; transpose+truncate Wq/k/v (Wq pre-scaled)
    trunc_kernel<<<(Mv * Cv / 4 + 255) / 256, 256>>>(x, xh, Mv * Cv / 4);
    trunc_kernel<<<(Cv * Cv / 4 + 255) / 256, 256>>>(Wp, wp, Cv * Cv / 4);
    wtrans_kernel<<<dim3(Cv / 64, Hv, 3), 256>>>(Wq, Wk, Wv);

    // 2. QKV projections (1-term, 3-stage, 4-warp 64x64 warp tiles)
    gemm_kernel<0><<<dim3(Cv / 128, Mv / 128, 3), 128, gemm_smem>>>(nullptr, nullptr);

    // 3. flash attention (all 1-term) -> combo fp16
    flash_kernel<<<dim3(Tv / 128, Bv * Hv), 256, fl_smem>>>();

    // 4. output projection (1-term, 3-stage) + bias
    gemm_kernel<1><<<dim3(Cv / 128, Mv / 128, 1), 128, gemm_smem>>>(bp, out);
}